// round 1
// baseline (speedup 1.0000x reference)
#include <cuda_runtime.h>
#include <math.h>

#define T_STEPS 64
#define B 32
#define D 1024
#define L 2
#define MEM 35
#define NTOK 32000
#define HEADS 2
#define DK 512
#define MB (MEM*B)          /* 1120 */
#define BD (B*D)            /* 32768 */
#define EPS 1e-6f
#define ATT_SCALE 0.04419417382415922f  /* 1/sqrt(512) */

/* output layout: decoded [T,B,NTOK], h [L,B,D], c, H [L,MEM,B,D], C */
#define OFF_DEC 0L
#define OFF_H   65536000L
#define OFF_C   65601536L
#define OFF_HM  65667072L
#define OFF_CM  67960832L

/* ------------------------- device scratch ------------------------- */
__device__ float d_e[BD];
__device__ float d_ln[BD];
__device__ float d_q[BD];
__device__ float d_att[BD];
__device__ float d_hupd[L*BD];
__device__ float d_scores[HEADS*B*MB];
__device__ float d_gates[B*4*D];
__device__ float d_hcur[L*BD];
__device__ float d_ccur[L*BD];
__device__ float d_Kc[MB*D];
__device__ float d_Vc[MB*D];
__device__ float d_Hh[L*MEM*BD];
__device__ float d_Ch[L*MEM*BD];
__device__ float d_X[T_STEPS*BD];

/* ------------------------- init / tail ------------------------- */
__global__ __launch_bounds__(256) void init_state(const float* __restrict__ h0,
                                                  const float* __restrict__ c0,
                                                  const float* __restrict__ H0,
                                                  const float* __restrict__ C0)
{
    long i = (long)blockIdx.x * 256 + threadIdx.x;
    if (i < (long)L*BD) { d_hcur[i] = h0[i]; d_ccur[i] = c0[i]; }
    if (i < (long)L*MEM*BD) { d_Hh[i] = H0[i]; d_Ch[i] = C0[i]; }
}

__global__ __launch_bounds__(256) void write_tail(float* __restrict__ out)
{
    long i = (long)blockIdx.x * 256 + threadIdx.x;
    if (i >= (long)L*MEM*BD) return;
    if (i < (long)L*BD) {
        out[OFF_H + i] = d_hcur[i];
        out[OFF_C + i] = d_ccur[i];
    }
    long l = i / ((long)MEM*BD);
    long r = i % ((long)MEM*BD);
    long j = r / BD;
    long q = r % BD;
    long phys = (T_STEPS + j) % MEM;
    long src = (l*MEM + phys)*(long)BD + q;
    out[OFF_HM + i] = d_Hh[src];
    out[OFF_CM + i] = d_Ch[src];
}

/* ------------------------- embed + layernorm ------------------------- */
__global__ __launch_bounds__(256) void embed_ln(const int* __restrict__ tok,
                                                const float* __restrict__ emb,
                                                const float* __restrict__ gg,
                                                const float* __restrict__ bb)
{
    __shared__ float sh[256];
    int b = blockIdx.x, tid = threadIdx.x;
    const float* row = emb + (long)tok[b] * D;
    float x[4]; float s = 0.f;
#pragma unroll
    for (int i = 0; i < 4; i++) { x[i] = row[tid + i*256]; s += x[i]; }
    sh[tid] = s; __syncthreads();
    for (int st = 128; st > 0; st >>= 1) { if (tid < st) sh[tid] += sh[tid+st]; __syncthreads(); }
    float mu = sh[0] * (1.f / D); __syncthreads();
    float ss = 0.f;
#pragma unroll
    for (int i = 0; i < 4; i++) { float dd = x[i] - mu; ss += dd*dd; }
    sh[tid] = ss; __syncthreads();
    for (int st = 128; st > 0; st >>= 1) { if (tid < st) sh[tid] += sh[tid+st]; __syncthreads(); }
    float sd = sqrtf(sh[0] / (float)(D - 1));
    float inv = 1.f / (sd + EPS);
#pragma unroll
    for (int i = 0; i < 4; i++) {
        int idx = tid + i*256;
        d_e[b*D + idx] = x[i];
        d_ln[b*D + idx] = gg[idx] * (x[i] - mu) * inv + bb[idx];
    }
}

/* ------------------------- generic NT gemm  C = alpha*(A@B^T)+bias -------------------------
   BM=32 (M must be multiple of 32), BN=64, BK=32 (K multiple of 32), 256 threads.
   blockIdx.z selects a "head" with per-operand element offsets. */
__global__ __launch_bounds__(256) void gemm_nt(const float* __restrict__ A, int lda, long long aoff,
                                               const float* __restrict__ Bw, int ldb, long long boff,
                                               float* __restrict__ C, int ldc, long long coff,
                                               const float* __restrict__ bias,
                                               int N, int K, float alpha)
{
    __shared__ float As[32][33];
    __shared__ float Bs[32][65];
    int z = blockIdx.z;
    A  += (long long)z * aoff;
    Bw += (long long)z * boff;
    C  += (long long)z * coff;
    int m0 = blockIdx.y * 32;
    int n0 = blockIdx.x * 64;
    int tid = threadIdx.x, tx = tid & 31, ty = tid >> 5;
    float acc[4][2] = {};
    for (int k0 = 0; k0 < K; k0 += 32) {
        __syncthreads();
        {
            int m = tid >> 3, k4 = (tid & 7) * 4;
            float4 v = *(const float4*)(A + (long long)(m0 + m)*lda + k0 + k4);
            As[k4+0][m]=v.x; As[k4+1][m]=v.y; As[k4+2][m]=v.z; As[k4+3][m]=v.w;
        }
#pragma unroll
        for (int s = tid; s < 512; s += 256) {
            int n = s >> 3, k4 = (s & 7) * 4;
            float4 v = make_float4(0.f,0.f,0.f,0.f);
            if (n0 + n < N) v = *(const float4*)(Bw + (long long)(n0 + n)*ldb + k0 + k4);
            Bs[k4+0][n]=v.x; Bs[k4+1][n]=v.y; Bs[k4+2][n]=v.z; Bs[k4+3][n]=v.w;
        }
        __syncthreads();
#pragma unroll
        for (int kk = 0; kk < 32; kk++) {
            float b0 = Bs[kk][tx], b1 = Bs[kk][tx+32];
#pragma unroll
            for (int i = 0; i < 4; i++) {
                float a = As[kk][ty*4 + i];
                acc[i][0] += a * b0;
                acc[i][1] += a * b1;
            }
        }
    }
#pragma unroll
    for (int i = 0; i < 4; i++) {
        int m = m0 + ty*4 + i;
#pragma unroll
        for (int j = 0; j < 2; j++) {
            int n = n0 + tx + j*32;
            if (n < N) {
                float v = alpha * acc[i][j];
                if (bias) v += bias[n];
                C[(long long)m*ldc + n] = v;
            }
        }
    }
}

/* ------------------------- NN gemm  C = A@B (exact dims: M=32, N%64==0, K%32==0) ------------ */
__global__ __launch_bounds__(256) void gemm_nn(const float* __restrict__ A, int lda, long long aoff,
                                               const float* __restrict__ Bm, int ldb, long long boff,
                                               float* __restrict__ C, int ldc, long long coff,
                                               int K)
{
    __shared__ float As[32][33];
    __shared__ float Bs[32][64];
    int z = blockIdx.z;
    A  += (long long)z * aoff;
    Bm += (long long)z * boff;
    C  += (long long)z * coff;
    int n0 = blockIdx.x * 64;
    int tid = threadIdx.x, tx = tid & 31, ty = tid >> 5;
    float acc[4][2] = {};
    for (int k0 = 0; k0 < K; k0 += 32) {
        __syncthreads();
        {
            int m = tid >> 3, k4 = (tid & 7) * 4;
            float4 v = *(const float4*)(A + (long long)m*lda + k0 + k4);
            As[k4+0][m]=v.x; As[k4+1][m]=v.y; As[k4+2][m]=v.z; As[k4+3][m]=v.w;
        }
#pragma unroll
        for (int s = tid; s < 512; s += 256) {
            int kk = s >> 4, n4 = (s & 15) * 4;
            *(float4*)&Bs[kk][n4] = *(const float4*)(Bm + (long long)(k0 + kk)*ldb + n0 + n4);
        }
        __syncthreads();
#pragma unroll
        for (int kk = 0; kk < 32; kk++) {
            float b0 = Bs[kk][tx], b1 = Bs[kk][tx+32];
#pragma unroll
            for (int i = 0; i < 4; i++) {
                float a = As[kk][ty*4 + i];
                acc[i][0] += a * b0;
                acc[i][1] += a * b1;
            }
        }
    }
#pragma unroll
    for (int i = 0; i < 4; i++) {
        int m = ty*4 + i;
#pragma unroll
        for (int j = 0; j < 2; j++) {
            int n = n0 + tx + j*32;
            C[(long long)m*ldc + n] = acc[i][j];
        }
    }
}

/* ------------------------- softmax over 1120-length rows (64 rows) ------------------------- */
__global__ __launch_bounds__(256) void softmax_rows()
{
    __shared__ float sh[256];
    int row = blockIdx.x, tid = threadIdx.x;
    float* p = d_scores + (long)row * MB;
    float v[5];
    float mx = -1e30f;
#pragma unroll
    for (int i = 0; i < 5; i++) {
        int idx = tid + i*256;
        v[i] = -1e30f;
        if (idx < MB) { v[i] = p[idx]; mx = fmaxf(mx, v[i]); }
    }
    sh[tid] = mx; __syncthreads();
    for (int st = 128; st > 0; st >>= 1) { if (tid < st) sh[tid] = fmaxf(sh[tid], sh[tid+st]); __syncthreads(); }
    float M = sh[0]; __syncthreads();
    float sum = 0.f;
#pragma unroll
    for (int i = 0; i < 5; i++) {
        int idx = tid + i*256;
        if (idx < MB) { v[i] = __expf(v[i] - M); sum += v[i]; }
    }
    sh[tid] = sum; __syncthreads();
    for (int st = 128; st > 0; st >>= 1) { if (tid < st) sh[tid] += sh[tid+st]; __syncthreads(); }
    float inv = 1.f / sh[0];
#pragma unroll
    for (int i = 0; i < 5; i++) {
        int idx = tid + i*256;
        if (idx < MB) p[idx] = v[i] * inv;
    }
}

/* ------------------------- Wo gemm with fused residual + layer broadcast -------------------
   h_att = e + att@Wo^T + bo ; h_upd[l] = h_att + h_cur[l]  (writes d_hupd for both layers) */
__global__ __launch_bounds__(256) void gemm_wo(const float* __restrict__ Wo,
                                               const float* __restrict__ bo)
{
    __shared__ float As[32][33];
    __shared__ float Bs[32][65];
    int n0 = blockIdx.x * 64;
    int tid = threadIdx.x, tx = tid & 31, ty = tid >> 5;
    float acc[4][2] = {};
    for (int k0 = 0; k0 < D; k0 += 32) {
        __syncthreads();
        {
            int m = tid >> 3, k4 = (tid & 7) * 4;
            float4 v = *(const float4*)(d_att + m*D + k0 + k4);
            As[k4+0][m]=v.x; As[k4+1][m]=v.y; As[k4+2][m]=v.z; As[k4+3][m]=v.w;
        }
#pragma unroll
        for (int s = tid; s < 512; s += 256) {
            int n = s >> 3, k4 = (s & 7) * 4;
            float4 v = *(const float4*)(Wo + (long long)(n0 + n)*D + k0 + k4);
            Bs[k4+0][n]=v.x; Bs[k4+1][n]=v.y; Bs[k4+2][n]=v.z; Bs[k4+3][n]=v.w;
        }
        __syncthreads();
#pragma unroll
        for (int kk = 0; kk < 32; kk++) {
            float b0 = Bs[kk][tx], b1 = Bs[kk][tx+32];
#pragma unroll
            for (int i = 0; i < 4; i++) {
                float a = As[kk][ty*4 + i];
                acc[i][0] += a * b0;
                acc[i][1] += a * b1;
            }
        }
    }
#pragma unroll
    for (int i = 0; i < 4; i++) {
        int m = ty*4 + i;
#pragma unroll
        for (int j = 0; j < 2; j++) {
            int n = n0 + tx + j*32;
            float hatt = acc[i][j] + bo[n] + d_e[m*D + n];
            d_hupd[m*D + n]      = hatt + d_hcur[m*D + n];
            d_hupd[BD + m*D + n] = hatt + d_hcur[BD + m*D + n];
        }
    }
}

/* ------------------------- LSTM dual gemm:  gates = A1@W1^T + A2@W2^T + b1 + b2 ----------- */
__global__ __launch_bounds__(256) void gemm_lstm(const float* __restrict__ A1,
                                                 const float* __restrict__ W1,
                                                 const float* __restrict__ A2,
                                                 const float* __restrict__ W2,
                                                 const float* __restrict__ b1,
                                                 const float* __restrict__ b2)
{
    __shared__ float As[32][33];
    __shared__ float Bs[32][65];
    int n0 = blockIdx.x * 64;
    int tid = threadIdx.x, tx = tid & 31, ty = tid >> 5;
    float acc[4][2] = {};
#pragma unroll
    for (int pass = 0; pass < 2; pass++) {
        const float* A = pass ? A2 : A1;
        const float* W = pass ? W2 : W1;
        for (int k0 = 0; k0 < D; k0 += 32) {
            __syncthreads();
            {
                int m = tid >> 3, k4 = (tid & 7) * 4;
                float4 v = *(const float4*)(A + m*D + k0 + k4);
                As[k4+0][m]=v.x; As[k4+1][m]=v.y; As[k4+2][m]=v.z; As[k4+3][m]=v.w;
            }
#pragma unroll
            for (int s = tid; s < 512; s += 256) {
                int n = s >> 3, k4 = (s & 7) * 4;
                float4 v = *(const float4*)(W + (long long)(n0 + n)*D + k0 + k4);
                Bs[k4+0][n]=v.x; Bs[k4+1][n]=v.y; Bs[k4+2][n]=v.z; Bs[k4+3][n]=v.w;
            }
            __syncthreads();
#pragma unroll
            for (int kk = 0; kk < 32; kk++) {
                float b0 = Bs[kk][tx], b1v = Bs[kk][tx+32];
#pragma unroll
                for (int i = 0; i < 4; i++) {
                    float a = As[kk][ty*4 + i];
                    acc[i][0] += a * b0;
                    acc[i][1] += a * b1v;
                }
            }
        }
    }
#pragma unroll
    for (int i = 0; i < 4; i++) {
        int m = ty*4 + i;
#pragma unroll
        for (int j = 0; j < 2; j++) {
            int n = n0 + tx + j*32;
            d_gates[(long)m*(4*D) + n] = acc[i][j] + b1[n] + b2[n];
        }
    }
}

/* ------------------------- LSTM elementwise cell ------------------------- */
__global__ __launch_bounds__(256) void lstm_cell(int l, int slot, int writeX, int t)
{
    int idx = blockIdx.x * 256 + threadIdx.x;   /* < BD */
    int b = idx >> 10, d = idx & 1023;
    const float* g = d_gates + (long)b * (4*D);
    float ig = g[d], fg = g[D + d], gg = g[2*D + d], og = g[3*D + d];
    float cp = d_ccur[l*BD + idx];
    float si = 1.f / (1.f + __expf(-ig));
    float sf = 1.f / (1.f + __expf(-fg));
    float so = 1.f / (1.f + __expf(-og));
    float cn = sf * cp + si * tanhf(gg);
    float hn = so * tanhf(cn);
    d_hcur[l*BD + idx] = hn;
    d_ccur[l*BD + idx] = cn;
    d_Hh[((long)l*MEM + slot)*BD + idx] = hn;
    d_Ch[((long)l*MEM + slot)*BD + idx] = cn;
    if (writeX) d_X[(long)t*BD + idx] = hn;
}

/* ------------------------- decode SGEMM: C[2048,32000] = X@decW^T + bias -------------------
   128x128x16 tiles, 256 threads, 8x8 per-thread microtile. All dims divide exactly. */
__global__ __launch_bounds__(256) void sgemm_decode(const float* __restrict__ A,
                                                    const float* __restrict__ Bw,
                                                    const float* __restrict__ bias,
                                                    float* __restrict__ C)
{
    __shared__ __align__(16) float As[16][132];
    __shared__ __align__(16) float Bs[16][132];
    int tid = threadIdx.x;
    int m0 = blockIdx.y * 128, n0 = blockIdx.x * 128;
    int tx = tid & 15, ty = tid >> 4;
    int lr = tid >> 2, lk4 = (tid & 3) * 4;
    float acc[8][8] = {};
    for (int k0 = 0; k0 < 1024; k0 += 16) {
        float4 a0 = *(const float4*)(A  + (long)(m0 + lr)      * 1024 + k0 + lk4);
        float4 a1 = *(const float4*)(A  + (long)(m0 + lr + 64) * 1024 + k0 + lk4);
        float4 b0 = *(const float4*)(Bw + (long)(n0 + lr)      * 1024 + k0 + lk4);
        float4 b1 = *(const float4*)(Bw + (long)(n0 + lr + 64) * 1024 + k0 + lk4);
        __syncthreads();
        As[lk4+0][lr]=a0.x; As[lk4+1][lr]=a0.y; As[lk4+2][lr]=a0.z; As[lk4+3][lr]=a0.w;
        As[lk4+0][lr+64]=a1.x; As[lk4+1][lr+64]=a1.y; As[lk4+2][lr+64]=a1.z; As[lk4+3][lr+64]=a1.w;
        Bs[lk4+0][lr]=b0.x; Bs[lk4+1][lr]=b0.y; Bs[lk4+2][lr]=b0.z; Bs[lk4+3][lr]=b0.w;
        Bs[lk4+0][lr+64]=b1.x; Bs[lk4+1][lr+64]=b1.y; Bs[lk4+2][lr+64]=b1.z; Bs[lk4+3][lr+64]=b1.w;
        __syncthreads();
#pragma unroll
        for (int kk = 0; kk < 16; kk++) {
            float a[8], b[8];
            *(float4*)&a[0] = *(const float4*)&As[kk][ty*8];
            *(float4*)&a[4] = *(const float4*)&As[kk][ty*8 + 4];
            *(float4*)&b[0] = *(const float4*)&Bs[kk][tx*8];
            *(float4*)&b[4] = *(const float4*)&Bs[kk][tx*8 + 4];
#pragma unroll
            for (int i = 0; i < 8; i++)
#pragma unroll
                for (int j = 0; j < 8; j++)
                    acc[i][j] += a[i] * b[j];
        }
    }
    float bs[8];
#pragma unroll
    for (int j = 0; j < 8; j++) bs[j] = bias[n0 + tx*8 + j];
#pragma unroll
    for (int i = 0; i < 8; i++) {
        long row = m0 + ty*8 + i;
        float4 v0 = make_float4(acc[i][0]+bs[0], acc[i][1]+bs[1], acc[i][2]+bs[2], acc[i][3]+bs[3]);
        float4 v1 = make_float4(acc[i][4]+bs[4], acc[i][5]+bs[5], acc[i][6]+bs[6], acc[i][7]+bs[7]);
        *(float4*)(C + row*NTOK + n0 + tx*8)     = v0;
        *(float4*)(C + row*NTOK + n0 + tx*8 + 4) = v1;
    }
}

/* ------------------------- host launch ------------------------- */
extern "C" void kernel_launch(void* const* d_in, const int* in_sizes, int n_in,
                              void* d_out, int out_size)
{
    (void)in_sizes; (void)n_in; (void)out_size;
    const int*   tok  = (const int*)d_in[0];
    const float* emb  = (const float*)d_in[1];
    const float* ln_g = (const float*)d_in[2];
    const float* ln_b = (const float*)d_in[3];
    const float* Wq = (const float*)d_in[4];  const float* bq = (const float*)d_in[5];
    const float* Wk = (const float*)d_in[6];  const float* bk = (const float*)d_in[7];
    const float* Wv = (const float*)d_in[8];  const float* bv = (const float*)d_in[9];
    const float* Wo = (const float*)d_in[10]; const float* bo = (const float*)d_in[11];
    const float* Wih = (const float*)d_in[12]; const float* bih = (const float*)d_in[13];
    const float* Whh = (const float*)d_in[14]; const float* bhh = (const float*)d_in[15];
    const float* dW = (const float*)d_in[16]; const float* db = (const float*)d_in[17];
    const float* h0 = (const float*)d_in[18]; const float* c0 = (const float*)d_in[19];
    const float* H0 = (const float*)d_in[20]; const float* C0 = (const float*)d_in[21];
    float* out = (float*)d_out;

    float *p_ln, *p_q, *p_att, *p_hupd, *p_scores, *p_hcur, *p_Kc, *p_Vc, *p_X, *p_e;
    cudaGetSymbolAddress((void**)&p_e,      d_e);
    cudaGetSymbolAddress((void**)&p_ln,     d_ln);
    cudaGetSymbolAddress((void**)&p_q,      d_q);
    cudaGetSymbolAddress((void**)&p_att,    d_att);
    cudaGetSymbolAddress((void**)&p_hupd,   d_hupd);
    cudaGetSymbolAddress((void**)&p_scores, d_scores);
    cudaGetSymbolAddress((void**)&p_hcur,   d_hcur);
    cudaGetSymbolAddress((void**)&p_Kc,     d_Kc);
    cudaGetSymbolAddress((void**)&p_Vc,     d_Vc);
    cudaGetSymbolAddress((void**)&p_X,      d_X);

    /* initialize states + full K/V cache from H0 layer 0 (M=1120) */
    init_state<<<8960, 256>>>(h0, c0, H0, C0);
    gemm_nt<<<dim3(16, 35, 1), 256>>>(H0, D, 0, Wk, D, 0, p_Kc, D, 0, bk, D, D, 1.f);
    gemm_nt<<<dim3(16, 35, 1), 256>>>(H0, D, 0, Wv, D, 0, p_Vc, D, 0, bv, D, D, 1.f);

    for (int t = 0; t < T_STEPS; t++) {
        int slot = t % MEM;
        embed_ln<<<32, 256>>>(tok + t*B, emb, ln_g, ln_b);
        /* q = LN(e) @ Wq^T + bq */
        gemm_nt<<<dim3(16, 1, 1), 256>>>(p_ln, D, 0, Wq, D, 0, p_q, D, 0, bq, D, D, 1.f);
        /* scores[h] = (q_h @ K_h^T) * scale   [32 x 1120] per head */
        gemm_nt<<<dim3(18, 1, HEADS), 256>>>(p_q, D, DK, p_Kc, D, DK,
                                             p_scores, MB, (long long)B*MB,
                                             nullptr, MB, DK, ATT_SCALE);
        softmax_rows<<<HEADS*B, 256>>>();
        /* att_h = w_h @ V_h   [32 x 512] per head */
        gemm_nn<<<dim3(8, 1, HEADS), 256>>>(p_scores, MB, (long long)B*MB,
                                            p_Vc, D, DK, p_att, D, DK, MB);
        /* h_att = e + att@Wo^T+bo ; h_upd[l] = h_att + h_cur[l] */
        gemm_wo<<<dim3(16, 1, 1), 256>>>(Wo, bo);
        /* LSTM layer 0 */
        gemm_lstm<<<dim3(64, 1, 1), 256>>>(p_e, Wih, p_hupd, Whh, bih, bhh);
        lstm_cell<<<128, 256>>>(0, slot, 0, t);
        /* LSTM layer 1 (x = hn0 = h_cur[0]) */
        gemm_lstm<<<dim3(64, 1, 1), 256>>>(p_hcur, Wih + 4096*1024, p_hupd + BD,
                                           Whh + 4096*1024, bih + 4096, bhh + 4096);
        lstm_cell<<<128, 256>>>(1, slot, 1, t);
        /* incremental K/V cache update from hn0 */
        gemm_nt<<<dim3(16, 1, 1), 256>>>(p_hcur, D, 0, Wk, D, 0,
                                         p_Kc + (long)slot*B*D, D, 0, bk, D, D, 1.f);
        gemm_nt<<<dim3(16, 1, 1), 256>>>(p_hcur, D, 0, Wv, D, 0,
                                         p_Vc + (long)slot*B*D, D, 0, bv, D, D, 1.f);
    }

    /* all decode projections at once: [2048,1024] @ [1024,32000] */
    sgemm_decode<<<dim3(NTOK/128, (T_STEPS*B)/128), 256>>>(p_X, dW, db, out + OFF_DEC);
    write_tail<<<8960, 256>>>(out);
}

// round 2
// speedup vs baseline: 1.0109x; 1.0109x over previous
#include <cuda_runtime.h>
#include <math.h>

#define T_STEPS 64
#define B 32
#define D 1024
#define L 2
#define MEM 35
#define NTOK 32000
#define HEADS 2
#define DK 512
#define MB (MEM*B)          /* 1120 */
#define BD (B*D)            /* 32768 */
#define EPS 1e-6f
#define ATT_SCALE 0.04419417382415922f  /* 1/sqrt(512) */

/* output layout: decoded [T,B,NTOK], h [L,B,D], c, H [L,MEM,B,D], C */
#define OFF_DEC 0L
#define OFF_H   65536000L
#define OFF_C   65601536L
#define OFF_HM  65667072L
#define OFF_CM  67960832L

/* ------------------------- device scratch ------------------------- */
__device__ float d_e[BD];
__device__ float d_ln[BD];
__device__ float d_q[BD];
__device__ float d_att[BD];
__device__ float d_hupd[L*BD];
__device__ float d_scores[HEADS*B*MB];
__device__ float d_gates[B*4*D];
__device__ float d_hcur[L*BD];
__device__ float d_ccur[L*BD];
__device__ float d_Kc[MB*D];
__device__ float d_Vc[MB*D];
__device__ float d_Hh[L*MEM*BD];
__device__ float d_Ch[L*MEM*BD];
__device__ float d_X[T_STEPS*BD];

/* ------------------------- init / tail ------------------------- */
__global__ __launch_bounds__(256) void init_state(const float* __restrict__ h0,
                                                  const float* __restrict__ c0,
                                                  const float* __restrict__ H0,
                                                  const float* __restrict__ C0)
{
    long i = (long)blockIdx.x * 256 + threadIdx.x;
    if (i < (long)L*BD) { d_hcur[i] = h0[i]; d_ccur[i] = c0[i]; }
    if (i < (long)L*MEM*BD) { d_Hh[i] = H0[i]; d_Ch[i] = C0[i]; }
}

__global__ __launch_bounds__(256) void write_tail(float* __restrict__ out)
{
    long i = (long)blockIdx.x * 256 + threadIdx.x;
    if (i >= (long)L*MEM*BD) return;
    if (i < (long)L*BD) {
        out[OFF_H + i] = d_hcur[i];
        out[OFF_C + i] = d_ccur[i];
    }
    long l = i / ((long)MEM*BD);
    long r = i % ((long)MEM*BD);
    long j = r / BD;
    long q = r % BD;
    long phys = (T_STEPS + j) % MEM;
    long src = (l*MEM + phys)*(long)BD + q;
    out[OFF_HM + i] = d_Hh[src];
    out[OFF_CM + i] = d_Ch[src];
}

/* ------------------------- embed + layernorm ------------------------- */
__global__ __launch_bounds__(256) void embed_ln(const int* __restrict__ tok,
                                                const float* __restrict__ emb,
                                                const float* __restrict__ gg,
                                                const float* __restrict__ bb)
{
    __shared__ float sh[256];
    int b = blockIdx.x, tid = threadIdx.x;
    const float* row = emb + (long)tok[b] * D;
    float x[4]; float s = 0.f;
#pragma unroll
    for (int i = 0; i < 4; i++) { x[i] = row[tid + i*256]; s += x[i]; }
    sh[tid] = s; __syncthreads();
    for (int st = 128; st > 0; st >>= 1) { if (tid < st) sh[tid] += sh[tid+st]; __syncthreads(); }
    float mu = sh[0] * (1.f / D); __syncthreads();
    float ss = 0.f;
#pragma unroll
    for (int i = 0; i < 4; i++) { float dd = x[i] - mu; ss += dd*dd; }
    sh[tid] = ss; __syncthreads();
    for (int st = 128; st > 0; st >>= 1) { if (tid < st) sh[tid] += sh[tid+st]; __syncthreads(); }
    float sd = sqrtf(sh[0] / (float)(D - 1));
    float inv = 1.f / (sd + EPS);
#pragma unroll
    for (int i = 0; i < 4; i++) {
        int idx = tid + i*256;
        d_e[b*D + idx] = x[i];
        d_ln[b*D + idx] = gg[idx] * (x[i] - mu) * inv + bb[idx];
    }
}

/* ------------------------- generic NT gemm  C = alpha*(A@B^T)+bias -------------------------
   BM=32 (M must be multiple of 32), BN=64, BK=32 (K multiple of 32), 256 threads.
   blockIdx.z selects a "head" with per-operand element offsets. */
__global__ __launch_bounds__(256) void gemm_nt(const float* __restrict__ A, int lda, long long aoff,
                                               const float* __restrict__ Bw, int ldb, long long boff,
                                               float* __restrict__ C, int ldc, long long coff,
                                               const float* __restrict__ bias,
                                               int N, int K, float alpha)
{
    __shared__ float As[32][33];
    __shared__ float Bs[32][65];
    int z = blockIdx.z;
    A  += (long long)z * aoff;
    Bw += (long long)z * boff;
    C  += (long long)z * coff;
    int m0 = blockIdx.y * 32;
    int n0 = blockIdx.x * 64;
    int tid = threadIdx.x, tx = tid & 31, ty = tid >> 5;
    float acc[4][2] = {};
    for (int k0 = 0; k0 < K; k0 += 32) {
        __syncthreads();
        {
            int m = tid >> 3, k4 = (tid & 7) * 4;
            float4 v = *(const float4*)(A + (long long)(m0 + m)*lda + k0 + k4);
            As[k4+0][m]=v.x; As[k4+1][m]=v.y; As[k4+2][m]=v.z; As[k4+3][m]=v.w;
        }
#pragma unroll
        for (int s = tid; s < 512; s += 256) {
            int n = s >> 3, k4 = (s & 7) * 4;
            float4 v = make_float4(0.f,0.f,0.f,0.f);
            if (n0 + n < N) v = *(const float4*)(Bw + (long long)(n0 + n)*ldb + k0 + k4);
            Bs[k4+0][n]=v.x; Bs[k4+1][n]=v.y; Bs[k4+2][n]=v.z; Bs[k4+3][n]=v.w;
        }
        __syncthreads();
#pragma unroll
        for (int kk = 0; kk < 32; kk++) {
            float b0 = Bs[kk][tx], b1 = Bs[kk][tx+32];
#pragma unroll
            for (int i = 0; i < 4; i++) {
                float a = As[kk][ty*4 + i];
                acc[i][0] += a * b0;
                acc[i][1] += a * b1;
            }
        }
    }
#pragma unroll
    for (int i = 0; i < 4; i++) {
        int m = m0 + ty*4 + i;
#pragma unroll
        for (int j = 0; j < 2; j++) {
            int n = n0 + tx + j*32;
            if (n < N) {
                float v = alpha * acc[i][j];
                if (bias) v += bias[n];
                C[(long long)m*ldc + n] = v;
            }
        }
    }
}

/* ------------------------- NN gemm  C = A@B (exact dims: M=32, N%64==0, K%32==0) ------------ */
__global__ __launch_bounds__(256) void gemm_nn(const float* __restrict__ A, int lda, long long aoff,
                                               const float* __restrict__ Bm, int ldb, long long boff,
                                               float* __restrict__ C, int ldc, long long coff,
                                               int K)
{
    __shared__ float As[32][33];
    __shared__ float Bs[32][64];
    int z = blockIdx.z;
    A  += (long long)z * aoff;
    Bm += (long long)z * boff;
    C  += (long long)z * coff;
    int n0 = blockIdx.x * 64;
    int tid = threadIdx.x, tx = tid & 31, ty = tid >> 5;
    float acc[4][2] = {};
    for (int k0 = 0; k0 < K; k0 += 32) {
        __syncthreads();
        {
            int m = tid >> 3, k4 = (tid & 7) * 4;
            float4 v = *(const float4*)(A + (long long)m*lda + k0 + k4);
            As[k4+0][m]=v.x; As[k4+1][m]=v.y; As[k4+2][m]=v.z; As[k4+3][m]=v.w;
        }
#pragma unroll
        for (int s = tid; s < 512; s += 256) {
            int kk = s >> 4, n4 = (s & 15) * 4;
            *(float4*)&Bs[kk][n4] = *(const float4*)(Bm + (long long)(k0 + kk)*ldb + n0 + n4);
        }
        __syncthreads();
#pragma unroll
        for (int kk = 0; kk < 32; kk++) {
            float b0 = Bs[kk][tx], b1 = Bs[kk][tx+32];
#pragma unroll
            for (int i = 0; i < 4; i++) {
                float a = As[kk][ty*4 + i];
                acc[i][0] += a * b0;
                acc[i][1] += a * b1;
            }
        }
    }
#pragma unroll
    for (int i = 0; i < 4; i++) {
        int m = ty*4 + i;
#pragma unroll
        for (int j = 0; j < 2; j++) {
            int n = n0 + tx + j*32;
            C[(long long)m*ldc + n] = acc[i][j];
        }
    }
}

/* ------------------------- softmax over 1120-length rows (64 rows) ------------------------- */
__global__ __launch_bounds__(256) void softmax_rows()
{
    __shared__ float sh[256];
    int row = blockIdx.x, tid = threadIdx.x;
    float* p = d_scores + (long)row * MB;
    float v[5];
    float mx = -1e30f;
#pragma unroll
    for (int i = 0; i < 5; i++) {
        int idx = tid + i*256;
        v[i] = -1e30f;
        if (idx < MB) { v[i] = p[idx]; mx = fmaxf(mx, v[i]); }
    }
    sh[tid] = mx; __syncthreads();
    for (int st = 128; st > 0; st >>= 1) { if (tid < st) sh[tid] = fmaxf(sh[tid], sh[tid+st]); __syncthreads(); }
    float M = sh[0]; __syncthreads();
    float sum = 0.f;
#pragma unroll
    for (int i = 0; i < 5; i++) {
        int idx = tid + i*256;
        if (idx < MB) { v[i] = __expf(v[i] - M); sum += v[i]; }
    }
    sh[tid] = sum; __syncthreads();
    for (int st = 128; st > 0; st >>= 1) { if (tid < st) sh[tid] += sh[tid+st]; __syncthreads(); }
    float inv = 1.f / sh[0];
#pragma unroll
    for (int i = 0; i < 5; i++) {
        int idx = tid + i*256;
        if (idx < MB) p[idx] = v[i] * inv;
    }
}

/* ------------------------- Wo gemm with fused residual + layer broadcast -------------------
   h_att = e + att@Wo^T + bo ; h_upd[l] = h_att + h_cur[l]  (writes d_hupd for both layers) */
__global__ __launch_bounds__(256) void gemm_wo(const float* __restrict__ Wo,
                                               const float* __restrict__ bo)
{
    __shared__ float As[32][33];
    __shared__ float Bs[32][65];
    int n0 = blockIdx.x * 64;
    int tid = threadIdx.x, tx = tid & 31, ty = tid >> 5;
    float acc[4][2] = {};
    for (int k0 = 0; k0 < D; k0 += 32) {
        __syncthreads();
        {
            int m = tid >> 3, k4 = (tid & 7) * 4;
            float4 v = *(const float4*)(d_att + m*D + k0 + k4);
            As[k4+0][m]=v.x; As[k4+1][m]=v.y; As[k4+2][m]=v.z; As[k4+3][m]=v.w;
        }
#pragma unroll
        for (int s = tid; s < 512; s += 256) {
            int n = s >> 3, k4 = (s & 7) * 4;
            float4 v = *(const float4*)(Wo + (long long)(n0 + n)*D + k0 + k4);
            Bs[k4+0][n]=v.x; Bs[k4+1][n]=v.y; Bs[k4+2][n]=v.z; Bs[k4+3][n]=v.w;
        }
        __syncthreads();
#pragma unroll
        for (int kk = 0; kk < 32; kk++) {
            float b0 = Bs[kk][tx], b1 = Bs[kk][tx+32];
#pragma unroll
            for (int i = 0; i < 4; i++) {
                float a = As[kk][ty*4 + i];
                acc[i][0] += a * b0;
                acc[i][1] += a * b1;
            }
        }
    }
#pragma unroll
    for (int i = 0; i < 4; i++) {
        int m = ty*4 + i;
#pragma unroll
        for (int j = 0; j < 2; j++) {
            int n = n0 + tx + j*32;
            float hatt = acc[i][j] + bo[n] + d_e[m*D + n];
            d_hupd[m*D + n]      = hatt + d_hcur[m*D + n];
            d_hupd[BD + m*D + n] = hatt + d_hcur[BD + m*D + n];
        }
    }
}

/* ------------------------- LSTM dual gemm:  gates = A1@W1^T + A2@W2^T + b1 + b2 ----------- */
__global__ __launch_bounds__(256) void gemm_lstm(const float* __restrict__ A1,
                                                 const float* __restrict__ W1,
                                                 const float* __restrict__ A2,
                                                 const float* __restrict__ W2,
                                                 const float* __restrict__ b1,
                                                 const float* __restrict__ b2)
{
    __shared__ float As[32][33];
    __shared__ float Bs[32][65];
    int n0 = blockIdx.x * 64;
    int tid = threadIdx.x, tx = tid & 31, ty = tid >> 5;
    float acc[4][2] = {};
#pragma unroll
    for (int pass = 0; pass < 2; pass++) {
        const float* A = pass ? A2 : A1;
        const float* W = pass ? W2 : W1;
        for (int k0 = 0; k0 < D; k0 += 32) {
            __syncthreads();
            {
                int m = tid >> 3, k4 = (tid & 7) * 4;
                float4 v = *(const float4*)(A + m*D + k0 + k4);
                As[k4+0][m]=v.x; As[k4+1][m]=v.y; As[k4+2][m]=v.z; As[k4+3][m]=v.w;
            }
#pragma unroll
            for (int s = tid; s < 512; s += 256) {
                int n = s >> 3, k4 = (s & 7) * 4;
                float4 v = *(const float4*)(W + (long long)(n0 + n)*D + k0 + k4);
                Bs[k4+0][n]=v.x; Bs[k4+1][n]=v.y; Bs[k4+2][n]=v.z; Bs[k4+3][n]=v.w;
            }
            __syncthreads();
#pragma unroll
            for (int kk = 0; kk < 32; kk++) {
                float b0 = Bs[kk][tx], b1v = Bs[kk][tx+32];
#pragma unroll
                for (int i = 0; i < 4; i++) {
                    float a = As[kk][ty*4 + i];
                    acc[i][0] += a * b0;
                    acc[i][1] += a * b1v;
                }
            }
        }
    }
#pragma unroll
    for (int i = 0; i < 4; i++) {
        int m = ty*4 + i;
#pragma unroll
        for (int j = 0; j < 2; j++) {
            int n = n0 + tx + j*32;
            d_gates[(long)m*(4*D) + n] = acc[i][j] + b1[n] + b2[n];
        }
    }
}

/* ------------------------- LSTM elementwise cell ------------------------- */
__global__ __launch_bounds__(256) void lstm_cell(int l, int slot, int writeX, int t)
{
    int idx = blockIdx.x * 256 + threadIdx.x;   /* < BD */
    int b = idx >> 10, d = idx & 1023;
    const float* g = d_gates + (long)b * (4*D);
    float ig = g[d], fg = g[D + d], gg = g[2*D + d], og = g[3*D + d];
    float cp = d_ccur[l*BD + idx];
    float si = 1.f / (1.f + __expf(-ig));
    float sf = 1.f / (1.f + __expf(-fg));
    float so = 1.f / (1.f + __expf(-og));
    float cn = sf * cp + si * tanhf(gg);
    float hn = so * tanhf(cn);
    d_hcur[l*BD + idx] = hn;
    d_ccur[l*BD + idx] = cn;
    d_Hh[((long)l*MEM + slot)*BD + idx] = hn;
    d_Ch[((long)l*MEM + slot)*BD + idx] = cn;
    if (writeX) d_X[(long)t*BD + idx] = hn;
}

/* ------------------------- decode SGEMM: C[2048,32000] = X@decW^T + bias -------------------
   128x128x16 tiles, 256 threads, 8x8 per-thread microtile. All dims divide exactly. */
__global__ __launch_bounds__(256) void sgemm_decode(const float* __restrict__ A,
                                                    const float* __restrict__ Bw,
                                                    const float* __restrict__ bias,
                                                    float* __restrict__ C)
{
    __shared__ __align__(16) float As[16][132];
    __shared__ __align__(16) float Bs[16][132];
    int tid = threadIdx.x;
    int m0 = blockIdx.y * 128, n0 = blockIdx.x * 128;
    int tx = tid & 15, ty = tid >> 4;
    int lr = tid >> 2, lk4 = (tid & 3) * 4;
    float acc[8][8] = {};
    for (int k0 = 0; k0 < 1024; k0 += 16) {
        float4 a0 = *(const float4*)(A  + (long)(m0 + lr)      * 1024 + k0 + lk4);
        float4 a1 = *(const float4*)(A  + (long)(m0 + lr + 64) * 1024 + k0 + lk4);
        float4 b0 = *(const float4*)(Bw + (long)(n0 + lr)      * 1024 + k0 + lk4);
        float4 b1 = *(const float4*)(Bw + (long)(n0 + lr + 64) * 1024 + k0 + lk4);
        __syncthreads();
        As[lk4+0][lr]=a0.x; As[lk4+1][lr]=a0.y; As[lk4+2][lr]=a0.z; As[lk4+3][lr]=a0.w;
        As[lk4+0][lr+64]=a1.x; As[lk4+1][lr+64]=a1.y; As[lk4+2][lr+64]=a1.z; As[lk4+3][lr+64]=a1.w;
        Bs[lk4+0][lr]=b0.x; Bs[lk4+1][lr]=b0.y; Bs[lk4+2][lr]=b0.z; Bs[lk4+3][lr]=b0.w;
        Bs[lk4+0][lr+64]=b1.x; Bs[lk4+1][lr+64]=b1.y; Bs[lk4+2][lr+64]=b1.z; Bs[lk4+3][lr+64]=b1.w;
        __syncthreads();
#pragma unroll
        for (int kk = 0; kk < 16; kk++) {
            float a[8], b[8];
            *(float4*)&a[0] = *(const float4*)&As[kk][ty*8];
            *(float4*)&a[4] = *(const float4*)&As[kk][ty*8 + 4];
            *(float4*)&b[0] = *(const float4*)&Bs[kk][tx*8];
            *(float4*)&b[4] = *(const float4*)&Bs[kk][tx*8 + 4];
#pragma unroll
            for (int i = 0; i < 8; i++)
#pragma unroll
                for (int j = 0; j < 8; j++)
                    acc[i][j] += a[i] * b[j];
        }
    }
    float bs[8];
#pragma unroll
    for (int j = 0; j < 8; j++) bs[j] = bias[n0 + tx*8 + j];
#pragma unroll
    for (int i = 0; i < 8; i++) {
        long row = m0 + ty*8 + i;
        float4 v0 = make_float4(acc[i][0]+bs[0], acc[i][1]+bs[1], acc[i][2]+bs[2], acc[i][3]+bs[3]);
        float4 v1 = make_float4(acc[i][4]+bs[4], acc[i][5]+bs[5], acc[i][6]+bs[6], acc[i][7]+bs[7]);
        *(float4*)(C + row*NTOK + n0 + tx*8)     = v0;
        *(float4*)(C + row*NTOK + n0 + tx*8 + 4) = v1;
    }
}

/* ------------------------- host launch ------------------------- */
extern "C" void kernel_launch(void* const* d_in, const int* in_sizes, int n_in,
                              void* d_out, int out_size)
{
    (void)in_sizes; (void)n_in; (void)out_size;
    const int*   tok  = (const int*)d_in[0];
    const float* emb  = (const float*)d_in[1];
    const float* ln_g = (const float*)d_in[2];
    const float* ln_b = (const float*)d_in[3];
    const float* Wq = (const float*)d_in[4];  const float* bq = (const float*)d_in[5];
    const float* Wk = (const float*)d_in[6];  const float* bk = (const float*)d_in[7];
    const float* Wv = (const float*)d_in[8];  const float* bv = (const float*)d_in[9];
    const float* Wo = (const float*)d_in[10]; const float* bo = (const float*)d_in[11];
    const float* Wih = (const float*)d_in[12]; const float* bih = (const float*)d_in[13];
    const float* Whh = (const float*)d_in[14]; const float* bhh = (const float*)d_in[15];
    const float* dW = (const float*)d_in[16]; const float* db = (const float*)d_in[17];
    const float* h0 = (const float*)d_in[18]; const float* c0 = (const float*)d_in[19];
    const float* H0 = (const float*)d_in[20]; const float* C0 = (const float*)d_in[21];
    float* out = (float*)d_out;

    float *p_ln, *p_q, *p_att, *p_hupd, *p_scores, *p_hcur, *p_Kc, *p_Vc, *p_X, *p_e;
    cudaGetSymbolAddress((void**)&p_e,      d_e);
    cudaGetSymbolAddress((void**)&p_ln,     d_ln);
    cudaGetSymbolAddress((void**)&p_q,      d_q);
    cudaGetSymbolAddress((void**)&p_att,    d_att);
    cudaGetSymbolAddress((void**)&p_hupd,   d_hupd);
    cudaGetSymbolAddress((void**)&p_scores, d_scores);
    cudaGetSymbolAddress((void**)&p_hcur,   d_hcur);
    cudaGetSymbolAddress((void**)&p_Kc,     d_Kc);
    cudaGetSymbolAddress((void**)&p_Vc,     d_Vc);
    cudaGetSymbolAddress((void**)&p_X,      d_X);

    /* initialize states + full K/V cache from H0 layer 0 (M=1120) */
    init_state<<<8960, 256>>>(h0, c0, H0, C0);
    gemm_nt<<<dim3(16, 35, 1), 256>>>(H0, D, 0, Wk, D, 0, p_Kc, D, 0, bk, D, D, 1.f);
    gemm_nt<<<dim3(16, 35, 1), 256>>>(H0, D, 0, Wv, D, 0, p_Vc, D, 0, bv, D, D, 1.f);

    for (int t = 0; t < T_STEPS; t++) {
        int slot = t % MEM;
        embed_ln<<<32, 256>>>(tok + t*B, emb, ln_g, ln_b);
        /* q = LN(e) @ Wq^T + bq */
        gemm_nt<<<dim3(16, 1, 1), 256>>>(p_ln, D, 0, Wq, D, 0, p_q, D, 0, bq, D, D, 1.f);
        /* scores[h] = (q_h @ K_h^T) * scale   [32 x 1120] per head */
        gemm_nt<<<dim3(18, 1, HEADS), 256>>>(p_q, D, DK, p_Kc, D, DK,
                                             p_scores, MB, (long long)B*MB,
                                             nullptr, MB, DK, ATT_SCALE);
        softmax_rows<<<HEADS*B, 256>>>();
        /* att_h = w_h @ V_h   [32 x 512] per head */
        gemm_nn<<<dim3(8, 1, HEADS), 256>>>(p_scores, MB, (long long)B*MB,
                                            p_Vc, D, DK, p_att, D, DK, MB);
        /* h_att = e + att@Wo^T+bo ; h_upd[l] = h_att + h_cur[l] */
        gemm_wo<<<dim3(16, 1, 1), 256>>>(Wo, bo);
        /* LSTM layer 0 */
        gemm_lstm<<<dim3(64, 1, 1), 256>>>(p_e, Wih, p_hupd, Whh, bih, bhh);
        lstm_cell<<<128, 256>>>(0, slot, 0, t);
        /* LSTM layer 1 (x = hn0 = h_cur[0]) */
        gemm_lstm<<<dim3(64, 1, 1), 256>>>(p_hcur, Wih + 4096*1024, p_hupd + BD,
                                           Whh + 4096*1024, bih + 4096, bhh + 4096);
        lstm_cell<<<128, 256>>>(1, slot, 1, t);
        /* incremental K/V cache update from hn0 */
        gemm_nt<<<dim3(16, 1, 1), 256>>>(p_hcur, D, 0, Wk, D, 0,
                                         p_Kc + (long)slot*B*D, D, 0, bk, D, D, 1.f);
        gemm_nt<<<dim3(16, 1, 1), 256>>>(p_hcur, D, 0, Wv, D, 0,
                                         p_Vc + (long)slot*B*D, D, 0, bv, D, D, 1.f);
    }

    /* all decode projections at once: [2048,1024] @ [1024,32000] */
    sgemm_decode<<<dim3(NTOK/128, (T_STEPS*B)/128), 256>>>(p_X, dW, db, out + OFF_DEC);
    write_tail<<<8960, 256>>>(out);
}

// round 3
// speedup vs baseline: 1.7285x; 1.7099x over previous
#include <cuda_runtime.h>
#include <math.h>

#define T_STEPS 64
#define B 32
#define D 1024
#define L 2
#define MEM 35
#define NTOK 32000
#define HEADS 2
#define DK 512
#define MB (MEM*B)
#define BD (B*D)
#define EPS 1e-6f
#define ATT_SCALE 0.04419417382415922f

#define OFF_H   65536000L
#define OFF_C   65601536L
#define OFF_HM  65667072L
#define OFF_CM  67960832L

__device__ float d_eAll[T_STEPS*BD];
__device__ float d_lnAll[T_STEPS*BD];
__device__ float d_q[BD];
__device__ float d_att[BD];
__device__ float d_hupd[L*BD];
__device__ float d_scores[HEADS*B*MB];
__device__ float d_lstmpart[8*B*4096];
__device__ float d_hcur[L*BD];
__device__ float d_ccur[L*BD];
__device__ float d_Kc[MB*D];
__device__ float d_Vc[MB*D];
__device__ float d_Hh[L*MEM*BD];
__device__ float d_Ch[L*MEM*BD];
__device__ float d_X[T_STEPS*BD];

/* ---------------- shared skinny-GEMM cores (M=32, BN=128) ---------------- */
/* NT: C32x128 += A[32,K] @ W[N,K]^T slice. As pad33, Bs pad129: conflict-free. */
__device__ __forceinline__ void nt_body(float (*As)[33], float (*Bs)[129],
    const float* A, int lda, const float* W, int ldw,
    int n0, int Nrows, int kbeg, int ntiles, float acc[4][4])
{
    int tid = threadIdx.x;
    int lm = tid >> 3, lk4 = (tid & 7) * 4;
    int mt = tid >> 5, nt = tid & 31;
    const float* arow = A + (long long)lm*lda + kbeg + lk4;
    const float* wr0 = W + kbeg + lk4;
    long long woff[4]; bool wok[4];
#pragma unroll
    for (int c = 0; c < 4; c++) {
        int n = n0 + lm + 32*c;
        wok[c] = (n < Nrows);
        woff[c] = (long long)(wok[c] ? n : 0) * ldw;
    }
    float4 z4 = make_float4(0.f,0.f,0.f,0.f);
    float4 pa = *(const float4*)arow;
    float4 pb[4];
#pragma unroll
    for (int c = 0; c < 4; c++) pb[c] = wok[c] ? *(const float4*)(wr0 + woff[c]) : z4;
    for (int kt = 0; kt < ntiles; kt++) {
        __syncthreads();
        As[lk4+0][lm]=pa.x; As[lk4+1][lm]=pa.y; As[lk4+2][lm]=pa.z; As[lk4+3][lm]=pa.w;
#pragma unroll
        for (int c = 0; c < 4; c++) {
            int n = lm + 32*c;
            Bs[lk4+0][n]=pb[c].x; Bs[lk4+1][n]=pb[c].y; Bs[lk4+2][n]=pb[c].z; Bs[lk4+3][n]=pb[c].w;
        }
        __syncthreads();
        if (kt + 1 < ntiles) {
            int ko = (kt+1)*32;
            pa = *(const float4*)(arow + ko);
#pragma unroll
            for (int c = 0; c < 4; c++) pb[c] = wok[c] ? *(const float4*)(wr0 + woff[c] + ko) : z4;
        }
#pragma unroll
        for (int kk = 0; kk < 32; kk++) {
            float a0=As[kk][mt*4+0], a1=As[kk][mt*4+1], a2=As[kk][mt*4+2], a3=As[kk][mt*4+3];
            float b0=Bs[kk][nt], b1=Bs[kk][nt+32], b2=Bs[kk][nt+64], b3=Bs[kk][nt+96];
            acc[0][0]+=a0*b0; acc[0][1]+=a0*b1; acc[0][2]+=a0*b2; acc[0][3]+=a0*b3;
            acc[1][0]+=a1*b0; acc[1][1]+=a1*b1; acc[1][2]+=a1*b2; acc[1][3]+=a1*b3;
            acc[2][0]+=a2*b0; acc[2][1]+=a2*b1; acc[2][2]+=a2*b2; acc[2][3]+=a2*b3;
            acc[3][0]+=a3*b0; acc[3][1]+=a3*b1; acc[3][2]+=a3*b2; acc[3][3]+=a3*b3;
        }
    }
}

/* NN: C32x128 += A[32,K] @ Bm[K,N] slice. Bs pad132, float4 stores, exact dims. */
__device__ __forceinline__ void nn_body(float (*As)[33], float (*Bs)[132],
    const float* A, int lda, const float* Bm, int ldb,
    int n0, int kbeg, int ntiles, float acc[4][4])
{
    int tid = threadIdx.x;
    int lm = tid >> 3, lk4 = (tid & 7) * 4;
    int mt = tid >> 5, nt = tid & 31;
    const float* arow = A + (long long)lm*lda + kbeg + lk4;
    int brow = tid >> 5, bcol = (tid & 31) * 4;
    const float* bbase = Bm + (long long)(kbeg + brow)*ldb + n0 + bcol;
    float4 pa = *(const float4*)arow;
    float4 pb[4];
#pragma unroll
    for (int c = 0; c < 4; c++) pb[c] = *(const float4*)(bbase + (long long)(8*c)*ldb);
    for (int kt = 0; kt < ntiles; kt++) {
        __syncthreads();
        As[lk4+0][lm]=pa.x; As[lk4+1][lm]=pa.y; As[lk4+2][lm]=pa.z; As[lk4+3][lm]=pa.w;
#pragma unroll
        for (int c = 0; c < 4; c++) *(float4*)&Bs[brow+8*c][bcol] = pb[c];
        __syncthreads();
        if (kt + 1 < ntiles) {
            int ko = (kt+1)*32;
            pa = *(const float4*)(arow + ko);
#pragma unroll
            for (int c = 0; c < 4; c++) pb[c] = *(const float4*)(bbase + (long long)(ko + 8*c)*ldb);
        }
#pragma unroll
        for (int kk = 0; kk < 32; kk++) {
            float a0=As[kk][mt*4+0], a1=As[kk][mt*4+1], a2=As[kk][mt*4+2], a3=As[kk][mt*4+3];
            float b0=Bs[kk][nt], b1=Bs[kk][nt+32], b2=Bs[kk][nt+64], b3=Bs[kk][nt+96];
            acc[0][0]+=a0*b0; acc[0][1]+=a0*b1; acc[0][2]+=a0*b2; acc[0][3]+=a0*b3;
            acc[1][0]+=a1*b0; acc[1][1]+=a1*b1; acc[1][2]+=a1*b2; acc[1][3]+=a1*b3;
            acc[2][0]+=a2*b0; acc[2][1]+=a2*b1; acc[2][2]+=a2*b2; acc[2][3]+=a2*b3;
            acc[3][0]+=a3*b0; acc[3][1]+=a3*b1; acc[3][2]+=a3*b2; acc[3][3]+=a3*b3;
        }
    }
}

/* ---------------- init / embed / tail ---------------- */
__global__ __launch_bounds__(256) void init_state(const float* __restrict__ h0,
    const float* __restrict__ c0, const float* __restrict__ H0, const float* __restrict__ C0)
{
    long i = (long)blockIdx.x * 256 + threadIdx.x;
    if (i < (long)L*BD) { d_hcur[i] = h0[i]; d_ccur[i] = c0[i]; }
    if (i < (long)L*MEM*BD) { d_Hh[i] = H0[i]; d_Ch[i] = C0[i]; }
}

__global__ __launch_bounds__(256) void write_tail(float* __restrict__ out)
{
    long i = (long)blockIdx.x * 256 + threadIdx.x;
    if (i >= (long)L*MEM*BD) return;
    if (i < (long)L*BD) { out[OFF_H + i] = d_hcur[i]; out[OFF_C + i] = d_ccur[i]; }
    long l = i / ((long)MEM*BD);
    long r = i % ((long)MEM*BD);
    long j = r / BD, q = r % BD;
    long phys = (T_STEPS + j) % MEM;
    long src = (l*MEM + phys)*(long)BD + q;
    out[OFF_HM + i] = d_Hh[src];
    out[OFF_CM + i] = d_Ch[src];
}

__global__ __launch_bounds__(256) void embed_all(const int* __restrict__ tok,
    const float* __restrict__ emb, const float* __restrict__ gg, const float* __restrict__ bb)
{
    __shared__ float sh[256];
    int r = blockIdx.x, tid = threadIdx.x;
    const float* row = emb + (long)tok[r] * D;
    float x[4]; float s = 0.f;
#pragma unroll
    for (int i = 0; i < 4; i++) { x[i] = row[tid + i*256]; s += x[i]; }
    sh[tid] = s; __syncthreads();
    for (int st = 128; st > 0; st >>= 1) { if (tid < st) sh[tid] += sh[tid+st]; __syncthreads(); }
    float mu = sh[0] * (1.f / D); __syncthreads();
    float ss = 0.f;
#pragma unroll
    for (int i = 0; i < 4; i++) { float dd = x[i] - mu; ss += dd*dd; }
    sh[tid] = ss; __syncthreads();
    for (int st = 128; st > 0; st >>= 1) { if (tid < st) sh[tid] += sh[tid+st]; __syncthreads(); }
    float inv = 1.f / (sqrtf(sh[0] / (float)(D - 1)) + EPS);
#pragma unroll
    for (int i = 0; i < 4; i++) {
        int idx = tid + i*256;
        d_eAll[(long)r*D + idx]  = x[i];
        d_lnAll[(long)r*D + idx] = gg[idx] * (x[i] - mu) * inv + bb[idx];
    }
}

/* ---------------- GEMM wrapper kernels ---------------- */
__global__ __launch_bounds__(256) void kv_init(const float* __restrict__ H0,
    const float* __restrict__ Wk, const float* __restrict__ Wv,
    const float* __restrict__ bk, const float* __restrict__ bv)
{
    __shared__ float As[32][33], Bs[32][129];
    int z = blockIdx.z;
    const float* W = z ? Wv : Wk;
    const float* bias = z ? bv : bk;
    float* C = (z ? d_Vc : d_Kc) + (long long)blockIdx.y * 32 * D;
    const float* A = H0 + (long long)blockIdx.y * 32 * D;
    int n0 = blockIdx.x * 128;
    float acc[4][4] = {};
    nt_body(As, Bs, A, D, W, D, n0, D, 0, 32, acc);
    int mt = threadIdx.x >> 5, nt = threadIdx.x & 31;
#pragma unroll
    for (int i = 0; i < 4; i++)
#pragma unroll
        for (int j = 0; j < 4; j++) {
            int n = n0 + nt + 32*j;
            C[(long long)(mt*4+i)*D + n] = acc[i][j] + bias[n];
        }
}

/* z=0: q = ln@Wq^T+bq ; z=1/2: K/V cache slot update from h_prev(l0) */
__global__ __launch_bounds__(256) void qkv3(const float* __restrict__ ln,
    const float* __restrict__ hsrc,
    const float* __restrict__ Wq, const float* __restrict__ bq,
    const float* __restrict__ Wk, const float* __restrict__ bk,
    const float* __restrict__ Wv, const float* __restrict__ bv, int slotPrev)
{
    __shared__ float As[32][33], Bs[32][129];
    int z = blockIdx.z;
    const float* A = (z == 0) ? ln : hsrc;
    const float* W = (z == 0) ? Wq : ((z == 1) ? Wk : Wv);
    const float* bias = (z == 0) ? bq : ((z == 1) ? bk : bv);
    float* C = (z == 0) ? d_q : ((z == 1) ? d_Kc : d_Vc) + (long long)slotPrev * BD;
    int n0 = blockIdx.x * 128;
    float acc[4][4] = {};
    nt_body(As, Bs, A, D, W, D, n0, D, 0, 32, acc);
    int mt = threadIdx.x >> 5, nt = threadIdx.x & 31;
#pragma unroll
    for (int i = 0; i < 4; i++)
#pragma unroll
        for (int j = 0; j < 4; j++) {
            int n = n0 + nt + 32*j;
            C[(long long)(mt*4+i)*D + n] = acc[i][j] + bias[n];
        }
}

__global__ __launch_bounds__(256) void scores_k()
{
    __shared__ float As[32][33], Bs[32][129];
    int z = blockIdx.z;
    int n0 = blockIdx.x * 128;
    float acc[4][4] = {};
    nt_body(As, Bs, d_q + z*DK, D, d_Kc + z*DK, D, n0, MB, 0, DK/32, acc);
    float* C = d_scores + (long long)z * B * MB;
    int mt = threadIdx.x >> 5, nt = threadIdx.x & 31;
#pragma unroll
    for (int i = 0; i < 4; i++)
#pragma unroll
        for (int j = 0; j < 4; j++) {
            int n = n0 + nt + 32*j;
            if (n < MB) C[(long long)(mt*4+i)*MB + n] = acc[i][j] * ATT_SCALE;
        }
}

__global__ __launch_bounds__(256) void softmax_rows()
{
    __shared__ float sh[256];
    int row = blockIdx.x, tid = threadIdx.x;
    float* p = d_scores + (long)row * MB;
    float v[5]; float mx = -1e30f;
#pragma unroll
    for (int i = 0; i < 5; i++) {
        int idx = tid + i*256; v[i] = -1e30f;
        if (idx < MB) { v[i] = p[idx]; mx = fmaxf(mx, v[i]); }
    }
    sh[tid] = mx; __syncthreads();
    for (int st = 128; st > 0; st >>= 1) { if (tid < st) sh[tid] = fmaxf(sh[tid], sh[tid+st]); __syncthreads(); }
    float M = sh[0]; __syncthreads();
    float sum = 0.f;
#pragma unroll
    for (int i = 0; i < 5; i++) {
        int idx = tid + i*256;
        if (idx < MB) { v[i] = __expf(v[i] - M); sum += v[i]; }
    }
    sh[tid] = sum; __syncthreads();
    for (int st = 128; st > 0; st >>= 1) { if (tid < st) sh[tid] += sh[tid+st]; __syncthreads(); }
    float inv = 1.f / sh[0];
#pragma unroll
    for (int i = 0; i < 5; i++) {
        int idx = tid + i*256;
        if (idx < MB) p[idx] = v[i] * inv;
    }
}

__global__ __launch_bounds__(256) void attnV()
{
    __shared__ float As[32][33], Bs[32][132];
    int z = blockIdx.z;
    int n0 = blockIdx.x * 128;
    float acc[4][4] = {};
    nn_body(As, Bs, d_scores + (long long)z*B*MB, MB, d_Vc + z*DK, D, n0, 0, MB/32, acc);
    float* C = d_att + z*DK;
    int mt = threadIdx.x >> 5, nt = threadIdx.x & 31;
#pragma unroll
    for (int i = 0; i < 4; i++)
#pragma unroll
        for (int j = 0; j < 4; j++)
            C[(long long)(mt*4+i)*D + n0 + nt + 32*j] = acc[i][j];
}

/* Wo with fused residual + layer broadcast: hupd[l] = e + att@Wo^T + bo + hcur[l] */
__global__ __launch_bounds__(256) void wo_g(const float* __restrict__ Wo,
    const float* __restrict__ bo, const float* __restrict__ e)
{
    __shared__ float As[32][33], Bs[32][129];
    int n0 = blockIdx.x * 128;
    float acc[4][4] = {};
    nt_body(As, Bs, d_att, D, Wo, D, n0, D, 0, 32, acc);
    int mt = threadIdx.x >> 5, nt = threadIdx.x & 31;
#pragma unroll
    for (int i = 0; i < 4; i++)
#pragma unroll
        for (int j = 0; j < 4; j++) {
            int n = n0 + nt + 32*j;
            long long idx = (long long)(mt*4+i)*D + n;
            float v = acc[i][j] + bo[n] + e[idx];
            d_hupd[idx]      = v + d_hcur[idx];
            d_hupd[BD + idx] = v + d_hcur[BD + idx];
        }
}

/* LSTM gates split-K: K=2048 = [x(1024)|hupd(1024)], 8 chunks of 256 -> partials */
__global__ __launch_bounds__(256) void lstm_g(const float* __restrict__ Aa,
    const float* __restrict__ Ab, const float* __restrict__ W1, const float* __restrict__ W2)
{
    __shared__ float As[32][33], Bs[32][129];
    int kb = blockIdx.y * 256;
    const float* A; const float* W; int kbeg;
    if (kb < 1024) { A = Aa; W = W1; kbeg = kb; } else { A = Ab; W = W2; kbeg = kb - 1024; }
    int n0 = blockIdx.x * 128;
    float acc[4][4] = {};
    nt_body(As, Bs, A, D, W, D, n0, 4096, kbeg, 8, acc);
    float* C = d_lstmpart + (long long)blockIdx.y * (B*4096);
    int mt = threadIdx.x >> 5, nt = threadIdx.x & 31;
#pragma unroll
    for (int i = 0; i < 4; i++)
#pragma unroll
        for (int j = 0; j < 4; j++)
            C[(long long)(mt*4+i)*4096 + n0 + nt + 32*j] = acc[i][j];
}

__global__ __launch_bounds__(256) void lstm_cell2(int l, int slot,
    const float* __restrict__ bi, const float* __restrict__ bh, int writeX, int t)
{
    int idx = blockIdx.x * 256 + threadIdx.x;
    int b = idx >> 10, d = idx & 1023;
    const float* p = d_lstmpart + (long long)b * 4096 + d;
    float gi = bi[d] + bh[d];
    float gf = bi[1024+d] + bh[1024+d];
    float gg = bi[2048+d] + bh[2048+d];
    float go = bi[3072+d] + bh[3072+d];
#pragma unroll
    for (int s = 0; s < 8; s++) {
        const float* q = p + (long long)s * (B*4096);
        gi += q[0]; gf += q[1024]; gg += q[2048]; go += q[3072];
    }
    float cp = d_ccur[l*BD + idx];
    float si = 1.f / (1.f + __expf(-gi));
    float sf = 1.f / (1.f + __expf(-gf));
    float so = 1.f / (1.f + __expf(-go));
    float cn = sf * cp + si * tanhf(gg);
    float hn = so * tanhf(cn);
    d_hcur[l*BD + idx] = hn;
    d_ccur[l*BD + idx] = cn;
    d_Hh[((long long)l*MEM + slot)*BD + idx] = hn;
    d_Ch[((long long)l*MEM + slot)*BD + idx] = cn;
    if (writeX) d_X[(long long)t*BD + idx] = hn;
}

/* ---------------- decode SGEMM (128x128x16, 8x8 microtile) ---------------- */
__global__ __launch_bounds__(256) void sgemm_decode(const float* __restrict__ A,
    const float* __restrict__ Bw, const float* __restrict__ bias, float* __restrict__ C)
{
    __shared__ __align__(16) float As[16][132];
    __shared__ __align__(16) float Bs[16][132];
    int tid = threadIdx.x;
    int m0 = blockIdx.y * 128, n0 = blockIdx.x * 128;
    int tx = tid & 15, ty = tid >> 4;
    int lr = tid >> 2, lk4 = (tid & 3) * 4;
    float acc[8][8] = {};
    for (int k0 = 0; k0 < 1024; k0 += 16) {
        float4 a0 = *(const float4*)(A  + (long)(m0 + lr)      * 1024 + k0 + lk4);
        float4 a1 = *(const float4*)(A  + (long)(m0 + lr + 64) * 1024 + k0 + lk4);
        float4 b0 = *(const float4*)(Bw + (long)(n0 + lr)      * 1024 + k0 + lk4);
        float4 b1 = *(const float4*)(Bw + (long)(n0 + lr + 64) * 1024 + k0 + lk4);
        __syncthreads();
        As[lk4+0][lr]=a0.x; As[lk4+1][lr]=a0.y; As[lk4+2][lr]=a0.z; As[lk4+3][lr]=a0.w;
        As[lk4+0][lr+64]=a1.x; As[lk4+1][lr+64]=a1.y; As[lk4+2][lr+64]=a1.z; As[lk4+3][lr+64]=a1.w;
        Bs[lk4+0][lr]=b0.x; Bs[lk4+1][lr]=b0.y; Bs[lk4+2][lr]=b0.z; Bs[lk4+3][lr]=b0.w;
        Bs[lk4+0][lr+64]=b1.x; Bs[lk4+1][lr+64]=b1.y; Bs[lk4+2][lr+64]=b1.z; Bs[lk4+3][lr+64]=b1.w;
        __syncthreads();
#pragma unroll
        for (int kk = 0; kk < 16; kk++) {
            float a[8], b[8];
            *(float4*)&a[0] = *(const float4*)&As[kk][ty*8];
            *(float4*)&a[4] = *(const float4*)&As[kk][ty*8 + 4];
            *(float4*)&b[0] = *(const float4*)&Bs[kk][tx*8];
            *(float4*)&b[4] = *(const float4*)&Bs[kk][tx*8 + 4];
#pragma unroll
            for (int i = 0; i < 8; i++)
#pragma unroll
                for (int j = 0; j < 8; j++)
                    acc[i][j] += a[i] * b[j];
        }
    }
    float bs[8];
#pragma unroll
    for (int j = 0; j < 8; j++) bs[j] = bias[n0 + tx*8 + j];
#pragma unroll
    for (int i = 0; i < 8; i++) {
        long row = m0 + ty*8 + i;
        float4 v0 = make_float4(acc[i][0]+bs[0], acc[i][1]+bs[1], acc[i][2]+bs[2], acc[i][3]+bs[3]);
        float4 v1 = make_float4(acc[i][4]+bs[4], acc[i][5]+bs[5], acc[i][6]+bs[6], acc[i][7]+bs[7]);
        *(float4*)(C + row*NTOK + n0 + tx*8)     = v0;
        *(float4*)(C + row*NTOK + n0 + tx*8 + 4) = v1;
    }
}

/* ---------------- host launch ---------------- */
extern "C" void kernel_launch(void* const* d_in, const int* in_sizes, int n_in,
                              void* d_out, int out_size)
{
    (void)in_sizes; (void)n_in; (void)out_size;
    const int*   tok  = (const int*)d_in[0];
    const float* emb  = (const float*)d_in[1];
    const float* ln_g = (const float*)d_in[2];
    const float* ln_b = (const float*)d_in[3];
    const float* Wq = (const float*)d_in[4];  const float* bq = (const float*)d_in[5];
    const float* Wk = (const float*)d_in[6];  const float* bk = (const float*)d_in[7];
    const float* Wv = (const float*)d_in[8];  const float* bv = (const float*)d_in[9];
    const float* Wo = (const float*)d_in[10]; const float* bo = (const float*)d_in[11];
    const float* Wih = (const float*)d_in[12]; const float* bih = (const float*)d_in[13];
    const float* Whh = (const float*)d_in[14]; const float* bhh = (const float*)d_in[15];
    const float* dW = (const float*)d_in[16]; const float* db = (const float*)d_in[17];
    const float* h0 = (const float*)d_in[18]; const float* c0 = (const float*)d_in[19];
    const float* H0 = (const float*)d_in[20]; const float* C0 = (const float*)d_in[21];
    float* out = (float*)d_out;

    float *p_eAll, *p_lnAll, *p_hcur, *p_hupd, *p_X;
    cudaGetSymbolAddress((void**)&p_eAll,  d_eAll);
    cudaGetSymbolAddress((void**)&p_lnAll, d_lnAll);
    cudaGetSymbolAddress((void**)&p_hcur,  d_hcur);
    cudaGetSymbolAddress((void**)&p_hupd,  d_hupd);
    cudaGetSymbolAddress((void**)&p_X,     d_X);

    init_state<<<8960, 256>>>(h0, c0, H0, C0);
    embed_all<<<T_STEPS*B, 256>>>(tok, emb, ln_g, ln_b);
    kv_init<<<dim3(8, 35, 2), 256>>>(H0, Wk, Wv, bk, bv);

    for (int t = 0; t < T_STEPS; t++) {
        int slot = t % MEM;
        int slotPrev = (t + MEM - 1) % MEM;
        qkv3<<<dim3(8, 1, t == 0 ? 1 : 3), 256>>>(p_lnAll + (long long)t*BD, p_hcur,
                                                  Wq, bq, Wk, bk, Wv, bv, slotPrev);
        scores_k<<<dim3(9, 1, HEADS), 256>>>();
        softmax_rows<<<HEADS*B, 256>>>();
        attnV<<<dim3(4, 1, HEADS), 256>>>();
        wo_g<<<8, 256>>>(Wo, bo, p_eAll + (long long)t*BD);
        lstm_g<<<dim3(32, 8), 256>>>(p_eAll + (long long)t*BD, p_hupd, Wih, Whh);
        lstm_cell2<<<128, 256>>>(0, slot, bih, bhh, 0, t);
        lstm_g<<<dim3(32, 8), 256>>>(p_hcur, p_hupd + BD, Wih + 4096*1024, Whh + 4096*1024);
        lstm_cell2<<<128, 256>>>(1, slot, bih + 4096, bhh + 4096, 1, t);
    }

    sgemm_decode<<<dim3(NTOK/128, (T_STEPS*B)/128), 256>>>(p_X, dW, db, out);
    write_tail<<<8960, 256>>>(out);
}

// round 4
// speedup vs baseline: 3.3442x; 1.9347x over previous
#include <cuda_runtime.h>
#include <math.h>

#define T_STEPS 64
#define B 32
#define D 1024
#define L 2
#define MEM 35
#define NTOK 32000
#define HEADS 2
#define DK 512
#define MB (MEM*B)
#define BD (B*D)
#define EPS 1e-6f
#define ATT_SCALE 0.04419417382415922f

#define OFF_H   65536000L
#define OFF_C   65601536L
#define OFF_HM  65667072L
#define OFF_CM  67960832L

__device__ float d_eAll[T_STEPS*BD];
__device__ float d_lnAll[T_STEPS*BD];
__device__ float d_q[BD];
__device__ float d_qkvpart[12*BD];
__device__ float d_scpart[2*HEADS*B*MB];
__device__ float d_probs[HEADS*B*MB];
__device__ float d_apart[5*BD];
__device__ float d_wopart[4*BD];
__device__ float d_hupd[L*BD];
__device__ float d_lstmpart[16*B*4096];
__device__ float d_hcur[L*BD];
__device__ float d_ccur[L*BD];
__device__ float d_Kc[MB*D];
__device__ float d_Vc[MB*D];
__device__ float d_Hh[L*MEM*BD];
__device__ float d_Ch[L*MEM*BD];
__device__ float d_X[T_STEPS*BD];

/* ---------------- skinny-GEMM cores (M=32, BN=128) ---------------- */
template<int AP>
__device__ __forceinline__ void nt_body(float (*As)[33], float (*Bs)[129],
    const float* A, int lda, long long aStride, const float* W, int ldw,
    int n0, int Nrows, int kbeg, int ntiles, float acc[4][4])
{
    int tid = threadIdx.x;
    int lm = tid >> 3, lk4 = (tid & 7) * 4;
    int mt = tid >> 5, nt = tid & 31;
    const float* arow = A + (long long)lm*lda + kbeg + lk4;
    const float* wr0 = W + kbeg + lk4;
    long long woff[4]; bool wok[4];
#pragma unroll
    for (int c = 0; c < 4; c++) {
        int n = n0 + lm + 32*c;
        wok[c] = (n < Nrows);
        woff[c] = (long long)(wok[c] ? n : 0) * ldw;
    }
    float4 z4 = make_float4(0.f,0.f,0.f,0.f);
    float4 pa = *(const float4*)arow;
#pragma unroll
    for (int p = 1; p < AP; p++) {
        float4 u = *(const float4*)(arow + (long long)p*aStride);
        pa.x += u.x; pa.y += u.y; pa.z += u.z; pa.w += u.w;
    }
    float4 pb[4];
#pragma unroll
    for (int c = 0; c < 4; c++) pb[c] = wok[c] ? *(const float4*)(wr0 + woff[c]) : z4;
    for (int kt = 0; kt < ntiles; kt++) {
        __syncthreads();
        As[lk4+0][lm]=pa.x; As[lk4+1][lm]=pa.y; As[lk4+2][lm]=pa.z; As[lk4+3][lm]=pa.w;
#pragma unroll
        for (int c = 0; c < 4; c++) {
            int n = lm + 32*c;
            Bs[lk4+0][n]=pb[c].x; Bs[lk4+1][n]=pb[c].y; Bs[lk4+2][n]=pb[c].z; Bs[lk4+3][n]=pb[c].w;
        }
        __syncthreads();
        if (kt + 1 < ntiles) {
            int ko = (kt+1)*32;
            pa = *(const float4*)(arow + ko);
#pragma unroll
            for (int p = 1; p < AP; p++) {
                float4 u = *(const float4*)(arow + ko + (long long)p*aStride);
                pa.x += u.x; pa.y += u.y; pa.z += u.z; pa.w += u.w;
            }
#pragma unroll
            for (int c = 0; c < 4; c++) pb[c] = wok[c] ? *(const float4*)(wr0 + woff[c] + ko) : z4;
        }
#pragma unroll
        for (int kk = 0; kk < 32; kk++) {
            float a0=As[kk][mt*4+0], a1=As[kk][mt*4+1], a2=As[kk][mt*4+2], a3=As[kk][mt*4+3];
            float b0=Bs[kk][nt], b1=Bs[kk][nt+32], b2=Bs[kk][nt+64], b3=Bs[kk][nt+96];
            acc[0][0]+=a0*b0; acc[0][1]+=a0*b1; acc[0][2]+=a0*b2; acc[0][3]+=a0*b3;
            acc[1][0]+=a1*b0; acc[1][1]+=a1*b1; acc[1][2]+=a1*b2; acc[1][3]+=a1*b3;
            acc[2][0]+=a2*b0; acc[2][1]+=a2*b1; acc[2][2]+=a2*b2; acc[2][3]+=a2*b3;
            acc[3][0]+=a3*b0; acc[3][1]+=a3*b1; acc[3][2]+=a3*b2; acc[3][3]+=a3*b3;
        }
    }
}

__device__ __forceinline__ void nn_body(float (*As)[33], float (*Bs)[132],
    const float* A, int lda, const float* Bm, int ldb,
    int n0, int kbeg, int ntiles, float acc[4][4])
{
    int tid = threadIdx.x;
    int lm = tid >> 3, lk4 = (tid & 7) * 4;
    int mt = tid >> 5, nt = tid & 31;
    const float* arow = A + (long long)lm*lda + kbeg + lk4;
    int brow = tid >> 5, bcol = (tid & 31) * 4;
    const float* bbase = Bm + (long long)(kbeg + brow)*ldb + n0 + bcol;
    float4 pa = *(const float4*)arow;
    float4 pb[4];
#pragma unroll
    for (int c = 0; c < 4; c++) pb[c] = *(const float4*)(bbase + (long long)(8*c)*ldb);
    for (int kt = 0; kt < ntiles; kt++) {
        __syncthreads();
        As[lk4+0][lm]=pa.x; As[lk4+1][lm]=pa.y; As[lk4+2][lm]=pa.z; As[lk4+3][lm]=pa.w;
#pragma unroll
        for (int c = 0; c < 4; c++) *(float4*)&Bs[brow+8*c][bcol] = pb[c];
        __syncthreads();
        if (kt + 1 < ntiles) {
            int ko = (kt+1)*32;
            pa = *(const float4*)(arow + ko);
#pragma unroll
            for (int c = 0; c < 4; c++) pb[c] = *(const float4*)(bbase + (long long)(ko + 8*c)*ldb);
        }
#pragma unroll
        for (int kk = 0; kk < 32; kk++) {
            float a0=As[kk][mt*4+0], a1=As[kk][mt*4+1], a2=As[kk][mt*4+2], a3=As[kk][mt*4+3];
            float b0=Bs[kk][nt], b1=Bs[kk][nt+32], b2=Bs[kk][nt+64], b3=Bs[kk][nt+96];
            acc[0][0]+=a0*b0; acc[0][1]+=a0*b1; acc[0][2]+=a0*b2; acc[0][3]+=a0*b3;
            acc[1][0]+=a1*b0; acc[1][1]+=a1*b1; acc[1][2]+=a1*b2; acc[1][3]+=a1*b3;
            acc[2][0]+=a2*b0; acc[2][1]+=a2*b1; acc[2][2]+=a2*b2; acc[2][3]+=a2*b3;
            acc[3][0]+=a3*b0; acc[3][1]+=a3*b1; acc[3][2]+=a3*b2; acc[3][3]+=a3*b3;
        }
    }
}

/* ---------------- init / embed / tail ---------------- */
__global__ __launch_bounds__(256) void init_state(const float* __restrict__ h0,
    const float* __restrict__ c0, const float* __restrict__ H0, const float* __restrict__ C0)
{
    long i = (long)blockIdx.x * 256 + threadIdx.x;
    if (i < (long)L*BD) { d_hcur[i] = h0[i]; d_ccur[i] = c0[i]; }
    if (i < (long)L*MEM*BD) { d_Hh[i] = H0[i]; d_Ch[i] = C0[i]; }
}

__global__ __launch_bounds__(256) void write_tail(float* __restrict__ out)
{
    long i = (long)blockIdx.x * 256 + threadIdx.x;
    if (i >= (long)L*MEM*BD) return;
    if (i < (long)L*BD) { out[OFF_H + i] = d_hcur[i]; out[OFF_C + i] = d_ccur[i]; }
    long l = i / ((long)MEM*BD);
    long r = i % ((long)MEM*BD);
    long j = r / BD, q = r % BD;
    long phys = (T_STEPS + j) % MEM;
    out[OFF_HM + i] = d_Hh[(l*MEM + phys)*(long)BD + q];
    out[OFF_CM + i] = d_Ch[(l*MEM + phys)*(long)BD + q];
}

__global__ __launch_bounds__(256) void embed_all(const int* __restrict__ tok,
    const float* __restrict__ emb, const float* __restrict__ gg, const float* __restrict__ bb)
{
    __shared__ float sh[256];
    int r = blockIdx.x, tid = threadIdx.x;
    const float* row = emb + (long)tok[r] * D;
    float x[4]; float s = 0.f;
#pragma unroll
    for (int i = 0; i < 4; i++) { x[i] = row[tid + i*256]; s += x[i]; }
    sh[tid] = s; __syncthreads();
    for (int st = 128; st > 0; st >>= 1) { if (tid < st) sh[tid] += sh[tid+st]; __syncthreads(); }
    float mu = sh[0] * (1.f / D); __syncthreads();
    float ss = 0.f;
#pragma unroll
    for (int i = 0; i < 4; i++) { float dd = x[i] - mu; ss += dd*dd; }
    sh[tid] = ss; __syncthreads();
    for (int st = 128; st > 0; st >>= 1) { if (tid < st) sh[tid] += sh[tid+st]; __syncthreads(); }
    float inv = 1.f / (sqrtf(sh[0] / (float)(D - 1)) + EPS);
#pragma unroll
    for (int i = 0; i < 4; i++) {
        int idx = tid + i*256;
        d_eAll[(long)r*D + idx]  = x[i];
        d_lnAll[(long)r*D + idx] = gg[idx] * (x[i] - mu) * inv + bb[idx];
    }
}

/* ---------------- per-step GEMM kernels (all split-K) ---------------- */
__global__ __launch_bounds__(256) void kv_init(const float* __restrict__ H0,
    const float* __restrict__ Wk, const float* __restrict__ Wv,
    const float* __restrict__ bk, const float* __restrict__ bv)
{
    __shared__ float As[32][33], Bs[32][129];
    int z = blockIdx.z;
    const float* W = z ? Wv : Wk;
    const float* bias = z ? bv : bk;
    float* C = (z ? d_Vc : d_Kc) + (long long)blockIdx.y * 32 * D;
    const float* A = H0 + (long long)blockIdx.y * 32 * D;
    int n0 = blockIdx.x * 128;
    float acc[4][4] = {};
    nt_body<1>(As, Bs, A, D, 0, W, D, n0, D, 0, 32, acc);
    int mt = threadIdx.x >> 5, nt = threadIdx.x & 31;
#pragma unroll
    for (int i = 0; i < 4; i++)
#pragma unroll
        for (int j = 0; j < 4; j++) {
            int n = n0 + nt + 32*j;
            C[(long long)(mt*4+i)*D + n] = acc[i][j] + bias[n];
        }
}

/* split-K qkv: grid (8, 4, z) -> partials [ks][z][BD] */
__global__ __launch_bounds__(256) void qkv3s(const float* __restrict__ ln,
    const float* __restrict__ hsrc, const float* __restrict__ Wq,
    const float* __restrict__ Wk, const float* __restrict__ Wv)
{
    __shared__ float As[32][33], Bs[32][129];
    int ks = blockIdx.y, z = blockIdx.z;
    const float* A = (z == 0) ? ln : hsrc;
    const float* W = (z == 0) ? Wq : ((z == 1) ? Wk : Wv);
    float* C = d_qkvpart + (long long)(ks*3 + z) * BD;
    int n0 = blockIdx.x * 128;
    float acc[4][4] = {};
    nt_body<1>(As, Bs, A, D, 0, W, D, n0, D, ks*256, 8, acc);
    int mt = threadIdx.x >> 5, nt = threadIdx.x & 31;
#pragma unroll
    for (int i = 0; i < 4; i++)
#pragma unroll
        for (int j = 0; j < 4; j++)
            C[(long long)(mt*4+i)*D + n0 + nt + 32*j] = acc[i][j];
}

__global__ __launch_bounds__(256) void qkv_red(const float* __restrict__ bq,
    const float* __restrict__ bk, const float* __restrict__ bv, int slotPrev, int writeKV)
{
    int i = blockIdx.x * 256 + threadIdx.x;      /* < 3*BD */
    int z = i >> 15, j = i & (BD-1);
    if (z && !writeKV) return;
    float v = 0.f;
#pragma unroll
    for (int s = 0; s < 4; s++) v += d_qkvpart[(long long)(s*3 + z)*BD + j];
    int col = j & 1023;
    if (z == 0)      d_q[j] = v + bq[col];
    else if (z == 1) d_Kc[(long long)slotPrev*BD + j] = v + bk[col];
    else             d_Vc[(long long)slotPrev*BD + j] = v + bv[col];
}

/* scores split-K: grid (9, 2, 2) -> partials [ks][z][B][MB] */
__global__ __launch_bounds__(256) void scores_ks()
{
    __shared__ float As[32][33], Bs[32][129];
    int ks = blockIdx.y, z = blockIdx.z;
    int n0 = blockIdx.x * 128;
    float acc[4][4] = {};
    nt_body<1>(As, Bs, d_q + z*DK, D, 0, d_Kc + z*DK, D, n0, MB, ks*256, 8, acc);
    float* C = d_scpart + (long long)(ks*HEADS + z) * (B*MB);
    int mt = threadIdx.x >> 5, nt = threadIdx.x & 31;
#pragma unroll
    for (int i = 0; i < 4; i++)
#pragma unroll
        for (int j = 0; j < 4; j++) {
            int n = n0 + nt + 32*j;
            if (n < MB) C[(long long)(mt*4+i)*MB + n] = acc[i][j];
        }
}

__global__ __launch_bounds__(256) void softmax2()
{
    __shared__ float sh[256];
    int row = blockIdx.x, tid = threadIdx.x;     /* row < HEADS*B */
    const float* p0 = d_scpart + (long)row * MB;
    const float* p1 = p0 + (long)HEADS*B*MB;
    float* po = d_probs + (long)row * MB;
    float v[5]; float mx = -1e30f;
#pragma unroll
    for (int i = 0; i < 5; i++) {
        int idx = tid + i*256; v[i] = -1e30f;
        if (idx < MB) { v[i] = (p0[idx] + p1[idx]) * ATT_SCALE; mx = fmaxf(mx, v[i]); }
    }
    sh[tid] = mx; __syncthreads();
    for (int st = 128; st > 0; st >>= 1) { if (tid < st) sh[tid] = fmaxf(sh[tid], sh[tid+st]); __syncthreads(); }
    float M = sh[0]; __syncthreads();
    float sum = 0.f;
#pragma unroll
    for (int i = 0; i < 5; i++) {
        int idx = tid + i*256;
        if (idx < MB) { v[i] = __expf(v[i] - M); sum += v[i]; }
    }
    sh[tid] = sum; __syncthreads();
    for (int st = 128; st > 0; st >>= 1) { if (tid < st) sh[tid] += sh[tid+st]; __syncthreads(); }
    float inv = 1.f / sh[0];
#pragma unroll
    for (int i = 0; i < 5; i++) {
        int idx = tid + i*256;
        if (idx < MB) po[idx] = v[i] * inv;
    }
}

/* attn@V split over MB: grid (4, 5, 2) -> partials [ks][32 x 1024] (head z -> cols z*512..) */
__global__ __launch_bounds__(256) void attnVs()
{
    __shared__ float As[32][33], Bs[32][132];
    int ks = blockIdx.y, z = blockIdx.z;
    int n0 = blockIdx.x * 128;
    float acc[4][4] = {};
    nn_body(As, Bs, d_probs + (long long)z*B*MB, MB, d_Vc + z*DK, D, n0, ks*224, 7, acc);
    float* C = d_apart + (long long)ks*BD + z*DK;
    int mt = threadIdx.x >> 5, nt = threadIdx.x & 31;
#pragma unroll
    for (int i = 0; i < 4; i++)
#pragma unroll
        for (int j = 0; j < 4; j++)
            C[(long long)(mt*4+i)*D + n0 + nt + 32*j] = acc[i][j];
}

/* Wo split-K with 5-way A-sum fused in loader: grid (8, 4) */
__global__ __launch_bounds__(256) void wo_gs(const float* __restrict__ Wo)
{
    __shared__ float As[32][33], Bs[32][129];
    int ks = blockIdx.y;
    int n0 = blockIdx.x * 128;
    float acc[4][4] = {};
    nt_body<5>(As, Bs, d_apart, D, BD, Wo, D, n0, D, ks*256, 8, acc);
    float* C = d_wopart + (long long)ks*BD;
    int mt = threadIdx.x >> 5, nt = threadIdx.x & 31;
#pragma unroll
    for (int i = 0; i < 4; i++)
#pragma unroll
        for (int j = 0; j < 4; j++)
            C[(long long)(mt*4+i)*D + n0 + nt + 32*j] = acc[i][j];
}

__global__ __launch_bounds__(256) void wo_red(const float* __restrict__ bo,
                                              const float* __restrict__ e)
{
    int i = blockIdx.x * 256 + threadIdx.x;      /* < BD */
    float v = bo[i & 1023] + e[i];
#pragma unroll
    for (int s = 0; s < 4; s++) v += d_wopart[(long long)s*BD + i];
    d_hupd[i]      = v + d_hcur[i];
    d_hupd[BD + i] = v + d_hcur[BD + i];
}

/* LSTM split-K x16: grid (32, 16) -> partials [16][B*4096] */
__global__ __launch_bounds__(256) void lstm_g(const float* __restrict__ Aa,
    const float* __restrict__ Ab, const float* __restrict__ W1, const float* __restrict__ W2)
{
    __shared__ float As[32][33], Bs[32][129];
    int kb = blockIdx.y * 128;
    const float* A; const float* W; int kbeg;
    if (kb < 1024) { A = Aa; W = W1; kbeg = kb; } else { A = Ab; W = W2; kbeg = kb - 1024; }
    int n0 = blockIdx.x * 128;
    float acc[4][4] = {};
    nt_body<1>(As, Bs, A, D, 0, W, D, n0, 4096, kbeg, 4, acc);
    float* C = d_lstmpart + (long long)blockIdx.y * (B*4096);
    int mt = threadIdx.x >> 5, nt = threadIdx.x & 31;
#pragma unroll
    for (int i = 0; i < 4; i++)
#pragma unroll
        for (int j = 0; j < 4; j++)
            C[(long long)(mt*4+i)*4096 + n0 + nt + 32*j] = acc[i][j];
}

__global__ __launch_bounds__(256) void lstm_cell2(int l, int slot,
    const float* __restrict__ bi, const float* __restrict__ bh, int writeX, int t)
{
    int idx = blockIdx.x * 256 + threadIdx.x;
    int b = idx >> 10, d = idx & 1023;
    const float* p = d_lstmpart + (long long)b * 4096 + d;
    float gi = bi[d] + bh[d];
    float gf = bi[1024+d] + bh[1024+d];
    float gg = bi[2048+d] + bh[2048+d];
    float go = bi[3072+d] + bh[3072+d];
#pragma unroll
    for (int s = 0; s < 16; s++) {
        const float* q = p + (long long)s * (B*4096);
        gi += q[0]; gf += q[1024]; gg += q[2048]; go += q[3072];
    }
    float cp = d_ccur[l*BD + idx];
    float si = 1.f / (1.f + __expf(-gi));
    float sf = 1.f / (1.f + __expf(-gf));
    float so = 1.f / (1.f + __expf(-go));
    float cn = sf * cp + si * tanhf(gg);
    float hn = so * tanhf(cn);
    d_hcur[l*BD + idx] = hn;
    d_ccur[l*BD + idx] = cn;
    d_Hh[((long long)l*MEM + slot)*BD + idx] = hn;
    d_Ch[((long long)l*MEM + slot)*BD + idx] = cn;
    if (writeX) d_X[(long long)t*BD + idx] = hn;
}

/* ---------------- decode SGEMM (128x128x16, 8x8 microtile) ---------------- */
__global__ __launch_bounds__(256) void sgemm_decode(const float* __restrict__ A,
    const float* __restrict__ Bw, const float* __restrict__ bias, float* __restrict__ C)
{
    __shared__ __align__(16) float As[16][132];
    __shared__ __align__(16) float Bs[16][132];
    int tid = threadIdx.x;
    int m0 = blockIdx.y * 128, n0 = blockIdx.x * 128;
    int tx = tid & 15, ty = tid >> 4;
    int lr = tid >> 2, lk4 = (tid & 3) * 4;
    float acc[8][8] = {};
    for (int k0 = 0; k0 < 1024; k0 += 16) {
        float4 a0 = *(const float4*)(A  + (long)(m0 + lr)      * 1024 + k0 + lk4);
        float4 a1 = *(const float4*)(A  + (long)(m0 + lr + 64) * 1024 + k0 + lk4);
        float4 b0 = *(const float4*)(Bw + (long)(n0 + lr)      * 1024 + k0 + lk4);
        float4 b1 = *(const float4*)(Bw + (long)(n0 + lr + 64) * 1024 + k0 + lk4);
        __syncthreads();
        As[lk4+0][lr]=a0.x; As[lk4+1][lr]=a0.y; As[lk4+2][lr]=a0.z; As[lk4+3][lr]=a0.w;
        As[lk4+0][lr+64]=a1.x; As[lk4+1][lr+64]=a1.y; As[lk4+2][lr+64]=a1.z; As[lk4+3][lr+64]=a1.w;
        Bs[lk4+0][lr]=b0.x; Bs[lk4+1][lr]=b0.y; Bs[lk4+2][lr]=b0.z; Bs[lk4+3][lr]=b0.w;
        Bs[lk4+0][lr+64]=b1.x; Bs[lk4+1][lr+64]=b1.y; Bs[lk4+2][lr+64]=b1.z; Bs[lk4+3][lr+64]=b1.w;
        __syncthreads();
#pragma unroll
        for (int kk = 0; kk < 16; kk++) {
            float a[8], b[8];
            *(float4*)&a[0] = *(const float4*)&As[kk][ty*8];
            *(float4*)&a[4] = *(const float4*)&As[kk][ty*8 + 4];
            *(float4*)&b[0] = *(const float4*)&Bs[kk][tx*8];
            *(float4*)&b[4] = *(const float4*)&Bs[kk][tx*8 + 4];
#pragma unroll
            for (int i = 0; i < 8; i++)
#pragma unroll
                for (int j = 0; j < 8; j++)
                    acc[i][j] += a[i] * b[j];
        }
    }
    float bs[8];
#pragma unroll
    for (int j = 0; j < 8; j++) bs[j] = bias[n0 + tx*8 + j];
#pragma unroll
    for (int i = 0; i < 8; i++) {
        long row = m0 + ty*8 + i;
        float4 v0 = make_float4(acc[i][0]+bs[0], acc[i][1]+bs[1], acc[i][2]+bs[2], acc[i][3]+bs[3]);
        float4 v1 = make_float4(acc[i][4]+bs[4], acc[i][5]+bs[5], acc[i][6]+bs[6], acc[i][7]+bs[7]);
        *(float4*)(C + row*NTOK + n0 + tx*8)     = v0;
        *(float4*)(C + row*NTOK + n0 + tx*8 + 4) = v1;
    }
}

/* ---------------- host launch ---------------- */
extern "C" void kernel_launch(void* const* d_in, const int* in_sizes, int n_in,
                              void* d_out, int out_size)
{
    (void)in_sizes; (void)n_in; (void)out_size;
    const int*   tok  = (const int*)d_in[0];
    const float* emb  = (const float*)d_in[1];
    const float* ln_g = (const float*)d_in[2];
    const float* ln_b = (const float*)d_in[3];
    const float* Wq = (const float*)d_in[4];  const float* bq = (const float*)d_in[5];
    const float* Wk = (const float*)d_in[6];  const float* bk = (const float*)d_in[7];
    const float* Wv = (const float*)d_in[8];  const float* bv = (const float*)d_in[9];
    const float* Wo = (const float*)d_in[10]; const float* bo = (const float*)d_in[11];
    const float* Wih = (const float*)d_in[12]; const float* bih = (const float*)d_in[13];
    const float* Whh = (const float*)d_in[14]; const float* bhh = (const float*)d_in[15];
    const float* dW = (const float*)d_in[16]; const float* db = (const float*)d_in[17];
    const float* h0 = (const float*)d_in[18]; const float* c0 = (const float*)d_in[19];
    const float* H0 = (const float*)d_in[20]; const float* C0 = (const float*)d_in[21];
    float* out = (float*)d_out;

    float *p_eAll, *p_lnAll, *p_hcur, *p_hupd, *p_X;
    cudaGetSymbolAddress((void**)&p_eAll,  d_eAll);
    cudaGetSymbolAddress((void**)&p_lnAll, d_lnAll);
    cudaGetSymbolAddress((void**)&p_hcur,  d_hcur);
    cudaGetSymbolAddress((void**)&p_hupd,  d_hupd);
    cudaGetSymbolAddress((void**)&p_X,     d_X);

    init_state<<<8960, 256>>>(h0, c0, H0, C0);
    embed_all<<<T_STEPS*B, 256>>>(tok, emb, ln_g, ln_b);
    kv_init<<<dim3(8, 35, 2), 256>>>(H0, Wk, Wv, bk, bv);

    for (int t = 0; t < T_STEPS; t++) {
        int slot = t % MEM;
        int slotPrev = (t + MEM - 1) % MEM;
        qkv3s<<<dim3(8, 4, t == 0 ? 1 : 3), 256>>>(p_lnAll + (long long)t*BD, p_hcur,
                                                   Wq, Wk, Wv);
        qkv_red<<<384, 256>>>(bq, bk, bv, slotPrev, t > 0);
        scores_ks<<<dim3(9, 2, HEADS), 256>>>();
        softmax2<<<HEADS*B, 256>>>();
        attnVs<<<dim3(4, 5, HEADS), 256>>>();
        wo_gs<<<dim3(8, 4), 256>>>(Wo);
        wo_red<<<128, 256>>>(bo, p_eAll + (long long)t*BD);
        lstm_g<<<dim3(32, 16), 256>>>(p_eAll + (long long)t*BD, p_hupd, Wih, Whh);
        lstm_cell2<<<128, 256>>>(0, slot, bih, bhh, 0, t);
        lstm_g<<<dim3(32, 16), 256>>>(p_hcur, p_hupd + BD, Wih + 4096*1024, Whh + 4096*1024);
        lstm_cell2<<<128, 256>>>(1, slot, bih + 4096, bhh + 4096, 1, t);
    }

    sgemm_decode<<<dim3(NTOK/128, (T_STEPS*B)/128), 256>>>(p_X, dW, db, out);
    write_tail<<<8960, 256>>>(out);
}

// round 8
// speedup vs baseline: 3.9348x; 1.1766x over previous
#include <cuda_runtime.h>
#include <cuda_bf16.h>
#include <stdint.h>
#include <math.h>

#define T_STEPS 64
#define B 32
#define D 1024
#define L 2
#define MEM 35
#define NTOK 32000
#define HEADS 2
#define DK 512
#define MB (MEM*B)
#define BD (B*D)
#define EPS 1e-6f
#define ATT_SCALE 0.04419417382415922f
#define DKC 3072

#define OFF_H   65536000L
#define OFF_C   65601536L
#define OFF_HM  65667072L
#define OFF_CM  67960832L

__device__ float d_eAll[T_STEPS*BD];
__device__ float d_lnAll[T_STEPS*BD];
__device__ float d_q[BD];
__device__ float d_qkvpart[12*BD];
__device__ float d_scpart[2*HEADS*B*MB];
__device__ float d_probs[HEADS*B*MB];
__device__ float d_apart[5*BD];
__device__ float d_wopart[4*BD];
__device__ float d_hupd[L*BD];
__device__ float d_lstmpart[16*B*4096];
__device__ float d_hcur[L*BD];
__device__ float d_ccur[L*BD];
__device__ float d_Kc[MB*D];
__device__ float d_Vc[MB*D];
__device__ float d_Hh[L*MEM*BD];
__device__ float d_Ch[L*MEM*BD];
__device__ float d_X[T_STEPS*BD];
__device__ __nv_bfloat16 d_Wcat[(long long)NTOK*DKC];
__device__ __nv_bfloat16 d_Xcat[(long long)T_STEPS*B*DKC];

/* ---------------- skinny-GEMM cores (M=32, BN=128) ---------------- */
template<int AP>
__device__ __forceinline__ void nt_body(float (*As)[33], float (*Bs)[129],
    const float* A, int lda, long long aStride, const float* W, int ldw,
    int n0, int Nrows, int kbeg, int ntiles, float acc[4][4])
{
    int tid = threadIdx.x;
    int lm = tid >> 3, lk4 = (tid & 7) * 4;
    int mt = tid >> 5, nt = tid & 31;
    const float* arow = A + (long long)lm*lda + kbeg + lk4;
    const float* wr0 = W + kbeg + lk4;
    long long woff[4]; bool wok[4];
#pragma unroll
    for (int c = 0; c < 4; c++) {
        int n = n0 + lm + 32*c;
        wok[c] = (n < Nrows);
        woff[c] = (long long)(wok[c] ? n : 0) * ldw;
    }
    float4 z4 = make_float4(0.f,0.f,0.f,0.f);
    float4 pa = *(const float4*)arow;
#pragma unroll
    for (int p = 1; p < AP; p++) {
        float4 u = *(const float4*)(arow + (long long)p*aStride);
        pa.x += u.x; pa.y += u.y; pa.z += u.z; pa.w += u.w;
    }
    float4 pb[4];
#pragma unroll
    for (int c = 0; c < 4; c++) pb[c] = wok[c] ? *(const float4*)(wr0 + woff[c]) : z4;
    for (int kt = 0; kt < ntiles; kt++) {
        __syncthreads();
        As[lk4+0][lm]=pa.x; As[lk4+1][lm]=pa.y; As[lk4+2][lm]=pa.z; As[lk4+3][lm]=pa.w;
#pragma unroll
        for (int c = 0; c < 4; c++) {
            int n = lm + 32*c;
            Bs[lk4+0][n]=pb[c].x; Bs[lk4+1][n]=pb[c].y; Bs[lk4+2][n]=pb[c].z; Bs[lk4+3][n]=pb[c].w;
        }
        __syncthreads();
        if (kt + 1 < ntiles) {
            int ko = (kt+1)*32;
            pa = *(const float4*)(arow + ko);
#pragma unroll
            for (int p = 1; p < AP; p++) {
                float4 u = *(const float4*)(arow + ko + (long long)p*aStride);
                pa.x += u.x; pa.y += u.y; pa.z += u.z; pa.w += u.w;
            }
#pragma unroll
            for (int c = 0; c < 4; c++) pb[c] = wok[c] ? *(const float4*)(wr0 + woff[c] + ko) : z4;
        }
#pragma unroll
        for (int kk = 0; kk < 32; kk++) {
            float a0=As[kk][mt*4+0], a1=As[kk][mt*4+1], a2=As[kk][mt*4+2], a3=As[kk][mt*4+3];
            float b0=Bs[kk][nt], b1=Bs[kk][nt+32], b2=Bs[kk][nt+64], b3=Bs[kk][nt+96];
            acc[0][0]+=a0*b0; acc[0][1]+=a0*b1; acc[0][2]+=a0*b2; acc[0][3]+=a0*b3;
            acc[1][0]+=a1*b0; acc[1][1]+=a1*b1; acc[1][2]+=a1*b2; acc[1][3]+=a1*b3;
            acc[2][0]+=a2*b0; acc[2][1]+=a2*b1; acc[2][2]+=a2*b2; acc[2][3]+=a2*b3;
            acc[3][0]+=a3*b0; acc[3][1]+=a3*b1; acc[3][2]+=a3*b2; acc[3][3]+=a3*b3;
        }
    }
}

__device__ __forceinline__ void nn_body(float (*As)[33], float (*Bs)[132],
    const float* A, int lda, const float* Bm, int ldb,
    int n0, int kbeg, int ntiles, float acc[4][4])
{
    int tid = threadIdx.x;
    int lm = tid >> 3, lk4 = (tid & 7) * 4;
    int mt = tid >> 5, nt = tid & 31;
    const float* arow = A + (long long)lm*lda + kbeg + lk4;
    int brow = tid >> 5, bcol = (tid & 31) * 4;
    const float* bbase = Bm + (long long)(kbeg + brow)*ldb + n0 + bcol;
    float4 pa = *(const float4*)arow;
    float4 pb[4];
#pragma unroll
    for (int c = 0; c < 4; c++) pb[c] = *(const float4*)(bbase + (long long)(8*c)*ldb);
    for (int kt = 0; kt < ntiles; kt++) {
        __syncthreads();
        As[lk4+0][lm]=pa.x; As[lk4+1][lm]=pa.y; As[lk4+2][lm]=pa.z; As[lk4+3][lm]=pa.w;
#pragma unroll
        for (int c = 0; c < 4; c++) *(float4*)&Bs[brow+8*c][bcol] = pb[c];
        __syncthreads();
        if (kt + 1 < ntiles) {
            int ko = (kt+1)*32;
            pa = *(const float4*)(arow + ko);
#pragma unroll
            for (int c = 0; c < 4; c++) pb[c] = *(const float4*)(bbase + (long long)(ko + 8*c)*ldb);
        }
#pragma unroll
        for (int kk = 0; kk < 32; kk++) {
            float a0=As[kk][mt*4+0], a1=As[kk][mt*4+1], a2=As[kk][mt*4+2], a3=As[kk][mt*4+3];
            float b0=Bs[kk][nt], b1=Bs[kk][nt+32], b2=Bs[kk][nt+64], b3=Bs[kk][nt+96];
            acc[0][0]+=a0*b0; acc[0][1]+=a0*b1; acc[0][2]+=a0*b2; acc[0][3]+=a0*b3;
            acc[1][0]+=a1*b0; acc[1][1]+=a1*b1; acc[1][2]+=a1*b2; acc[1][3]+=a1*b3;
            acc[2][0]+=a2*b0; acc[2][1]+=a2*b1; acc[2][2]+=a2*b2; acc[2][3]+=a2*b3;
            acc[3][0]+=a3*b0; acc[3][1]+=a3*b1; acc[3][2]+=a3*b2; acc[3][3]+=a3*b3;
        }
    }
}

/* ---------------- init / embed / tail ---------------- */
__global__ __launch_bounds__(256) void init_state(const float* __restrict__ h0,
    const float* __restrict__ c0, const float* __restrict__ H0, const float* __restrict__ C0)
{
    long i = (long)blockIdx.x * 256 + threadIdx.x;
    if (i < (long)L*BD) { d_hcur[i] = h0[i]; d_ccur[i] = c0[i]; }
    if (i < (long)L*MEM*BD) { d_Hh[i] = H0[i]; d_Ch[i] = C0[i]; }
}

__global__ __launch_bounds__(256) void write_tail(float* __restrict__ out)
{
    long i = (long)blockIdx.x * 256 + threadIdx.x;
    if (i >= (long)L*MEM*BD) return;
    if (i < (long)L*BD) { out[OFF_H + i] = d_hcur[i]; out[OFF_C + i] = d_ccur[i]; }
    long l = i / ((long)MEM*BD);
    long r = i % ((long)MEM*BD);
    long j = r / BD, q = r % BD;
    long phys = (T_STEPS + j) % MEM;
    out[OFF_HM + i] = d_Hh[(l*MEM + phys)*(long)BD + q];
    out[OFF_CM + i] = d_Ch[(l*MEM + phys)*(long)BD + q];
}

__global__ __launch_bounds__(256) void embed_all(const int* __restrict__ tok,
    const float* __restrict__ emb, const float* __restrict__ gg, const float* __restrict__ bb)
{
    __shared__ float sh[256];
    int r = blockIdx.x, tid = threadIdx.x;
    const float* row = emb + (long)tok[r] * D;
    float x[4]; float s = 0.f;
#pragma unroll
    for (int i = 0; i < 4; i++) { x[i] = row[tid + i*256]; s += x[i]; }
    sh[tid] = s; __syncthreads();
    for (int st = 128; st > 0; st >>= 1) { if (tid < st) sh[tid] += sh[tid+st]; __syncthreads(); }
    float mu = sh[0] * (1.f / D); __syncthreads();
    float ss = 0.f;
#pragma unroll
    for (int i = 0; i < 4; i++) { float dd = x[i] - mu; ss += dd*dd; }
    sh[tid] = ss; __syncthreads();
    for (int st = 128; st > 0; st >>= 1) { if (tid < st) sh[tid] += sh[tid+st]; __syncthreads(); }
    float inv = 1.f / (sqrtf(sh[0] / (float)(D - 1)) + EPS);
#pragma unroll
    for (int i = 0; i < 4; i++) {
        int idx = tid + i*256;
        d_eAll[(long)r*D + idx]  = x[i];
        d_lnAll[(long)r*D + idx] = gg[idx] * (x[i] - mu) * inv + bb[idx];
    }
}

/* ---------------- per-step GEMM kernels (split-K) ---------------- */
__global__ __launch_bounds__(256) void kv_init(const float* __restrict__ H0,
    const float* __restrict__ Wk, const float* __restrict__ Wv,
    const float* __restrict__ bk, const float* __restrict__ bv)
{
    __shared__ float As[32][33], Bs[32][129];
    int z = blockIdx.z;
    const float* W = z ? Wv : Wk;
    const float* bias = z ? bv : bk;
    float* C = (z ? d_Vc : d_Kc) + (long long)blockIdx.y * 32 * D;
    const float* A = H0 + (long long)blockIdx.y * 32 * D;
    int n0 = blockIdx.x * 128;
    float acc[4][4] = {};
    nt_body<1>(As, Bs, A, D, 0, W, D, n0, D, 0, 32, acc);
    int mt = threadIdx.x >> 5, nt = threadIdx.x & 31;
#pragma unroll
    for (int i = 0; i < 4; i++)
#pragma unroll
        for (int j = 0; j < 4; j++) {
            int n = n0 + nt + 32*j;
            C[(long long)(mt*4+i)*D + n] = acc[i][j] + bias[n];
        }
}

__global__ __launch_bounds__(256) void qkv3s(const float* __restrict__ ln,
    const float* __restrict__ hsrc, const float* __restrict__ Wq,
    const float* __restrict__ Wk, const float* __restrict__ Wv)
{
    __shared__ float As[32][33], Bs[32][129];
    int ks = blockIdx.y, z = blockIdx.z;
    const float* A = (z == 0) ? ln : hsrc;
    const float* W = (z == 0) ? Wq : ((z == 1) ? Wk : Wv);
    float* C = d_qkvpart + (long long)(ks*3 + z) * BD;
    int n0 = blockIdx.x * 128;
    float acc[4][4] = {};
    nt_body<1>(As, Bs, A, D, 0, W, D, n0, D, ks*256, 8, acc);
    int mt = threadIdx.x >> 5, nt = threadIdx.x & 31;
#pragma unroll
    for (int i = 0; i < 4; i++)
#pragma unroll
        for (int j = 0; j < 4; j++)
            C[(long long)(mt*4+i)*D + n0 + nt + 32*j] = acc[i][j];
}

__global__ __launch_bounds__(256) void qkv_red(const float* __restrict__ bq,
    const float* __restrict__ bk, const float* __restrict__ bv, int slotPrev, int writeKV)
{
    int i = blockIdx.x * 256 + threadIdx.x;
    int z = i >> 15, j = i & (BD-1);
    if (z && !writeKV) return;
    float v = 0.f;
#pragma unroll
    for (int s = 0; s < 4; s++) v += d_qkvpart[(long long)(s*3 + z)*BD + j];
    int col = j & 1023;
    if (z == 0)      d_q[j] = v + bq[col];
    else if (z == 1) d_Kc[(long long)slotPrev*BD + j] = v + bk[col];
    else             d_Vc[(long long)slotPrev*BD + j] = v + bv[col];
}

__global__ __launch_bounds__(256) void scores_ks()
{
    __shared__ float As[32][33], Bs[32][129];
    int ks = blockIdx.y, z = blockIdx.z;
    int n0 = blockIdx.x * 128;
    float acc[4][4] = {};
    nt_body<1>(As, Bs, d_q + z*DK, D, 0, d_Kc + z*DK, D, n0, MB, ks*256, 8, acc);
    float* C = d_scpart + (long long)(ks*HEADS + z) * (B*MB);
    int mt = threadIdx.x >> 5, nt = threadIdx.x & 31;
#pragma unroll
    for (int i = 0; i < 4; i++)
#pragma unroll
        for (int j = 0; j < 4; j++) {
            int n = n0 + nt + 32*j;
            if (n < MB) C[(long long)(mt*4+i)*MB + n] = acc[i][j];
        }
}

__global__ __launch_bounds__(256) void softmax2()
{
    __shared__ float sh[256];
    int row = blockIdx.x, tid = threadIdx.x;
    const float* p0 = d_scpart + (long)row * MB;
    const float* p1 = p0 + (long)HEADS*B*MB;
    float* po = d_probs + (long)row * MB;
    float v[5]; float mx = -1e30f;
#pragma unroll
    for (int i = 0; i < 5; i++) {
        int idx = tid + i*256; v[i] = -1e30f;
        if (idx < MB) { v[i] = (p0[idx] + p1[idx]) * ATT_SCALE; mx = fmaxf(mx, v[i]); }
    }
    sh[tid] = mx; __syncthreads();
    for (int st = 128; st > 0; st >>= 1) { if (tid < st) sh[tid] = fmaxf(sh[tid], sh[tid+st]); __syncthreads(); }
    float M = sh[0]; __syncthreads();
    float sum = 0.f;
#pragma unroll
    for (int i = 0; i < 5; i++) {
        int idx = tid + i*256;
        if (idx < MB) { v[i] = __expf(v[i] - M); sum += v[i]; }
    }
    sh[tid] = sum; __syncthreads();
    for (int st = 128; st > 0; st >>= 1) { if (tid < st) sh[tid] += sh[tid+st]; __syncthreads(); }
    float inv = 1.f / sh[0];
#pragma unroll
    for (int i = 0; i < 5; i++) {
        int idx = tid + i*256;
        if (idx < MB) po[idx] = v[i] * inv;
    }
}

__global__ __launch_bounds__(256) void attnVs()
{
    __shared__ float As[32][33], Bs[32][132];
    int ks = blockIdx.y, z = blockIdx.z;
    int n0 = blockIdx.x * 128;
    float acc[4][4] = {};
    nn_body(As, Bs, d_probs + (long long)z*B*MB, MB, d_Vc + z*DK, D, n0, ks*224, 7, acc);
    float* C = d_apart + (long long)ks*BD + z*DK;
    int mt = threadIdx.x >> 5, nt = threadIdx.x & 31;
#pragma unroll
    for (int i = 0; i < 4; i++)
#pragma unroll
        for (int j = 0; j < 4; j++)
            C[(long long)(mt*4+i)*D + n0 + nt + 32*j] = acc[i][j];
}

__global__ __launch_bounds__(256) void wo_gs(const float* __restrict__ Wo)
{
    __shared__ float As[32][33], Bs[32][129];
    int ks = blockIdx.y;
    int n0 = blockIdx.x * 128;
    float acc[4][4] = {};
    nt_body<5>(As, Bs, d_apart, D, BD, Wo, D, n0, D, ks*256, 8, acc);
    float* C = d_wopart + (long long)ks*BD;
    int mt = threadIdx.x >> 5, nt = threadIdx.x & 31;
#pragma unroll
    for (int i = 0; i < 4; i++)
#pragma unroll
        for (int j = 0; j < 4; j++)
            C[(long long)(mt*4+i)*D + n0 + nt + 32*j] = acc[i][j];
}

__global__ __launch_bounds__(256) void wo_red(const float* __restrict__ bo,
                                              const float* __restrict__ e)
{
    int i = blockIdx.x * 256 + threadIdx.x;
    float v = bo[i & 1023] + e[i];
#pragma unroll
    for (int s = 0; s < 4; s++) v += d_wopart[(long long)s*BD + i];
    d_hupd[i]      = v + d_hcur[i];
    d_hupd[BD + i] = v + d_hcur[BD + i];
}

__global__ __launch_bounds__(256) void lstm_g(const float* __restrict__ Aa,
    const float* __restrict__ Ab, const float* __restrict__ W1, const float* __restrict__ W2)
{
    __shared__ float As[32][33], Bs[32][129];
    int kb = blockIdx.y * 128;
    const float* A; const float* W; int kbeg;
    if (kb < 1024) { A = Aa; W = W1; kbeg = kb; } else { A = Ab; W = W2; kbeg = kb - 1024; }
    int n0 = blockIdx.x * 128;
    float acc[4][4] = {};
    nt_body<1>(As, Bs, A, D, 0, W, D, n0, 4096, kbeg, 4, acc);
    float* C = d_lstmpart + (long long)blockIdx.y * (B*4096);
    int mt = threadIdx.x >> 5, nt = threadIdx.x & 31;
#pragma unroll
    for (int i = 0; i < 4; i++)
#pragma unroll
        for (int j = 0; j < 4; j++)
            C[(long long)(mt*4+i)*4096 + n0 + nt + 32*j] = acc[i][j];
}

__global__ __launch_bounds__(256) void lstm_cell2(int l, int slot,
    const float* __restrict__ bi, const float* __restrict__ bh, int writeX, int t)
{
    int idx = blockIdx.x * 256 + threadIdx.x;
    int b = idx >> 10, d = idx & 1023;
    const float* p = d_lstmpart + (long long)b * 4096 + d;
    float gi = bi[d] + bh[d];
    float gf = bi[1024+d] + bh[1024+d];
    float gg = bi[2048+d] + bh[2048+d];
    float go = bi[3072+d] + bh[3072+d];
#pragma unroll
    for (int s = 0; s < 16; s++) {
        const float* q = p + (long long)s * (B*4096);
        gi += q[0]; gf += q[1024]; gg += q[2048]; go += q[3072];
    }
    float cp = d_ccur[l*BD + idx];
    float si = 1.f / (1.f + __expf(-gi));
    float sf = 1.f / (1.f + __expf(-gf));
    float so = 1.f / (1.f + __expf(-go));
    float cn = sf * cp + si * tanhf(gg);
    float hn = so * tanhf(cn);
    d_hcur[l*BD + idx] = hn;
    d_ccur[l*BD + idx] = cn;
    d_Hh[((long long)l*MEM + slot)*BD + idx] = hn;
    d_Ch[((long long)l*MEM + slot)*BD + idx] = cn;
    if (writeX) d_X[(long long)t*BD + idx] = hn;
}

/* ---------------- bf16 split conversion ---------------- */
__global__ __launch_bounds__(256) void convW(const float* __restrict__ W)
{
    long long i = (long long)blockIdx.x * 256 + threadIdx.x;
    long long n = i >> 10, k = i & 1023;
    float w = W[i];
    __nv_bfloat16 hi = __float2bfloat16(w);
    __nv_bfloat16 lo = __float2bfloat16(w - __bfloat162float(hi));
    __nv_bfloat16* row = d_Wcat + n * DKC;
    row[k] = hi; row[1024 + k] = lo; row[2048 + k] = hi;
}

__global__ __launch_bounds__(256) void convX()
{
    long long i = (long long)blockIdx.x * 256 + threadIdx.x;
    long long m = i >> 10, k = i & 1023;
    float x = d_X[i];
    __nv_bfloat16 hi = __float2bfloat16(x);
    __nv_bfloat16 lo = __float2bfloat16(x - __bfloat162float(hi));
    __nv_bfloat16* row = d_Xcat + m * DKC;
    row[k] = hi; row[1024 + k] = hi; row[2048 + k] = lo;
}

/* ---------------- decode: bf16 HMMA GEMM ---------------- */
__device__ __forceinline__ void ldsm4(uint32_t& r0, uint32_t& r1, uint32_t& r2, uint32_t& r3, uint32_t addr)
{
    asm volatile("ldmatrix.sync.aligned.m8n8.x4.shared.b16 {%0,%1,%2,%3}, [%4];" : "=r"(r0), "=r"(r1), "=r"(r2), "=r"(r3) : "r"(addr));
}

__device__ __forceinline__ void mma16816(float* d, const uint32_t* a, uint32_t b0, uint32_t b1)
{
    asm volatile("mma.sync.aligned.m16n8k16.row.col.f32.bf16.bf16.f32 {%0,%1,%2,%3}, {%4,%5,%6,%7}, {%8,%9}, {%0,%1,%2,%3};" : "+f"(d[0]), "+f"(d[1]), "+f"(d[2]), "+f"(d[3]) : "r"(a[0]), "r"(a[1]), "r"(a[2]), "r"(a[3]), "r"(b0), "r"(b1));
}

__global__ __launch_bounds__(256) void mma_decode(const float* __restrict__ bias,
                                                  float* __restrict__ C)
{
    __shared__ __align__(16) __nv_bfloat16 sA[2][128*32];
    __shared__ __align__(16) __nv_bfloat16 sB[2][128*32];
    int tid = threadIdx.x;
    int wid = tid >> 5, lane = tid & 31;
    int wm = wid >> 1, wn = wid & 1;
    long long m0 = blockIdx.y * 128, n0 = blockIdx.x * 128;

    int lrow0 = tid >> 2, gc = tid & 3;
    int lrow1 = lrow0 + 64;
    int sidx0 = lrow0*4 + (gc ^ ((lrow0 >> 1) & 3));
    int sidx1 = lrow1*4 + (gc ^ ((lrow1 >> 1) & 3));
    const uint4* gA0 = (const uint4*)(d_Xcat + (m0 + lrow0)*DKC) + gc;
    const uint4* gA1 = (const uint4*)(d_Xcat + (m0 + lrow1)*DKC) + gc;
    const uint4* gB0 = (const uint4*)(d_Wcat + (n0 + lrow0)*DKC) + gc;
    const uint4* gB1 = (const uint4*)(d_Wcat + (n0 + lrow1)*DKC) + gc;

    int lane7 = lane & 7;
    int mrow[2], msw[2];
#pragma unroll
    for (int mi = 0; mi < 2; mi++) {
        mrow[mi] = wm*32 + mi*16 + lane7 + ((lane >> 3) & 1)*8;
        msw[mi] = (mrow[mi] >> 1) & 3;
    }
    int kgA = lane >> 4;
    int nrow[4], nsw[4];
#pragma unroll
    for (int nb = 0; nb < 4; nb++) {
        nrow[nb] = wn*64 + nb*16 + lane7 + ((lane >> 4) & 1)*8;
        nsw[nb] = (nrow[nb] >> 1) & 3;
    }
    int kgB = (lane >> 3) & 1;

    uint32_t aBase = (uint32_t)__cvta_generic_to_shared(&sA[0][0]);
    uint32_t bBase = (uint32_t)__cvta_generic_to_shared(&sB[0][0]);

    float acc[2][8][4];
#pragma unroll
    for (int i = 0; i < 2; i++)
#pragma unroll
        for (int j = 0; j < 8; j++)
#pragma unroll
            for (int r = 0; r < 4; r++) acc[i][j][r] = 0.f;

    uint4 ra0 = gA0[0], ra1 = gA1[0], rb0 = gB0[0], rb1 = gB1[0];
    *((uint4*)sA[0] + sidx0) = ra0; *((uint4*)sA[0] + sidx1) = ra1;
    *((uint4*)sB[0] + sidx0) = rb0; *((uint4*)sB[0] + sidx1) = rb1;
    ra0 = gA0[4]; ra1 = gA1[4]; rb0 = gB0[4]; rb1 = gB1[4];
    __syncthreads();

    const int NCHUNK = DKC/32;
    for (int kc = 0; kc < NCHUNK; kc++) {
        int buf = kc & 1;
        uint32_t aB = aBase + buf*(128*32*2);
        uint32_t bB = bBase + buf*(128*32*2);
#pragma unroll
        for (int kk = 0; kk < 2; kk++) {
            uint32_t afr[2][4];
#pragma unroll
            for (int mi = 0; mi < 2; mi++) {
                int kg = kk*2 + kgA;
                ldsm4(afr[mi][0], afr[mi][1], afr[mi][2], afr[mi][3],
                      aB + (uint32_t)(mrow[mi]*64 + ((kg ^ msw[mi])*16)));
            }
#pragma unroll
            for (int nb = 0; nb < 4; nb++) {
                uint32_t bf0, bf1, bf2, bf3;
                int kg = kk*2 + kgB;
                ldsm4(bf0, bf1, bf2, bf3,
                      bB + (uint32_t)(nrow[nb]*64 + ((kg ^ nsw[nb])*16)));
#pragma unroll
                for (int mi = 0; mi < 2; mi++) {
                    mma16816(acc[mi][nb*2+0], afr[mi], bf0, bf1);
                    mma16816(acc[mi][nb*2+1], afr[mi], bf2, bf3);
                }
            }
        }
        if (kc + 1 < NCHUNK) {
            int nb2 = (kc + 1) & 1;
            *((uint4*)sA[nb2] + sidx0) = ra0; *((uint4*)sA[nb2] + sidx1) = ra1;
            *((uint4*)sB[nb2] + sidx0) = rb0; *((uint4*)sB[nb2] + sidx1) = rb1;
            if (kc + 2 < NCHUNK) {
                ra0 = gA0[(kc+2)*4]; ra1 = gA1[(kc+2)*4];
                rb0 = gB0[(kc+2)*4]; rb1 = gB1[(kc+2)*4];
            }
            __syncthreads();
        }
    }

#pragma unroll
    for (int mi = 0; mi < 2; mi++) {
#pragma unroll
        for (int nt = 0; nt < 8; nt++) {
            long long row = m0 + wm*32 + mi*16 + (lane >> 2);
            long long col = n0 + wn*64 + nt*8 + (lane & 3)*2;
            float c0 = bias[col], c1 = bias[col+1];
            *(float2*)(C + row*NTOK + col) =
                make_float2(acc[mi][nt][0] + c0, acc[mi][nt][1] + c1);
            *(float2*)(C + (row+8)*NTOK + col) =
                make_float2(acc[mi][nt][2] + c0, acc[mi][nt][3] + c1);
        }
    }
}

/* ---------------- host launch ---------------- */
extern "C" void kernel_launch(void* const* d_in, const int* in_sizes, int n_in,
                              void* d_out, int out_size)
{
    (void)in_sizes; (void)n_in; (void)out_size;
    const int*   tok  = (const int*)d_in[0];
    const float* emb  = (const float*)d_in[1];
    const float* ln_g = (const float*)d_in[2];
    const float* ln_b = (const float*)d_in[3];
    const float* Wq = (const float*)d_in[4];  const float* bq = (const float*)d_in[5];
    const float* Wk = (const float*)d_in[6];  const float* bk = (const float*)d_in[7];
    const float* Wv = (const float*)d_in[8];  const float* bv = (const float*)d_in[9];
    const float* Wo = (const float*)d_in[10]; const float* bo = (const float*)d_in[11];
    const float* Wih = (const float*)d_in[12]; const float* bih = (const float*)d_in[13];
    const float* Whh = (const float*)d_in[14]; const float* bhh = (const float*)d_in[15];
    const float* dW = (const float*)d_in[16]; const float* db = (const float*)d_in[17];
    const float* h0 = (const float*)d_in[18]; const float* c0 = (const float*)d_in[19];
    const float* H0 = (const float*)d_in[20]; const float* C0 = (const float*)d_in[21];
    float* out = (float*)d_out;

    float *p_eAll, *p_lnAll, *p_hcur, *p_hupd;
    cudaGetSymbolAddress((void**)&p_eAll,  d_eAll);
    cudaGetSymbolAddress((void**)&p_lnAll, d_lnAll);
    cudaGetSymbolAddress((void**)&p_hcur,  d_hcur);
    cudaGetSymbolAddress((void**)&p_hupd,  d_hupd);

    init_state<<<8960, 256>>>(h0, c0, H0, C0);
    embed_all<<<T_STEPS*B, 256>>>(tok, emb, ln_g, ln_b);
    kv_init<<<dim3(8, 35, 2), 256>>>(H0, Wk, Wv, bk, bv);
    convW<<<(NTOK*1024)/256, 256>>>(dW);

    for (int t = 0; t < T_STEPS; t++) {
        int slot = t % MEM;
        int slotPrev = (t + MEM - 1) % MEM;
        qkv3s<<<dim3(8, 4, t == 0 ? 1 : 3), 256>>>(p_lnAll + (long long)t*BD, p_hcur,
                                                   Wq, Wk, Wv);
        qkv_red<<<384, 256>>>(bq, bk, bv, slotPrev, t > 0);
        scores_ks<<<dim3(9, 2, HEADS), 256>>>();
        softmax2<<<HEADS*B, 256>>>();
        attnVs<<<dim3(4, 5, HEADS), 256>>>();
        wo_gs<<<dim3(8, 4), 256>>>(Wo);
        wo_red<<<128, 256>>>(bo, p_eAll + (long long)t*BD);
        lstm_g<<<dim3(32, 16), 256>>>(p_eAll + (long long)t*BD, p_hupd, Wih, Whh);
        lstm_cell2<<<128, 256>>>(0, slot, bih, bhh, 0, t);
        lstm_g<<<dim3(32, 16), 256>>>(p_hcur, p_hupd + BD, Wih + 4096*1024, Whh + 4096*1024);
        lstm_cell2<<<128, 256>>>(1, slot, bih + 4096, bhh + 4096, 1, t);
    }

    convX<<<(T_STEPS*B*1024)/256, 256>>>();
    mma_decode<<<dim3(NTOK/128, (T_STEPS*B)/128), 256>>>(db, out);
    write_tail<<<8960, 256>>>(out);
}

// round 11
// speedup vs baseline: 4.0024x; 1.0172x over previous
#include <cuda_runtime.h>
#include <cuda_bf16.h>
#include <stdint.h>
#include <math.h>

#define T_STEPS 64
#define B 32
#define D 1024
#define L 2
#define MEM 35
#define NTOK 32000
#define HEADS 2
#define DK 512
#define MB (MEM*B)
#define BD (B*D)
#define EPS 1e-6f
#define ATT_SCALE 0.04419417382415922f
#define DKC 3072

#define OFF_H   65536000L
#define OFF_C   65601536L
#define OFF_HM  65667072L
#define OFF_CM  67960832L

__device__ float d_eAll[T_STEPS*BD];
__device__ float d_lnAll[T_STEPS*BD];
__device__ float d_q[BD];
__device__ float d_qkvpart[12*BD];
__device__ float d_scpart[2*HEADS*B*MB];
__device__ float d_probs[HEADS*B*MB];
__device__ float d_apart[5*BD];
__device__ float d_wopart[4*BD];
__device__ float d_hupd[L*BD];
__device__ float d_lstmpart[16*B*4096];
__device__ float d_hcur[L*BD];
__device__ float d_ccur[L*BD];
__device__ float d_Kc[MB*D];
__device__ float d_Vc[MB*D];
__device__ float d_Hh[L*MEM*BD];
__device__ float d_Ch[L*MEM*BD];
__device__ float d_X[T_STEPS*BD];
__device__ __nv_bfloat16 d_Wcat[(long long)NTOK*DKC];
__device__ __nv_bfloat16 d_Xcat[(long long)T_STEPS*B*DKC];

/* ---------------- skinny-GEMM cores (M=32, BN=128) ---------------- */
template<int AP>
__device__ __forceinline__ void nt_body(float (*As)[33], float (*Bs)[129],
    const float* A, int lda, long long aStride, const float* W, int ldw,
    int n0, int Nrows, int kbeg, int ntiles, float acc[4][4])
{
    int tid = threadIdx.x;
    int lm = tid >> 3, lk4 = (tid & 7) * 4;
    int mt = tid >> 5, nt = tid & 31;
    const float* arow = A + (long long)lm*lda + kbeg + lk4;
    const float* wr0 = W + kbeg + lk4;
    long long woff[4]; bool wok[4];
#pragma unroll
    for (int c = 0; c < 4; c++) {
        int n = n0 + lm + 32*c;
        wok[c] = (n < Nrows);
        woff[c] = (long long)(wok[c] ? n : 0) * ldw;
    }
    float4 z4 = make_float4(0.f,0.f,0.f,0.f);
    float4 pa = *(const float4*)arow;
#pragma unroll
    for (int p = 1; p < AP; p++) {
        float4 u = *(const float4*)(arow + (long long)p*aStride);
        pa.x += u.x; pa.y += u.y; pa.z += u.z; pa.w += u.w;
    }
    float4 pb[4];
#pragma unroll
    for (int c = 0; c < 4; c++) pb[c] = wok[c] ? *(const float4*)(wr0 + woff[c]) : z4;
    for (int kt = 0; kt < ntiles; kt++) {
        __syncthreads();
        As[lk4+0][lm]=pa.x; As[lk4+1][lm]=pa.y; As[lk4+2][lm]=pa.z; As[lk4+3][lm]=pa.w;
#pragma unroll
        for (int c = 0; c < 4; c++) {
            int n = lm + 32*c;
            Bs[lk4+0][n]=pb[c].x; Bs[lk4+1][n]=pb[c].y; Bs[lk4+2][n]=pb[c].z; Bs[lk4+3][n]=pb[c].w;
        }
        __syncthreads();
        if (kt + 1 < ntiles) {
            int ko = (kt+1)*32;
            pa = *(const float4*)(arow + ko);
#pragma unroll
            for (int p = 1; p < AP; p++) {
                float4 u = *(const float4*)(arow + ko + (long long)p*aStride);
                pa.x += u.x; pa.y += u.y; pa.z += u.z; pa.w += u.w;
            }
#pragma unroll
            for (int c = 0; c < 4; c++) pb[c] = wok[c] ? *(const float4*)(wr0 + woff[c] + ko) : z4;
        }
#pragma unroll
        for (int kk = 0; kk < 32; kk++) {
            float a0=As[kk][mt*4+0], a1=As[kk][mt*4+1], a2=As[kk][mt*4+2], a3=As[kk][mt*4+3];
            float b0=Bs[kk][nt], b1=Bs[kk][nt+32], b2=Bs[kk][nt+64], b3=Bs[kk][nt+96];
            acc[0][0]+=a0*b0; acc[0][1]+=a0*b1; acc[0][2]+=a0*b2; acc[0][3]+=a0*b3;
            acc[1][0]+=a1*b0; acc[1][1]+=a1*b1; acc[1][2]+=a1*b2; acc[1][3]+=a1*b3;
            acc[2][0]+=a2*b0; acc[2][1]+=a2*b1; acc[2][2]+=a2*b2; acc[2][3]+=a2*b3;
            acc[3][0]+=a3*b0; acc[3][1]+=a3*b1; acc[3][2]+=a3*b2; acc[3][3]+=a3*b3;
        }
    }
}

__device__ __forceinline__ void nn_body(float (*As)[33], float (*Bs)[132],
    const float* A, int lda, const float* Bm, int ldb,
    int n0, int kbeg, int ntiles, float acc[4][4])
{
    int tid = threadIdx.x;
    int lm = tid >> 3, lk4 = (tid & 7) * 4;
    int mt = tid >> 5, nt = tid & 31;
    const float* arow = A + (long long)lm*lda + kbeg + lk4;
    int brow = tid >> 5, bcol = (tid & 31) * 4;
    const float* bbase = Bm + (long long)(kbeg + brow)*ldb + n0 + bcol;
    float4 pa = *(const float4*)arow;
    float4 pb[4];
#pragma unroll
    for (int c = 0; c < 4; c++) pb[c] = *(const float4*)(bbase + (long long)(8*c)*ldb);
    for (int kt = 0; kt < ntiles; kt++) {
        __syncthreads();
        As[lk4+0][lm]=pa.x; As[lk4+1][lm]=pa.y; As[lk4+2][lm]=pa.z; As[lk4+3][lm]=pa.w;
#pragma unroll
        for (int c = 0; c < 4; c++) *(float4*)&Bs[brow+8*c][bcol] = pb[c];
        __syncthreads();
        if (kt + 1 < ntiles) {
            int ko = (kt+1)*32;
            pa = *(const float4*)(arow + ko);
#pragma unroll
            for (int c = 0; c < 4; c++) pb[c] = *(const float4*)(bbase + (long long)(ko + 8*c)*ldb);
        }
#pragma unroll
        for (int kk = 0; kk < 32; kk++) {
            float a0=As[kk][mt*4+0], a1=As[kk][mt*4+1], a2=As[kk][mt*4+2], a3=As[kk][mt*4+3];
            float b0=Bs[kk][nt], b1=Bs[kk][nt+32], b2=Bs[kk][nt+64], b3=Bs[kk][nt+96];
            acc[0][0]+=a0*b0; acc[0][1]+=a0*b1; acc[0][2]+=a0*b2; acc[0][3]+=a0*b3;
            acc[1][0]+=a1*b0; acc[1][1]+=a1*b1; acc[1][2]+=a1*b2; acc[1][3]+=a1*b3;
            acc[2][0]+=a2*b0; acc[2][1]+=a2*b1; acc[2][2]+=a2*b2; acc[2][3]+=a2*b3;
            acc[3][0]+=a3*b0; acc[3][1]+=a3*b1; acc[3][2]+=a3*b2; acc[3][3]+=a3*b3;
        }
    }
}

/* ---------------- init / embed / tail ---------------- */
__global__ __launch_bounds__(256) void init_state(const float* __restrict__ h0,
    const float* __restrict__ c0, const float* __restrict__ H0, const float* __restrict__ C0)
{
    long i = (long)blockIdx.x * 256 + threadIdx.x;
    if (i < (long)L*BD) { d_hcur[i] = h0[i]; d_ccur[i] = c0[i]; }
    if (i < (long)L*MEM*BD) { d_Hh[i] = H0[i]; d_Ch[i] = C0[i]; }
}

__global__ __launch_bounds__(256) void write_tail(float* __restrict__ out)
{
    long i = (long)blockIdx.x * 256 + threadIdx.x;
    if (i >= (long)L*MEM*BD) return;
    if (i < (long)L*BD) { out[OFF_H + i] = d_hcur[i]; out[OFF_C + i] = d_ccur[i]; }
    long l = i / ((long)MEM*BD);
    long r = i % ((long)MEM*BD);
    long j = r / BD, q = r % BD;
    long phys = (T_STEPS + j) % MEM;
    out[OFF_HM + i] = d_Hh[(l*MEM + phys)*(long)BD + q];
    out[OFF_CM + i] = d_Ch[(l*MEM + phys)*(long)BD + q];
}

__global__ __launch_bounds__(256) void embed_all(const int* __restrict__ tok,
    const float* __restrict__ emb, const float* __restrict__ gg, const float* __restrict__ bb)
{
    __shared__ float sh[256];
    int r = blockIdx.x, tid = threadIdx.x;
    const float* row = emb + (long)tok[r] * D;
    float x[4]; float s = 0.f;
#pragma unroll
    for (int i = 0; i < 4; i++) { x[i] = row[tid + i*256]; s += x[i]; }
    sh[tid] = s; __syncthreads();
    for (int st = 128; st > 0; st >>= 1) { if (tid < st) sh[tid] += sh[tid+st]; __syncthreads(); }
    float mu = sh[0] * (1.f / D); __syncthreads();
    float ss = 0.f;
#pragma unroll
    for (int i = 0; i < 4; i++) { float dd = x[i] - mu; ss += dd*dd; }
    sh[tid] = ss; __syncthreads();
    for (int st = 128; st > 0; st >>= 1) { if (tid < st) sh[tid] += sh[tid+st]; __syncthreads(); }
    float inv = 1.f / (sqrtf(sh[0] / (float)(D - 1)) + EPS);
#pragma unroll
    for (int i = 0; i < 4; i++) {
        int idx = tid + i*256;
        d_eAll[(long)r*D + idx]  = x[i];
        d_lnAll[(long)r*D + idx] = gg[idx] * (x[i] - mu) * inv + bb[idx];
    }
}

/* ---------------- per-step GEMM kernels (split-K) ---------------- */
__global__ __launch_bounds__(256) void kv_init(const float* __restrict__ H0,
    const float* __restrict__ Wk, const float* __restrict__ Wv,
    const float* __restrict__ bk, const float* __restrict__ bv)
{
    __shared__ float As[32][33], Bs[32][129];
    int z = blockIdx.z;
    const float* W = z ? Wv : Wk;
    const float* bias = z ? bv : bk;
    float* C = (z ? d_Vc : d_Kc) + (long long)blockIdx.y * 32 * D;
    const float* A = H0 + (long long)blockIdx.y * 32 * D;
    int n0 = blockIdx.x * 128;
    float acc[4][4] = {};
    nt_body<1>(As, Bs, A, D, 0, W, D, n0, D, 0, 32, acc);
    int mt = threadIdx.x >> 5, nt = threadIdx.x & 31;
#pragma unroll
    for (int i = 0; i < 4; i++)
#pragma unroll
        for (int j = 0; j < 4; j++) {
            int n = n0 + nt + 32*j;
            C[(long long)(mt*4+i)*D + n] = acc[i][j] + bias[n];
        }
}

__global__ __launch_bounds__(256) void qkv3s(const float* __restrict__ ln,
    const float* __restrict__ hsrc, const float* __restrict__ Wq,
    const float* __restrict__ Wk, const float* __restrict__ Wv)
{
    __shared__ float As[32][33], Bs[32][129];
    int ks = blockIdx.y, z = blockIdx.z;
    const float* A = (z == 0) ? ln : hsrc;
    const float* W = (z == 0) ? Wq : ((z == 1) ? Wk : Wv);
    float* C = d_qkvpart + (long long)(ks*3 + z) * BD;
    int n0 = blockIdx.x * 128;
    float acc[4][4] = {};
    nt_body<1>(As, Bs, A, D, 0, W, D, n0, D, ks*256, 8, acc);
    int mt = threadIdx.x >> 5, nt = threadIdx.x & 31;
#pragma unroll
    for (int i = 0; i < 4; i++)
#pragma unroll
        for (int j = 0; j < 4; j++)
            C[(long long)(mt*4+i)*D + n0 + nt + 32*j] = acc[i][j];
}

__global__ __launch_bounds__(256) void qkv_red(const float* __restrict__ bq,
    const float* __restrict__ bk, const float* __restrict__ bv, int slotPrev, int writeKV)
{
    int i = blockIdx.x * 256 + threadIdx.x;
    int z = i >> 15, j = i & (BD-1);
    if (z && !writeKV) return;
    float v = 0.f;
#pragma unroll
    for (int s = 0; s < 4; s++) v += d_qkvpart[(long long)(s*3 + z)*BD + j];
    int col = j & 1023;
    if (z == 0)      d_q[j] = v + bq[col];
    else if (z == 1) d_Kc[(long long)slotPrev*BD + j] = v + bk[col];
    else             d_Vc[(long long)slotPrev*BD + j] = v + bv[col];
}

__global__ __launch_bounds__(256) void scores_ks()
{
    __shared__ float As[32][33], Bs[32][129];
    int ks = blockIdx.y, z = blockIdx.z;
    int n0 = blockIdx.x * 128;
    float acc[4][4] = {};
    nt_body<1>(As, Bs, d_q + z*DK, D, 0, d_Kc + z*DK, D, n0, MB, ks*256, 8, acc);
    float* C = d_scpart + (long long)(ks*HEADS + z) * (B*MB);
    int mt = threadIdx.x >> 5, nt = threadIdx.x & 31;
#pragma unroll
    for (int i = 0; i < 4; i++)
#pragma unroll
        for (int j = 0; j < 4; j++) {
            int n = n0 + nt + 32*j;
            if (n < MB) C[(long long)(mt*4+i)*MB + n] = acc[i][j];
        }
}

__global__ __launch_bounds__(256) void softmax2()
{
    __shared__ float sh[256];
    int row = blockIdx.x, tid = threadIdx.x;
    const float* p0 = d_scpart + (long)row * MB;
    const float* p1 = p0 + (long)HEADS*B*MB;
    float* po = d_probs + (long)row * MB;
    float v[5]; float mx = -1e30f;
#pragma unroll
    for (int i = 0; i < 5; i++) {
        int idx = tid + i*256; v[i] = -1e30f;
        if (idx < MB) { v[i] = (p0[idx] + p1[idx]) * ATT_SCALE; mx = fmaxf(mx, v[i]); }
    }
    sh[tid] = mx; __syncthreads();
    for (int st = 128; st > 0; st >>= 1) { if (tid < st) sh[tid] = fmaxf(sh[tid], sh[tid+st]); __syncthreads(); }
    float M = sh[0]; __syncthreads();
    float sum = 0.f;
#pragma unroll
    for (int i = 0; i < 5; i++) {
        int idx = tid + i*256;
        if (idx < MB) { v[i] = __expf(v[i] - M); sum += v[i]; }
    }
    sh[tid] = sum; __syncthreads();
    for (int st = 128; st > 0; st >>= 1) { if (tid < st) sh[tid] += sh[tid+st]; __syncthreads(); }
    float inv = 1.f / sh[0];
#pragma unroll
    for (int i = 0; i < 5; i++) {
        int idx = tid + i*256;
        if (idx < MB) po[idx] = v[i] * inv;
    }
}

__global__ __launch_bounds__(256) void attnVs()
{
    __shared__ float As[32][33], Bs[32][132];
    int ks = blockIdx.y, z = blockIdx.z;
    int n0 = blockIdx.x * 128;
    float acc[4][4] = {};
    nn_body(As, Bs, d_probs + (long long)z*B*MB, MB, d_Vc + z*DK, D, n0, ks*224, 7, acc);
    float* C = d_apart + (long long)ks*BD + z*DK;
    int mt = threadIdx.x >> 5, nt = threadIdx.x & 31;
#pragma unroll
    for (int i = 0; i < 4; i++)
#pragma unroll
        for (int j = 0; j < 4; j++)
            C[(long long)(mt*4+i)*D + n0 + nt + 32*j] = acc[i][j];
}

__global__ __launch_bounds__(256) void wo_gs(const float* __restrict__ Wo)
{
    __shared__ float As[32][33], Bs[32][129];
    int ks = blockIdx.y;
    int n0 = blockIdx.x * 128;
    float acc[4][4] = {};
    nt_body<5>(As, Bs, d_apart, D, BD, Wo, D, n0, D, ks*256, 8, acc);
    float* C = d_wopart + (long long)ks*BD;
    int mt = threadIdx.x >> 5, nt = threadIdx.x & 31;
#pragma unroll
    for (int i = 0; i < 4; i++)
#pragma unroll
        for (int j = 0; j < 4; j++)
            C[(long long)(mt*4+i)*D + n0 + nt + 32*j] = acc[i][j];
}

__global__ __launch_bounds__(256) void wo_red(const float* __restrict__ bo,
                                              const float* __restrict__ e)
{
    int i = blockIdx.x * 256 + threadIdx.x;
    float v = bo[i & 1023] + e[i];
#pragma unroll
    for (int s = 0; s < 4; s++) v += d_wopart[(long long)s*BD + i];
    d_hupd[i]      = v + d_hcur[i];
    d_hupd[BD + i] = v + d_hcur[BD + i];
}

__global__ __launch_bounds__(256) void lstm_g(const float* __restrict__ Aa,
    const float* __restrict__ Ab, const float* __restrict__ W1, const float* __restrict__ W2)
{
    __shared__ float As[32][33], Bs[32][129];
    int kb = blockIdx.y * 128;
    const float* A; const float* W; int kbeg;
    if (kb < 1024) { A = Aa; W = W1; kbeg = kb; } else { A = Ab; W = W2; kbeg = kb - 1024; }
    int n0 = blockIdx.x * 128;
    float acc[4][4] = {};
    nt_body<1>(As, Bs, A, D, 0, W, D, n0, 4096, kbeg, 4, acc);
    float* C = d_lstmpart + (long long)blockIdx.y * (B*4096);
    int mt = threadIdx.x >> 5, nt = threadIdx.x & 31;
#pragma unroll
    for (int i = 0; i < 4; i++)
#pragma unroll
        for (int j = 0; j < 4; j++)
            C[(long long)(mt*4+i)*4096 + n0 + nt + 32*j] = acc[i][j];
}

__global__ __launch_bounds__(256) void lstm_cell2(int l, int slot,
    const float* __restrict__ bi, const float* __restrict__ bh, int writeX, int t)
{
    int idx = blockIdx.x * 256 + threadIdx.x;
    int b = idx >> 10, d = idx & 1023;
    const float* p = d_lstmpart + (long long)b * 4096 + d;
    float gi = bi[d] + bh[d];
    float gf = bi[1024+d] + bh[1024+d];
    float gg = bi[2048+d] + bh[2048+d];
    float go = bi[3072+d] + bh[3072+d];
#pragma unroll
    for (int s = 0; s < 16; s++) {
        const float* q = p + (long long)s * (B*4096);
        gi += q[0]; gf += q[1024]; gg += q[2048]; go += q[3072];
    }
    float cp = d_ccur[l*BD + idx];
    float si = 1.f / (1.f + __expf(-gi));
    float sf = 1.f / (1.f + __expf(-gf));
    float so = 1.f / (1.f + __expf(-go));
    float cn = sf * cp + si * tanhf(gg);
    float hn = so * tanhf(cn);
    d_hcur[l*BD + idx] = hn;
    d_ccur[l*BD + idx] = cn;
    d_Hh[((long long)l*MEM + slot)*BD + idx] = hn;
    d_Ch[((long long)l*MEM + slot)*BD + idx] = cn;
    if (writeX) d_X[(long long)t*BD + idx] = hn;
}

/* ---------------- bf16 split conversion ---------------- */
__global__ __launch_bounds__(256) void convW(const float* __restrict__ W)
{
    long long i = (long long)blockIdx.x * 256 + threadIdx.x;
    long long n = i >> 10, k = i & 1023;
    float w = W[i];
    __nv_bfloat16 hi = __float2bfloat16(w);
    __nv_bfloat16 lo = __float2bfloat16(w - __bfloat162float(hi));
    __nv_bfloat16* row = d_Wcat + n * DKC;
    row[k] = hi; row[1024 + k] = lo; row[2048 + k] = hi;
}

__global__ __launch_bounds__(256) void convX()
{
    long long i = (long long)blockIdx.x * 256 + threadIdx.x;
    long long m = i >> 10, k = i & 1023;
    float x = d_X[i];
    __nv_bfloat16 hi = __float2bfloat16(x);
    __nv_bfloat16 lo = __float2bfloat16(x - __bfloat162float(hi));
    __nv_bfloat16* row = d_Xcat + m * DKC;
    row[k] = hi; row[1024 + k] = hi; row[2048 + k] = lo;
}

/* ---------------- decode: bf16 HMMA GEMM, 4-stage cp.async pipeline ----------------
   BM=128, BN=128, BK=32, 8 warps (4m x 2n), mma.m16n8k16, grid (16 m, 250 n) m-fastest. */
#define DSTAGES 4
#define DTILE_B 8192
#define DEC_SMEM (DSTAGES*2*DTILE_B)   /* 64 KB */

__device__ __forceinline__ void ldsm4(uint32_t& r0, uint32_t& r1, uint32_t& r2, uint32_t& r3, uint32_t addr)
{
    asm volatile("ldmatrix.sync.aligned.m8n8.x4.shared.b16 {%0,%1,%2,%3}, [%4];" : "=r"(r0), "=r"(r1), "=r"(r2), "=r"(r3) : "r"(addr));
}
__device__ __forceinline__ void mma16816(float* d, const uint32_t* a, uint32_t b0, uint32_t b1)
{
    asm volatile("mma.sync.aligned.m16n8k16.row.col.f32.bf16.bf16.f32 {%0,%1,%2,%3}, {%4,%5,%6,%7}, {%8,%9}, {%0,%1,%2,%3};" : "+f"(d[0]), "+f"(d[1]), "+f"(d[2]), "+f"(d[3]) : "r"(a[0]), "r"(a[1]), "r"(a[2]), "r"(a[3]), "r"(b0), "r"(b1));
}
__device__ __forceinline__ void cpasync16(uint32_t saddr, const void* g)
{
    asm volatile("cp.async.cg.shared.global [%0], [%1], 16;" :: "r"(saddr), "l"(g));
}
__device__ __forceinline__ uint32_t smem_u32d(const void* p)
{
    uint32_t a;
    asm("{ .reg .u64 t; cvta.to.shared.u64 t, %1; cvt.u32.u64 %0, t; }" : "=r"(a) : "l"(p));
    return a;
}

__global__ __launch_bounds__(256) void mma_decode(const float* __restrict__ bias,
                                                  float* __restrict__ C)
{
    extern __shared__ __align__(16) char dsm[];
    uint32_t aBase = smem_u32d(dsm);
    uint32_t bBase = aBase + DSTAGES*DTILE_B;
    int tid = threadIdx.x;
    int wid = tid >> 5, lane = tid & 31;
    int wm = wid >> 1, wn = wid & 1;
    long long m0 = (long long)blockIdx.x * 128;   /* m fastest: 16 m-blocks share W tile */
    long long n0 = (long long)blockIdx.y * 128;

    /* loader: 2 granules (16B) per thread per tile, XOR swizzle */
    int lrow0 = tid >> 2, gc = tid & 3;
    int lrow1 = lrow0 + 64;
    uint32_t soff0 = (uint32_t)(lrow0*4 + (gc ^ ((lrow0 >> 1) & 3))) * 16;
    uint32_t soff1 = (uint32_t)(lrow1*4 + (gc ^ ((lrow1 >> 1) & 3))) * 16;
    const char* gA0 = (const char*)(d_Xcat + (m0 + lrow0)*DKC) + gc*16;
    const char* gA1 = (const char*)(d_Xcat + (m0 + lrow1)*DKC) + gc*16;
    const char* gB0 = (const char*)(d_Wcat + (n0 + lrow0)*DKC) + gc*16;
    const char* gB1 = (const char*)(d_Wcat + (n0 + lrow1)*DKC) + gc*16;

    /* ldmatrix lane address components */
    int lane7 = lane & 7;
    int mrow[2], msw[2];
#pragma unroll
    for (int mi = 0; mi < 2; mi++) {
        mrow[mi] = wm*32 + mi*16 + lane7 + ((lane >> 3) & 1)*8;
        msw[mi] = (mrow[mi] >> 1) & 3;
    }
    int kgA = lane >> 4;
    int nrow[4], nsw[4];
#pragma unroll
    for (int nb = 0; nb < 4; nb++) {
        nrow[nb] = wn*64 + nb*16 + lane7 + ((lane >> 4) & 1)*8;
        nsw[nb] = (nrow[nb] >> 1) & 3;
    }
    int kgB = (lane >> 3) & 1;

    float acc[2][8][4];
#pragma unroll
    for (int i = 0; i < 2; i++)
#pragma unroll
        for (int j = 0; j < 8; j++)
#pragma unroll
            for (int r = 0; r < 4; r++) acc[i][j][r] = 0.f;

    const int NCHUNK = DKC/32;     /* 96; chunk stride in gmem = 64 bytes */

    /* prologue: stages 0..2 */
#pragma unroll
    for (int s = 0; s < DSTAGES-1; s++) {
        uint32_t sa = aBase + (uint32_t)(s & (DSTAGES-1))*DTILE_B;
        uint32_t sb = bBase + (uint32_t)(s & (DSTAGES-1))*DTILE_B;
        cpasync16(sa + soff0, gA0 + s*64);
        cpasync16(sa + soff1, gA1 + s*64);
        cpasync16(sb + soff0, gB0 + s*64);
        cpasync16(sb + soff1, gB1 + s*64);
        asm volatile("cp.async.commit_group;" ::: "memory");
    }

    for (int kc = 0; kc < NCHUNK; kc++) {
        int buf = kc & (DSTAGES-1);
        asm volatile("cp.async.wait_group %0;" :: "n"(DSTAGES-2) : "memory");
        __syncthreads();
        /* prefetch stage kc+3 (overwrites buffer of chunk kc-1, done by all after sync) */
        {
            int s = kc + DSTAGES - 1;
            if (s < NCHUNK) {
                uint32_t sa = aBase + (uint32_t)(s & (DSTAGES-1))*DTILE_B;
                uint32_t sb = bBase + (uint32_t)(s & (DSTAGES-1))*DTILE_B;
                cpasync16(sa + soff0, gA0 + s*64);
                cpasync16(sa + soff1, gA1 + s*64);
                cpasync16(sb + soff0, gB0 + s*64);
                cpasync16(sb + soff1, gB1 + s*64);
            }
            asm volatile("cp.async.commit_group;" ::: "memory");
        }
        uint32_t aB = aBase + (uint32_t)buf*DTILE_B;
        uint32_t bB = bBase + (uint32_t)buf*DTILE_B;
#pragma unroll
        for (int kk = 0; kk < 2; kk++) {
            uint32_t afr[2][4];
#pragma unroll
            for (int mi = 0; mi < 2; mi++) {
                int kg = kk*2 + kgA;
                ldsm4(afr[mi][0], afr[mi][1], afr[mi][2], afr[mi][3],
                      aB + (uint32_t)(mrow[mi]*64 + ((kg ^ msw[mi])*16)));
            }
#pragma unroll
            for (int nb = 0; nb < 4; nb++) {
                uint32_t bf0, bf1, bf2, bf3;
                int kg = kk*2 + kgB;
                ldsm4(bf0, bf1, bf2, bf3,
                      bB + (uint32_t)(nrow[nb]*64 + ((kg ^ nsw[nb])*16)));
#pragma unroll
                for (int mi = 0; mi < 2; mi++) {
                    mma16816(acc[mi][nb*2+0], afr[mi], bf0, bf1);
                    mma16816(acc[mi][nb*2+1], afr[mi], bf2, bf3);
                }
            }
        }
    }

#pragma unroll
    for (int mi = 0; mi < 2; mi++) {
#pragma unroll
        for (int nt = 0; nt < 8; nt++) {
            long long row = m0 + wm*32 + mi*16 + (lane >> 2);
            long long col = n0 + wn*64 + nt*8 + (lane & 3)*2;
            float c0 = bias[col], c1 = bias[col+1];
            *(float2*)(C + row*NTOK + col) =
                make_float2(acc[mi][nt][0] + c0, acc[mi][nt][1] + c1);
            *(float2*)(C + (row+8)*NTOK + col) =
                make_float2(acc[mi][nt][2] + c0, acc[mi][nt][3] + c1);
        }
    }
}

/* ---------------- host launch ---------------- */
extern "C" void kernel_launch(void* const* d_in, const int* in_sizes, int n_in,
                              void* d_out, int out_size)
{
    (void)in_sizes; (void)n_in; (void)out_size;
    const int*   tok  = (const int*)d_in[0];
    const float* emb  = (const float*)d_in[1];
    const float* ln_g = (const float*)d_in[2];
    const float* ln_b = (const float*)d_in[3];
    const float* Wq = (const float*)d_in[4];  const float* bq = (const float*)d_in[5];
    const float* Wk = (const float*)d_in[6];  const float* bk = (const float*)d_in[7];
    const float* Wv = (const float*)d_in[8];  const float* bv = (const float*)d_in[9];
    const float* Wo = (const float*)d_in[10]; const float* bo = (const float*)d_in[11];
    const float* Wih = (const float*)d_in[12]; const float* bih = (const float*)d_in[13];
    const float* Whh = (const float*)d_in[14]; const float* bhh = (const float*)d_in[15];
    const float* dW = (const float*)d_in[16]; const float* db = (const float*)d_in[17];
    const float* h0 = (const float*)d_in[18]; const float* c0 = (const float*)d_in[19];
    const float* H0 = (const float*)d_in[20]; const float* C0 = (const float*)d_in[21];
    float* out = (float*)d_out;

    float *p_eAll, *p_lnAll, *p_hcur, *p_hupd;
    cudaGetSymbolAddress((void**)&p_eAll,  d_eAll);
    cudaGetSymbolAddress((void**)&p_lnAll, d_lnAll);
    cudaGetSymbolAddress((void**)&p_hcur,  d_hcur);
    cudaGetSymbolAddress((void**)&p_hupd,  d_hupd);

    cudaFuncSetAttribute(mma_decode, cudaFuncAttributeMaxDynamicSharedMemorySize, DEC_SMEM);

    init_state<<<8960, 256>>>(h0, c0, H0, C0);
    embed_all<<<T_STEPS*B, 256>>>(tok, emb, ln_g, ln_b);
    kv_init<<<dim3(8, 35, 2), 256>>>(H0, Wk, Wv, bk, bv);
    convW<<<(NTOK*1024)/256, 256>>>(dW);

    for (int t = 0; t < T_STEPS; t++) {
        int slot = t % MEM;
        int slotPrev = (t + MEM - 1) % MEM;
        qkv3s<<<dim3(8, 4, t == 0 ? 1 : 3), 256>>>(p_lnAll + (long long)t*BD, p_hcur,
                                                   Wq, Wk, Wv);
        qkv_red<<<384, 256>>>(bq, bk, bv, slotPrev, t > 0);
        scores_ks<<<dim3(9, 2, HEADS), 256>>>();
        softmax2<<<HEADS*B, 256>>>();
        attnVs<<<dim3(4, 5, HEADS), 256>>>();
        wo_gs<<<dim3(8, 4), 256>>>(Wo);
        wo_red<<<128, 256>>>(bo, p_eAll + (long long)t*BD);
        lstm_g<<<dim3(32, 16), 256>>>(p_eAll + (long long)t*BD, p_hupd, Wih, Whh);
        lstm_cell2<<<128, 256>>>(0, slot, bih, bhh, 0, t);
        lstm_g<<<dim3(32, 16), 256>>>(p_hcur, p_hupd + BD, Wih + 4096*1024, Whh + 4096*1024);
        lstm_cell2<<<128, 256>>>(1, slot, bih + 4096, bhh + 4096, 1, t);
    }

    convX<<<(T_STEPS*B*1024)/256, 256>>>();
    mma_decode<<<dim3((T_STEPS*B)/128, NTOK/128), 256, DEC_SMEM>>>(db, out);
    write_tail<<<8960, 256>>>(out);
}

// round 13
// speedup vs baseline: 4.3747x; 1.0930x over previous
#include <cuda_runtime.h>
#include <cuda_bf16.h>
#include <stdint.h>
#include <math.h>

#define T_STEPS 64
#define B 32
#define D 1024
#define L 2
#define MEM 35
#define NTOK 32000
#define HEADS 2
#define DK 512
#define MB (MEM*B)
#define BD (B*D)
#define EPS 1e-6f
#define ATT_SCALE 0.04419417382415922f
#define DKC 3072

#define OFF_H   65536000L
#define OFF_C   65601536L
#define OFF_HM  65667072L
#define OFF_CM  67960832L

__device__ float d_eAll[T_STEPS*BD];
__device__ float d_lnAll[T_STEPS*BD];
__device__ float d_q[BD];
__device__ float d_qkvpart[24*BD];
__device__ float d_scpart[4*HEADS*B*MB];
__device__ float d_probs[HEADS*B*MB];
__device__ float d_apart[7*BD];
__device__ float d_wopart[8*BD];
__device__ float d_lstmpart[16*B*4096];
__device__ float d_hcur[L*BD];
__device__ float d_ccur[L*BD];
__device__ float d_Kc[MB*D];
__device__ float d_Vc[MB*D];
__device__ float d_Hh[L*MEM*BD];
__device__ float d_Ch[L*MEM*BD];
__device__ float d_X[T_STEPS*BD];
__device__ __nv_bfloat16 d_Wcat[(long long)NTOK*DKC];
__device__ __nv_bfloat16 d_Xcat[(long long)T_STEPS*B*DKC];

/* ---------------- skinny-GEMM cores (M=32, BN=128) ----------------
   AP: number of strided A partials summed in loader.
   FUSED: additionally add e + h + bo[col] to A (LSTM hupd fusion). */
template<int AP, int FUSED>
__device__ __forceinline__ void nt_body(float (*As)[33], float (*Bs)[129],
    const float* A, int lda, long long aStride, const float* W, int ldw,
    int n0, int Nrows, int kbeg, int ntiles, float acc[4][4],
    const float* eP, const float* hP, const float* boP)
{
    int tid = threadIdx.x;
    int lm = tid >> 3, lk4 = (tid & 7) * 4;
    int mt = tid >> 5, nt = tid & 31;
    const float* arow = A + (long long)lm*lda + kbeg + lk4;
    const float* wr0 = W + kbeg + lk4;
    long long woff[4]; bool wok[4];
#pragma unroll
    for (int c = 0; c < 4; c++) {
        int n = n0 + lm + 32*c;
        wok[c] = (n < Nrows);
        woff[c] = (long long)(wok[c] ? n : 0) * ldw;
    }
    float4 z4 = make_float4(0.f,0.f,0.f,0.f);
    float4 pa = *(const float4*)arow;
#pragma unroll
    for (int p = 1; p < AP; p++) {
        float4 u = *(const float4*)(arow + (long long)p*aStride);
        pa.x += u.x; pa.y += u.y; pa.z += u.z; pa.w += u.w;
    }
    if (FUSED) {
        float4 ev = *(const float4*)(eP + (long long)lm*lda + kbeg + lk4);
        float4 hv = *(const float4*)(hP + (long long)lm*lda + kbeg + lk4);
        float4 bv = *(const float4*)(boP + kbeg + lk4);
        pa.x += ev.x + hv.x + bv.x; pa.y += ev.y + hv.y + bv.y;
        pa.z += ev.z + hv.z + bv.z; pa.w += ev.w + hv.w + bv.w;
    }
    float4 pb[4];
#pragma unroll
    for (int c = 0; c < 4; c++) pb[c] = wok[c] ? *(const float4*)(wr0 + woff[c]) : z4;
    for (int kt = 0; kt < ntiles; kt++) {
        __syncthreads();
        As[lk4+0][lm]=pa.x; As[lk4+1][lm]=pa.y; As[lk4+2][lm]=pa.z; As[lk4+3][lm]=pa.w;
#pragma unroll
        for (int c = 0; c < 4; c++) {
            int n = lm + 32*c;
            Bs[lk4+0][n]=pb[c].x; Bs[lk4+1][n]=pb[c].y; Bs[lk4+2][n]=pb[c].z; Bs[lk4+3][n]=pb[c].w;
        }
        __syncthreads();
        if (kt + 1 < ntiles) {
            int ko = (kt+1)*32;
            pa = *(const float4*)(arow + ko);
#pragma unroll
            for (int p = 1; p < AP; p++) {
                float4 u = *(const float4*)(arow + ko + (long long)p*aStride);
                pa.x += u.x; pa.y += u.y; pa.z += u.z; pa.w += u.w;
            }
            if (FUSED) {
                float4 ev = *(const float4*)(eP + (long long)lm*lda + kbeg + ko + lk4);
                float4 hv = *(const float4*)(hP + (long long)lm*lda + kbeg + ko + lk4);
                float4 bv = *(const float4*)(boP + kbeg + ko + lk4);
                pa.x += ev.x + hv.x + bv.x; pa.y += ev.y + hv.y + bv.y;
                pa.z += ev.z + hv.z + bv.z; pa.w += ev.w + hv.w + bv.w;
            }
#pragma unroll
            for (int c = 0; c < 4; c++) pb[c] = wok[c] ? *(const float4*)(wr0 + woff[c] + ko) : z4;
        }
#pragma unroll
        for (int kk = 0; kk < 32; kk++) {
            float a0=As[kk][mt*4+0], a1=As[kk][mt*4+1], a2=As[kk][mt*4+2], a3=As[kk][mt*4+3];
            float b0=Bs[kk][nt], b1=Bs[kk][nt+32], b2=Bs[kk][nt+64], b3=Bs[kk][nt+96];
            acc[0][0]+=a0*b0; acc[0][1]+=a0*b1; acc[0][2]+=a0*b2; acc[0][3]+=a0*b3;
            acc[1][0]+=a1*b0; acc[1][1]+=a1*b1; acc[1][2]+=a1*b2; acc[1][3]+=a1*b3;
            acc[2][0]+=a2*b0; acc[2][1]+=a2*b1; acc[2][2]+=a2*b2; acc[2][3]+=a2*b3;
            acc[3][0]+=a3*b0; acc[3][1]+=a3*b1; acc[3][2]+=a3*b2; acc[3][3]+=a3*b3;
        }
    }
}

__device__ __forceinline__ void nn_body(float (*As)[33], float (*Bs)[132],
    const float* A, int lda, const float* Bm, int ldb,
    int n0, int kbeg, int ntiles, float acc[4][4])
{
    int tid = threadIdx.x;
    int lm = tid >> 3, lk4 = (tid & 7) * 4;
    int mt = tid >> 5, nt = tid & 31;
    const float* arow = A + (long long)lm*lda + kbeg + lk4;
    int brow = tid >> 5, bcol = (tid & 31) * 4;
    const float* bbase = Bm + (long long)(kbeg + brow)*ldb + n0 + bcol;
    float4 pa = *(const float4*)arow;
    float4 pb[4];
#pragma unroll
    for (int c = 0; c < 4; c++) pb[c] = *(const float4*)(bbase + (long long)(8*c)*ldb);
    for (int kt = 0; kt < ntiles; kt++) {
        __syncthreads();
        As[lk4+0][lm]=pa.x; As[lk4+1][lm]=pa.y; As[lk4+2][lm]=pa.z; As[lk4+3][lm]=pa.w;
#pragma unroll
        for (int c = 0; c < 4; c++) *(float4*)&Bs[brow+8*c][bcol] = pb[c];
        __syncthreads();
        if (kt + 1 < ntiles) {
            int ko = (kt+1)*32;
            pa = *(const float4*)(arow + ko);
#pragma unroll
            for (int c = 0; c < 4; c++) pb[c] = *(const float4*)(bbase + (long long)(ko + 8*c)*ldb);
        }
#pragma unroll
        for (int kk = 0; kk < 32; kk++) {
            float a0=As[kk][mt*4+0], a1=As[kk][mt*4+1], a2=As[kk][mt*4+2], a3=As[kk][mt*4+3];
            float b0=Bs[kk][nt], b1=Bs[kk][nt+32], b2=Bs[kk][nt+64], b3=Bs[kk][nt+96];
            acc[0][0]+=a0*b0; acc[0][1]+=a0*b1; acc[0][2]+=a0*b2; acc[0][3]+=a0*b3;
            acc[1][0]+=a1*b0; acc[1][1]+=a1*b1; acc[1][2]+=a1*b2; acc[1][3]+=a1*b3;
            acc[2][0]+=a2*b0; acc[2][1]+=a2*b1; acc[2][2]+=a2*b2; acc[2][3]+=a2*b3;
            acc[3][0]+=a3*b0; acc[3][1]+=a3*b1; acc[3][2]+=a3*b2; acc[3][3]+=a3*b3;
        }
    }
}

/* ---------------- init / embed / tail ---------------- */
__global__ __launch_bounds__(256) void init_state(const float* __restrict__ h0,
    const float* __restrict__ c0, const float* __restrict__ H0, const float* __restrict__ C0)
{
    long i = (long)blockIdx.x * 256 + threadIdx.x;
    if (i < (long)L*BD) { d_hcur[i] = h0[i]; d_ccur[i] = c0[i]; }
    if (i < (long)L*MEM*BD) { d_Hh[i] = H0[i]; d_Ch[i] = C0[i]; }
}

__global__ __launch_bounds__(256) void write_tail(float* __restrict__ out)
{
    long i = (long)blockIdx.x * 256 + threadIdx.x;
    if (i >= (long)L*MEM*BD) return;
    if (i < (long)L*BD) { out[OFF_H + i] = d_hcur[i]; out[OFF_C + i] = d_ccur[i]; }
    long l = i / ((long)MEM*BD);
    long r = i % ((long)MEM*BD);
    long j = r / BD, q = r % BD;
    long phys = (T_STEPS + j) % MEM;
    out[OFF_HM + i] = d_Hh[(l*MEM + phys)*(long)BD + q];
    out[OFF_CM + i] = d_Ch[(l*MEM + phys)*(long)BD + q];
}

__global__ __launch_bounds__(256) void embed_all(const int* __restrict__ tok,
    const float* __restrict__ emb, const float* __restrict__ gg, const float* __restrict__ bb)
{
    __shared__ float sh[256];
    int r = blockIdx.x, tid = threadIdx.x;
    const float* row = emb + (long)tok[r] * D;
    float x[4]; float s = 0.f;
#pragma unroll
    for (int i = 0; i < 4; i++) { x[i] = row[tid + i*256]; s += x[i]; }
    sh[tid] = s; __syncthreads();
    for (int st = 128; st > 0; st >>= 1) { if (tid < st) sh[tid] += sh[tid+st]; __syncthreads(); }
    float mu = sh[0] * (1.f / D); __syncthreads();
    float ss = 0.f;
#pragma unroll
    for (int i = 0; i < 4; i++) { float dd = x[i] - mu; ss += dd*dd; }
    sh[tid] = ss; __syncthreads();
    for (int st = 128; st > 0; st >>= 1) { if (tid < st) sh[tid] += sh[tid+st]; __syncthreads(); }
    float inv = 1.f / (sqrtf(sh[0] / (float)(D - 1)) + EPS);
#pragma unroll
    for (int i = 0; i < 4; i++) {
        int idx = tid + i*256;
        d_eAll[(long)r*D + idx]  = x[i];
        d_lnAll[(long)r*D + idx] = gg[idx] * (x[i] - mu) * inv + bb[idx];
    }
}

/* ---------------- per-step GEMM kernels (deep split-K) ---------------- */
__global__ __launch_bounds__(256) void kv_init(const float* __restrict__ H0,
    const float* __restrict__ Wk, const float* __restrict__ Wv,
    const float* __restrict__ bk, const float* __restrict__ bv)
{
    __shared__ float As[32][33], Bs[32][129];
    int z = blockIdx.z;
    const float* W = z ? Wv : Wk;
    const float* bias = z ? bv : bk;
    float* C = (z ? d_Vc : d_Kc) + (long long)blockIdx.y * 32 * D;
    const float* A = H0 + (long long)blockIdx.y * 32 * D;
    int n0 = blockIdx.x * 128;
    float acc[4][4] = {};
    nt_body<1,0>(As, Bs, A, D, 0, W, D, n0, D, 0, 32, acc, nullptr, nullptr, nullptr);
    int mt = threadIdx.x >> 5, nt = threadIdx.x & 31;
#pragma unroll
    for (int i = 0; i < 4; i++)
#pragma unroll
        for (int j = 0; j < 4; j++) {
            int n = n0 + nt + 32*j;
            C[(long long)(mt*4+i)*D + n] = acc[i][j] + bias[n];
        }
}

/* qkv: grid (8, 8, z) -> partials [ks][z][BD], chunk 128 */
__global__ __launch_bounds__(256) void qkv3s(const float* __restrict__ ln,
    const float* __restrict__ hsrc, const float* __restrict__ Wq,
    const float* __restrict__ Wk, const float* __restrict__ Wv)
{
    __shared__ float As[32][33], Bs[32][129];
    int ks = blockIdx.y, z = blockIdx.z;
    const float* A = (z == 0) ? ln : hsrc;
    const float* W = (z == 0) ? Wq : ((z == 1) ? Wk : Wv);
    float* C = d_qkvpart + (long long)(ks*3 + z) * BD;
    int n0 = blockIdx.x * 128;
    float acc[4][4] = {};
    nt_body<1,0>(As, Bs, A, D, 0, W, D, n0, D, ks*128, 4, acc, nullptr, nullptr, nullptr);
    int mt = threadIdx.x >> 5, nt = threadIdx.x & 31;
#pragma unroll
    for (int i = 0; i < 4; i++)
#pragma unroll
        for (int j = 0; j < 4; j++)
            C[(long long)(mt*4+i)*D + n0 + nt + 32*j] = acc[i][j];
}

__global__ __launch_bounds__(256) void qkv_red(const float* __restrict__ bq,
    const float* __restrict__ bk, const float* __restrict__ bv, int slotPrev, int writeKV)
{
    int i = blockIdx.x * 256 + threadIdx.x;
    int z = i >> 15, j = i & (BD-1);
    if (z && !writeKV) return;
    float v = 0.f;
#pragma unroll
    for (int s = 0; s < 8; s++) v += d_qkvpart[(long long)(s*3 + z)*BD + j];
    int col = j & 1023;
    if (z == 0)      d_q[j] = v + bq[col];
    else if (z == 1) d_Kc[(long long)slotPrev*BD + j] = v + bk[col];
    else             d_Vc[(long long)slotPrev*BD + j] = v + bv[col];
}

/* scores: grid (9, 4, 2) -> partials [ks][z][B][MB], chunk 128 */
__global__ __launch_bounds__(256) void scores_ks()
{
    __shared__ float As[32][33], Bs[32][129];
    int ks = blockIdx.y, z = blockIdx.z;
    int n0 = blockIdx.x * 128;
    float acc[4][4] = {};
    nt_body<1,0>(As, Bs, d_q + z*DK, D, 0, d_Kc + z*DK, D, n0, MB, ks*128, 4, acc,
                 nullptr, nullptr, nullptr);
    float* C = d_scpart + (long long)(ks*HEADS + z) * (B*MB);
    int mt = threadIdx.x >> 5, nt = threadIdx.x & 31;
#pragma unroll
    for (int i = 0; i < 4; i++)
#pragma unroll
        for (int j = 0; j < 4; j++) {
            int n = n0 + nt + 32*j;
            if (n < MB) C[(long long)(mt*4+i)*MB + n] = acc[i][j];
        }
}

__global__ __launch_bounds__(256) void softmax2()
{
    __shared__ float sh[256];
    int row = blockIdx.x, tid = threadIdx.x;
    const float* p0 = d_scpart + (long)row * MB;
    float* po = d_probs + (long)row * MB;
    const long PS = (long)HEADS*B*MB;
    float v[5]; float mx = -1e30f;
#pragma unroll
    for (int i = 0; i < 5; i++) {
        int idx = tid + i*256; v[i] = -1e30f;
        if (idx < MB) {
            v[i] = (p0[idx] + p0[PS + idx] + p0[2*PS + idx] + p0[3*PS + idx]) * ATT_SCALE;
            mx = fmaxf(mx, v[i]);
        }
    }
    sh[tid] = mx; __syncthreads();
    for (int st = 128; st > 0; st >>= 1) { if (tid < st) sh[tid] = fmaxf(sh[tid], sh[tid+st]); __syncthreads(); }
    float M = sh[0]; __syncthreads();
    float sum = 0.f;
#pragma unroll
    for (int i = 0; i < 5; i++) {
        int idx = tid + i*256;
        if (idx < MB) { v[i] = __expf(v[i] - M); sum += v[i]; }
    }
    sh[tid] = sum; __syncthreads();
    for (int st = 128; st > 0; st >>= 1) { if (tid < st) sh[tid] += sh[tid+st]; __syncthreads(); }
    float inv = 1.f / sh[0];
#pragma unroll
    for (int i = 0; i < 5; i++) {
        int idx = tid + i*256;
        if (idx < MB) po[idx] = v[i] * inv;
    }
}

/* attn@V: grid (4, 7, 2), chunk 160 -> partials [ks][32 x 1024] */
__global__ __launch_bounds__(256) void attnVs()
{
    __shared__ float As[32][33], Bs[32][132];
    int ks = blockIdx.y, z = blockIdx.z;
    int n0 = blockIdx.x * 128;
    float acc[4][4] = {};
    nn_body(As, Bs, d_probs + (long long)z*B*MB, MB, d_Vc + z*DK, D, n0, ks*160, 5, acc);
    float* C = d_apart + (long long)ks*BD + z*DK;
    int mt = threadIdx.x >> 5, nt = threadIdx.x & 31;
#pragma unroll
    for (int i = 0; i < 4; i++)
#pragma unroll
        for (int j = 0; j < 4; j++)
            C[(long long)(mt*4+i)*D + n0 + nt + 32*j] = acc[i][j];
}

/* Wo: grid (8, 8), chunk 128, 7-way A-sum fused -> partials [ks][BD] */
__global__ __launch_bounds__(256) void wo_gs(const float* __restrict__ Wo)
{
    __shared__ float As[32][33], Bs[32][129];
    int ks = blockIdx.y;
    int n0 = blockIdx.x * 128;
    float acc[4][4] = {};
    nt_body<7,0>(As, Bs, d_apart, D, BD, Wo, D, n0, D, ks*128, 4, acc,
                 nullptr, nullptr, nullptr);
    float* C = d_wopart + (long long)ks*BD;
    int mt = threadIdx.x >> 5, nt = threadIdx.x & 31;
#pragma unroll
    for (int i = 0; i < 4; i++)
#pragma unroll
        for (int j = 0; j < 4; j++)
            C[(long long)(mt*4+i)*D + n0 + nt + 32*j] = acc[i][j];
}

/* LSTM: grid (32, 16). First 8 k-chunks: x @ W_ih. Last 8: fused hupd @ W_hh,
   hupd built in-loader as e + sum(8 woparts) + bo + hcur[l]. */
__global__ __launch_bounds__(256) void lstm_g(const float* __restrict__ Afirst,
    const float* __restrict__ e, const float* __restrict__ hc,
    const float* __restrict__ W1, const float* __restrict__ W2,
    const float* __restrict__ bo)
{
    __shared__ float As[32][33], Bs[32][129];
    int kb = blockIdx.y * 128;
    int n0 = blockIdx.x * 128;
    float acc[4][4] = {};
    if (kb < 1024) {
        nt_body<1,0>(As, Bs, Afirst, D, 0, W1, D, n0, 4096, kb, 4, acc,
                     nullptr, nullptr, nullptr);
    } else {
        nt_body<8,1>(As, Bs, d_wopart, D, BD, W2, D, n0, 4096, kb - 1024, 4, acc,
                     e, hc, bo);
    }
    float* C = d_lstmpart + (long long)blockIdx.y * (B*4096);
    int mt = threadIdx.x >> 5, nt = threadIdx.x & 31;
#pragma unroll
    for (int i = 0; i < 4; i++)
#pragma unroll
        for (int j = 0; j < 4; j++)
            C[(long long)(mt*4+i)*4096 + n0 + nt + 32*j] = acc[i][j];
}

__global__ __launch_bounds__(256) void lstm_cell2(int l, int slot,
    const float* __restrict__ bi, const float* __restrict__ bh, int writeX, int t)
{
    int idx = blockIdx.x * 256 + threadIdx.x;
    int b = idx >> 10, d = idx & 1023;
    const float* p = d_lstmpart + (long long)b * 4096 + d;
    float gi = bi[d] + bh[d];
    float gf = bi[1024+d] + bh[1024+d];
    float gg = bi[2048+d] + bh[2048+d];
    float go = bi[3072+d] + bh[3072+d];
#pragma unroll
    for (int s = 0; s < 16; s++) {
        const float* q = p + (long long)s * (B*4096);
        gi += q[0]; gf += q[1024]; gg += q[2048]; go += q[3072];
    }
    float cp = d_ccur[l*BD + idx];
    float si = 1.f / (1.f + __expf(-gi));
    float sf = 1.f / (1.f + __expf(-gf));
    float so = 1.f / (1.f + __expf(-go));
    float cn = sf * cp + si * tanhf(gg);
    float hn = so * tanhf(cn);
    d_hcur[l*BD + idx] = hn;
    d_ccur[l*BD + idx] = cn;
    d_Hh[((long long)l*MEM + slot)*BD + idx] = hn;
    d_Ch[((long long)l*MEM + slot)*BD + idx] = cn;
    if (writeX) d_X[(long long)t*BD + idx] = hn;
}

/* ---------------- bf16 split conversion ---------------- */
__global__ __launch_bounds__(256) void convW(const float* __restrict__ W)
{
    long long i = (long long)blockIdx.x * 256 + threadIdx.x;
    long long n = i >> 10, k = i & 1023;
    float w = W[i];
    __nv_bfloat16 hi = __float2bfloat16(w);
    __nv_bfloat16 lo = __float2bfloat16(w - __bfloat162float(hi));
    __nv_bfloat16* row = d_Wcat + n * DKC;
    row[k] = hi; row[1024 + k] = lo; row[2048 + k] = hi;
}

__global__ __launch_bounds__(256) void convX()
{
    long long i = (long long)blockIdx.x * 256 + threadIdx.x;
    long long m = i >> 10, k = i & 1023;
    float x = d_X[i];
    __nv_bfloat16 hi = __float2bfloat16(x);
    __nv_bfloat16 lo = __float2bfloat16(x - __bfloat162float(hi));
    __nv_bfloat16* row = d_Xcat + m * DKC;
    row[k] = hi; row[1024 + k] = hi; row[2048 + k] = lo;
}

/* ---------------- decode: bf16 HMMA GEMM, 4-stage cp.async pipeline ---------------- */
#define DSTAGES 4
#define DTILE_B 8192
#define DEC_SMEM (DSTAGES*2*DTILE_B)

__device__ __forceinline__ void ldsm4(uint32_t& r0, uint32_t& r1, uint32_t& r2, uint32_t& r3, uint32_t addr)
{
    asm volatile("ldmatrix.sync.aligned.m8n8.x4.shared.b16 {%0,%1,%2,%3}, [%4];" : "=r"(r0), "=r"(r1), "=r"(r2), "=r"(r3) : "r"(addr));
}
__device__ __forceinline__ void mma16816(float* d, const uint32_t* a, uint32_t b0, uint32_t b1)
{
    asm volatile("mma.sync.aligned.m16n8k16.row.col.f32.bf16.bf16.f32 {%0,%1,%2,%3}, {%4,%5,%6,%7}, {%8,%9}, {%0,%1,%2,%3};" : "+f"(d[0]), "+f"(d[1]), "+f"(d[2]), "+f"(d[3]) : "r"(a[0]), "r"(a[1]), "r"(a[2]), "r"(a[3]), "r"(b0), "r"(b1));
}
__device__ __forceinline__ void cpasync16(uint32_t saddr, const void* g)
{
    asm volatile("cp.async.cg.shared.global [%0], [%1], 16;" :: "r"(saddr), "l"(g));
}
__device__ __forceinline__ uint32_t smem_u32d(const void* p)
{
    uint32_t a;
    asm("{ .reg .u64 t; cvta.to.shared.u64 t, %1; cvt.u32.u64 %0, t; }" : "=r"(a) : "l"(p));
    return a;
}

__global__ __launch_bounds__(256) void mma_decode(const float* __restrict__ bias,
                                                  float* __restrict__ C)
{
    extern __shared__ __align__(16) char dsm[];
    uint32_t aBase = smem_u32d(dsm);
    uint32_t bBase = aBase + DSTAGES*DTILE_B;
    int tid = threadIdx.x;
    int wid = tid >> 5, lane = tid & 31;
    int wm = wid >> 1, wn = wid & 1;
    long long m0 = (long long)blockIdx.x * 128;
    long long n0 = (long long)blockIdx.y * 128;

    int lrow0 = tid >> 2, gc = tid & 3;
    int lrow1 = lrow0 + 64;
    uint32_t soff0 = (uint32_t)(lrow0*4 + (gc ^ ((lrow0 >> 1) & 3))) * 16;
    uint32_t soff1 = (uint32_t)(lrow1*4 + (gc ^ ((lrow1 >> 1) & 3))) * 16;
    const char* gA0 = (const char*)(d_Xcat + (m0 + lrow0)*DKC) + gc*16;
    const char* gA1 = (const char*)(d_Xcat + (m0 + lrow1)*DKC) + gc*16;
    const char* gB0 = (const char*)(d_Wcat + (n0 + lrow0)*DKC) + gc*16;
    const char* gB1 = (const char*)(d_Wcat + (n0 + lrow1)*DKC) + gc*16;

    int lane7 = lane & 7;
    int mrow[2], msw[2];
#pragma unroll
    for (int mi = 0; mi < 2; mi++) {
        mrow[mi] = wm*32 + mi*16 + lane7 + ((lane >> 3) & 1)*8;
        msw[mi] = (mrow[mi] >> 1) & 3;
    }
    int kgA = lane >> 4;
    int nrow[4], nsw[4];
#pragma unroll
    for (int nb = 0; nb < 4; nb++) {
        nrow[nb] = wn*64 + nb*16 + lane7 + ((lane >> 4) & 1)*8;
        nsw[nb] = (nrow[nb] >> 1) & 3;
    }
    int kgB = (lane >> 3) & 1;

    float acc[2][8][4];
#pragma unroll
    for (int i = 0; i < 2; i++)
#pragma unroll
        for (int j = 0; j < 8; j++)
#pragma unroll
            for (int r = 0; r < 4; r++) acc[i][j][r] = 0.f;

    const int NCHUNK = DKC/32;

#pragma unroll
    for (int s = 0; s < DSTAGES-1; s++) {
        uint32_t sa = aBase + (uint32_t)(s & (DSTAGES-1))*DTILE_B;
        uint32_t sb = bBase + (uint32_t)(s & (DSTAGES-1))*DTILE_B;
        cpasync16(sa + soff0, gA0 + s*64);
        cpasync16(sa + soff1, gA1 + s*64);
        cpasync16(sb + soff0, gB0 + s*64);
        cpasync16(sb + soff1, gB1 + s*64);
        asm volatile("cp.async.commit_group;" ::: "memory");
    }

    for (int kc = 0; kc < NCHUNK; kc++) {
        int buf = kc & (DSTAGES-1);
        asm volatile("cp.async.wait_group %0;" :: "n"(DSTAGES-2) : "memory");
        __syncthreads();
        {
            int s = kc + DSTAGES - 1;
            if (s < NCHUNK) {
                uint32_t sa = aBase + (uint32_t)(s & (DSTAGES-1))*DTILE_B;
                uint32_t sb = bBase + (uint32_t)(s & (DSTAGES-1))*DTILE_B;
                cpasync16(sa + soff0, gA0 + s*64);
                cpasync16(sa + soff1, gA1 + s*64);
                cpasync16(sb + soff0, gB0 + s*64);
                cpasync16(sb + soff1, gB1 + s*64);
            }
            asm volatile("cp.async.commit_group;" ::: "memory");
        }
        uint32_t aB = aBase + (uint32_t)buf*DTILE_B;
        uint32_t bB = bBase + (uint32_t)buf*DTILE_B;
#pragma unroll
        for (int kk = 0; kk < 2; kk++) {
            uint32_t afr[2][4];
#pragma unroll
            for (int mi = 0; mi < 2; mi++) {
                int kg = kk*2 + kgA;
                ldsm4(afr[mi][0], afr[mi][1], afr[mi][2], afr[mi][3],
                      aB + (uint32_t)(mrow[mi]*64 + ((kg ^ msw[mi])*16)));
            }
#pragma unroll
            for (int nb = 0; nb < 4; nb++) {
                uint32_t bf0, bf1, bf2, bf3;
                int kg = kk*2 + kgB;
                ldsm4(bf0, bf1, bf2, bf3,
                      bB + (uint32_t)(nrow[nb]*64 + ((kg ^ nsw[nb])*16)));
#pragma unroll
                for (int mi = 0; mi < 2; mi++) {
                    mma16816(acc[mi][nb*2+0], afr[mi], bf0, bf1);
                    mma16816(acc[mi][nb*2+1], afr[mi], bf2, bf3);
                }
            }
        }
    }

#pragma unroll
    for (int mi = 0; mi < 2; mi++) {
#pragma unroll
        for (int nt = 0; nt < 8; nt++) {
            long long row = m0 + wm*32 + mi*16 + (lane >> 2);
            long long col = n0 + wn*64 + nt*8 + (lane & 3)*2;
            float c0 = bias[col], c1 = bias[col+1];
            *(float2*)(C + row*NTOK + col) =
                make_float2(acc[mi][nt][0] + c0, acc[mi][nt][1] + c1);
            *(float2*)(C + (row+8)*NTOK + col) =
                make_float2(acc[mi][nt][2] + c0, acc[mi][nt][3] + c1);
        }
    }
}

/* ---------------- host launch ---------------- */
extern "C" void kernel_launch(void* const* d_in, const int* in_sizes, int n_in,
                              void* d_out, int out_size)
{
    (void)in_sizes; (void)n_in; (void)out_size;
    const int*   tok  = (const int*)d_in[0];
    const float* emb  = (const float*)d_in[1];
    const float* ln_g = (const float*)d_in[2];
    const float* ln_b = (const float*)d_in[3];
    const float* Wq = (const float*)d_in[4];  const float* bq = (const float*)d_in[5];
    const float* Wk = (const float*)d_in[6];  const float* bk = (const float*)d_in[7];
    const float* Wv = (const float*)d_in[8];  const float* bv = (const float*)d_in[9];
    const float* Wo = (const float*)d_in[10]; const float* bo = (const float*)d_in[11];
    const float* Wih = (const float*)d_in[12]; const float* bih = (const float*)d_in[13];
    const float* Whh = (const float*)d_in[14]; const float* bhh = (const float*)d_in[15];
    const float* dW = (const float*)d_in[16]; const float* db = (const float*)d_in[17];
    const float* h0 = (const float*)d_in[18]; const float* c0 = (const float*)d_in[19];
    const float* H0 = (const float*)d_in[20]; const float* C0 = (const float*)d_in[21];
    float* out = (float*)d_out;

    float *p_eAll, *p_lnAll, *p_hcur;
    cudaGetSymbolAddress((void**)&p_eAll,  d_eAll);
    cudaGetSymbolAddress((void**)&p_lnAll, d_lnAll);
    cudaGetSymbolAddress((void**)&p_hcur,  d_hcur);

    cudaFuncSetAttribute(mma_decode, cudaFuncAttributeMaxDynamicSharedMemorySize, DEC_SMEM);

    init_state<<<8960, 256>>>(h0, c0, H0, C0);
    embed_all<<<T_STEPS*B, 256>>>(tok, emb, ln_g, ln_b);
    kv_init<<<dim3(8, 35, 2), 256>>>(H0, Wk, Wv, bk, bv);
    convW<<<(NTOK*1024)/256, 256>>>(dW);

    for (int t = 0; t < T_STEPS; t++) {
        int slot = t % MEM;
        int slotPrev = (t + MEM - 1) % MEM;
        const float* e_t = p_eAll + (long long)t*BD;
        qkv3s<<<dim3(8, 8, t == 0 ? 1 : 3), 256>>>(p_lnAll + (long long)t*BD, p_hcur,
                                                   Wq, Wk, Wv);
        qkv_red<<<384, 256>>>(bq, bk, bv, slotPrev, t > 0);
        scores_ks<<<dim3(9, 4, HEADS), 256>>>();
        softmax2<<<HEADS*B, 256>>>();
        attnVs<<<dim3(4, 7, HEADS), 256>>>();
        wo_gs<<<dim3(8, 8), 256>>>(Wo);
        lstm_g<<<dim3(32, 16), 256>>>(e_t, e_t, p_hcur, Wih, Whh, bo);
        lstm_cell2<<<128, 256>>>(0, slot, bih, bhh, 0, t);
        lstm_g<<<dim3(32, 16), 256>>>(p_hcur, e_t, p_hcur + BD,
                                      Wih + 4096*1024, Whh + 4096*1024, bo);
        lstm_cell2<<<128, 256>>>(1, slot, bih + 4096, bhh + 4096, 1, t);
    }

    convX<<<(T_STEPS*B*1024)/256, 256>>>();
    mma_decode<<<dim3((T_STEPS*B)/128, NTOK/128), 256, DEC_SMEM>>>(db, out);
    write_tail<<<8960, 256>>>(out);
}

// round 15
// speedup vs baseline: 4.5433x; 1.0385x over previous
#include <cuda_runtime.h>
#include <cuda_bf16.h>
#include <stdint.h>
#include <math.h>

#define T_STEPS 64
#define B 32
#define D 1024
#define L 2
#define MEM 35
#define NTOK 32000
#define HEADS 2
#define DK 512
#define MB (MEM*B)
#define BD (B*D)
#define EPS 1e-6f
#define ATT_SCALE 0.04419417382415922f
#define DKC 3072

#define OFF_H   65536000L
#define OFF_C   65601536L
#define OFF_HM  65667072L
#define OFF_CM  67960832L

__device__ float d_eAll[T_STEPS*BD];
__device__ float d_lnAll[T_STEPS*BD];
__device__ float d_q[BD];
__device__ float d_qkvpart[24*BD];
__device__ float d_scpart[4*HEADS*B*MB];
__device__ float d_probs[HEADS*B*MB];
__device__ float d_apart[7*BD];
__device__ float d_wopart[8*BD];
__device__ float d_lstmpart[16*B*4096];
__device__ float d_hcur[L*BD];
__device__ float d_ccur[L*BD];
__device__ float d_Kc[MB*D];
__device__ float d_Vc[MB*D];
__device__ float d_Hh[L*MEM*BD];
__device__ float d_Ch[L*MEM*BD];
__device__ float d_X[T_STEPS*BD];
__device__ __nv_bfloat16 d_Wcat[(long long)NTOK*DKC];
__device__ __nv_bfloat16 d_Xcat[(long long)T_STEPS*B*DKC];

/* ---------------- skinny-GEMM cores (M=32, BN=128) ---------------- */
template<int AP, int FUSED>
__device__ __forceinline__ void nt_body(float (*As)[33], float (*Bs)[129],
    const float* A, int lda, long long aStride, const float* W, int ldw,
    int n0, int Nrows, int kbeg, int ntiles, float acc[4][4],
    const float* eP, const float* hP, const float* boP)
{
    int tid = threadIdx.x;
    int lm = tid >> 3, lk4 = (tid & 7) * 4;
    int mt = tid >> 5, nt = tid & 31;
    const float* arow = A + (long long)lm*lda + kbeg + lk4;
    const float* wr0 = W + kbeg + lk4;
    long long woff[4]; bool wok[4];
#pragma unroll
    for (int c = 0; c < 4; c++) {
        int n = n0 + lm + 32*c;
        wok[c] = (n < Nrows);
        woff[c] = (long long)(wok[c] ? n : 0) * ldw;
    }
    float4 z4 = make_float4(0.f,0.f,0.f,0.f);
    float4 pa = *(const float4*)arow;
#pragma unroll
    for (int p = 1; p < AP; p++) {
        float4 u = *(const float4*)(arow + (long long)p*aStride);
        pa.x += u.x; pa.y += u.y; pa.z += u.z; pa.w += u.w;
    }
    if (FUSED) {
        float4 ev = *(const float4*)(eP + (long long)lm*lda + kbeg + lk4);
        float4 hv = *(const float4*)(hP + (long long)lm*lda + kbeg + lk4);
        float4 bv = *(const float4*)(boP + kbeg + lk4);
        pa.x += ev.x + hv.x + bv.x; pa.y += ev.y + hv.y + bv.y;
        pa.z += ev.z + hv.z + bv.z; pa.w += ev.w + hv.w + bv.w;
    }
    float4 pb[4];
#pragma unroll
    for (int c = 0; c < 4; c++) pb[c] = wok[c] ? *(const float4*)(wr0 + woff[c]) : z4;
    for (int kt = 0; kt < ntiles; kt++) {
        __syncthreads();
        As[lk4+0][lm]=pa.x; As[lk4+1][lm]=pa.y; As[lk4+2][lm]=pa.z; As[lk4+3][lm]=pa.w;
#pragma unroll
        for (int c = 0; c < 4; c++) {
            int n = lm + 32*c;
            Bs[lk4+0][n]=pb[c].x; Bs[lk4+1][n]=pb[c].y; Bs[lk4+2][n]=pb[c].z; Bs[lk4+3][n]=pb[c].w;
        }
        __syncthreads();
        if (kt + 1 < ntiles) {
            int ko = (kt+1)*32;
            pa = *(const float4*)(arow + ko);
#pragma unroll
            for (int p = 1; p < AP; p++) {
                float4 u = *(const float4*)(arow + ko + (long long)p*aStride);
                pa.x += u.x; pa.y += u.y; pa.z += u.z; pa.w += u.w;
            }
            if (FUSED) {
                float4 ev = *(const float4*)(eP + (long long)lm*lda + kbeg + ko + lk4);
                float4 hv = *(const float4*)(hP + (long long)lm*lda + kbeg + ko + lk4);
                float4 bv = *(const float4*)(boP + kbeg + ko + lk4);
                pa.x += ev.x + hv.x + bv.x; pa.y += ev.y + hv.y + bv.y;
                pa.z += ev.z + hv.z + bv.z; pa.w += ev.w + hv.w + bv.w;
            }
#pragma unroll
            for (int c = 0; c < 4; c++) pb[c] = wok[c] ? *(const float4*)(wr0 + woff[c] + ko) : z4;
        }
#pragma unroll
        for (int kk = 0; kk < 32; kk++) {
            float a0=As[kk][mt*4+0], a1=As[kk][mt*4+1], a2=As[kk][mt*4+2], a3=As[kk][mt*4+3];
            float b0=Bs[kk][nt], b1=Bs[kk][nt+32], b2=Bs[kk][nt+64], b3=Bs[kk][nt+96];
            acc[0][0]+=a0*b0; acc[0][1]+=a0*b1; acc[0][2]+=a0*b2; acc[0][3]+=a0*b3;
            acc[1][0]+=a1*b0; acc[1][1]+=a1*b1; acc[1][2]+=a1*b2; acc[1][3]+=a1*b3;
            acc[2][0]+=a2*b0; acc[2][1]+=a2*b1; acc[2][2]+=a2*b2; acc[2][3]+=a2*b3;
            acc[3][0]+=a3*b0; acc[3][1]+=a3*b1; acc[3][2]+=a3*b2; acc[3][3]+=a3*b3;
        }
    }
}

__device__ __forceinline__ void nn_body(float (*As)[33], float (*Bs)[132],
    const float* A, int lda, const float* Bm, int ldb,
    int n0, int kbeg, int ntiles, float acc[4][4])
{
    int tid = threadIdx.x;
    int lm = tid >> 3, lk4 = (tid & 7) * 4;
    int mt = tid >> 5, nt = tid & 31;
    const float* arow = A + (long long)lm*lda + kbeg + lk4;
    int brow = tid >> 5, bcol = (tid & 31) * 4;
    const float* bbase = Bm + (long long)(kbeg + brow)*ldb + n0 + bcol;
    float4 pa = *(const float4*)arow;
    float4 pb[4];
#pragma unroll
    for (int c = 0; c < 4; c++) pb[c] = *(const float4*)(bbase + (long long)(8*c)*ldb);
    for (int kt = 0; kt < ntiles; kt++) {
        __syncthreads();
        As[lk4+0][lm]=pa.x; As[lk4+1][lm]=pa.y; As[lk4+2][lm]=pa.z; As[lk4+3][lm]=pa.w;
#pragma unroll
        for (int c = 0; c < 4; c++) *(float4*)&Bs[brow+8*c][bcol] = pb[c];
        __syncthreads();
        if (kt + 1 < ntiles) {
            int ko = (kt+1)*32;
            pa = *(const float4*)(arow + ko);
#pragma unroll
            for (int c = 0; c < 4; c++) pb[c] = *(const float4*)(bbase + (long long)(ko + 8*c)*ldb);
        }
#pragma unroll
        for (int kk = 0; kk < 32; kk++) {
            float a0=As[kk][mt*4+0], a1=As[kk][mt*4+1], a2=As[kk][mt*4+2], a3=As[kk][mt*4+3];
            float b0=Bs[kk][nt], b1=Bs[kk][nt+32], b2=Bs[kk][nt+64], b3=Bs[kk][nt+96];
            acc[0][0]+=a0*b0; acc[0][1]+=a0*b1; acc[0][2]+=a0*b2; acc[0][3]+=a0*b3;
            acc[1][0]+=a1*b0; acc[1][1]+=a1*b1; acc[1][2]+=a1*b2; acc[1][3]+=a1*b3;
            acc[2][0]+=a2*b0; acc[2][1]+=a2*b1; acc[2][2]+=a2*b2; acc[2][3]+=a2*b3;
            acc[3][0]+=a3*b0; acc[3][1]+=a3*b1; acc[3][2]+=a3*b2; acc[3][3]+=a3*b3;
        }
    }
}

/* ---------------- init / embed / tail ---------------- */
__global__ __launch_bounds__(256) void init_state(const float* __restrict__ h0,
    const float* __restrict__ c0, const float* __restrict__ H0, const float* __restrict__ C0)
{
    long i = (long)blockIdx.x * 256 + threadIdx.x;
    if (i < (long)L*BD) { d_hcur[i] = h0[i]; d_ccur[i] = c0[i]; }
    if (i < (long)L*MEM*BD) { d_Hh[i] = H0[i]; d_Ch[i] = C0[i]; }
}

__global__ __launch_bounds__(256) void write_tail(float* __restrict__ out)
{
    long i = (long)blockIdx.x * 256 + threadIdx.x;
    if (i >= (long)L*MEM*BD) return;
    if (i < (long)L*BD) { out[OFF_H + i] = d_hcur[i]; out[OFF_C + i] = d_ccur[i]; }
    long l = i / ((long)MEM*BD);
    long r = i % ((long)MEM*BD);
    long j = r / BD, q = r % BD;
    long phys = (T_STEPS + j) % MEM;
    out[OFF_HM + i] = d_Hh[(l*MEM + phys)*(long)BD + q];
    out[OFF_CM + i] = d_Ch[(l*MEM + phys)*(long)BD + q];
}

__global__ __launch_bounds__(256) void embed_all(const int* __restrict__ tok,
    const float* __restrict__ emb, const float* __restrict__ gg, const float* __restrict__ bb)
{
    __shared__ float sh[256];
    int r = blockIdx.x, tid = threadIdx.x;
    const float* row = emb + (long)tok[r] * D;
    float x[4]; float s = 0.f;
#pragma unroll
    for (int i = 0; i < 4; i++) { x[i] = row[tid + i*256]; s += x[i]; }
    sh[tid] = s; __syncthreads();
    for (int st = 128; st > 0; st >>= 1) { if (tid < st) sh[tid] += sh[tid+st]; __syncthreads(); }
    float mu = sh[0] * (1.f / D); __syncthreads();
    float ss = 0.f;
#pragma unroll
    for (int i = 0; i < 4; i++) { float dd = x[i] - mu; ss += dd*dd; }
    sh[tid] = ss; __syncthreads();
    for (int st = 128; st > 0; st >>= 1) { if (tid < st) sh[tid] += sh[tid+st]; __syncthreads(); }
    float inv = 1.f / (sqrtf(sh[0] / (float)(D - 1)) + EPS);
#pragma unroll
    for (int i = 0; i < 4; i++) {
        int idx = tid + i*256;
        d_eAll[(long)r*D + idx]  = x[i];
        d_lnAll[(long)r*D + idx] = gg[idx] * (x[i] - mu) * inv + bb[idx];
    }
}

/* ---------------- per-step GEMM kernels (deep split-K) ---------------- */
__global__ __launch_bounds__(256) void kv_init(const float* __restrict__ H0,
    const float* __restrict__ Wk, const float* __restrict__ Wv,
    const float* __restrict__ bk, const float* __restrict__ bv)
{
    __shared__ float As[32][33], Bs[32][129];
    int z = blockIdx.z;
    const float* W = z ? Wv : Wk;
    const float* bias = z ? bv : bk;
    float* C = (z ? d_Vc : d_Kc) + (long long)blockIdx.y * 32 * D;
    const float* A = H0 + (long long)blockIdx.y * 32 * D;
    int n0 = blockIdx.x * 128;
    float acc[4][4] = {};
    nt_body<1,0>(As, Bs, A, D, 0, W, D, n0, D, 0, 32, acc, nullptr, nullptr, nullptr);
    int mt = threadIdx.x >> 5, nt = threadIdx.x & 31;
#pragma unroll
    for (int i = 0; i < 4; i++)
#pragma unroll
        for (int j = 0; j < 4; j++) {
            int n = n0 + nt + 32*j;
            C[(long long)(mt*4+i)*D + n] = acc[i][j] + bias[n];
        }
}

__global__ __launch_bounds__(256) void qkv3s(const float* __restrict__ ln,
    const float* __restrict__ hsrc, const float* __restrict__ Wq,
    const float* __restrict__ Wk, const float* __restrict__ Wv)
{
    __shared__ float As[32][33], Bs[32][129];
    int ks = blockIdx.y, z = blockIdx.z;
    const float* A = (z == 0) ? ln : hsrc;
    const float* W = (z == 0) ? Wq : ((z == 1) ? Wk : Wv);
    float* C = d_qkvpart + (long long)(ks*3 + z) * BD;
    int n0 = blockIdx.x * 128;
    float acc[4][4] = {};
    nt_body<1,0>(As, Bs, A, D, 0, W, D, n0, D, ks*128, 4, acc, nullptr, nullptr, nullptr);
    int mt = threadIdx.x >> 5, nt = threadIdx.x & 31;
#pragma unroll
    for (int i = 0; i < 4; i++)
#pragma unroll
        for (int j = 0; j < 4; j++)
            C[(long long)(mt*4+i)*D + n0 + nt + 32*j] = acc[i][j];
}

__global__ __launch_bounds__(256) void qkv_red(const float* __restrict__ bq,
    const float* __restrict__ bk, const float* __restrict__ bv, int slotPrev, int writeKV)
{
    int i = blockIdx.x * 256 + threadIdx.x;
    int z = i >> 15, j = i & (BD-1);
    if (z && !writeKV) return;
    float v = 0.f;
#pragma unroll
    for (int s = 0; s < 8; s++) v += d_qkvpart[(long long)(s*3 + z)*BD + j];
    int col = j & 1023;
    if (z == 0)      d_q[j] = v + bq[col];
    else if (z == 1) d_Kc[(long long)slotPrev*BD + j] = v + bk[col];
    else             d_Vc[(long long)slotPrev*BD + j] = v + bv[col];
}

__global__ __launch_bounds__(256) void scores_ks()
{
    __shared__ float As[32][33], Bs[32][129];
    int ks = blockIdx.y, z = blockIdx.z;
    int n0 = blockIdx.x * 128;
    float acc[4][4] = {};
    nt_body<1,0>(As, Bs, d_q + z*DK, D, 0, d_Kc + z*DK, D, n0, MB, ks*128, 4, acc,
                 nullptr, nullptr, nullptr);
    float* C = d_scpart + (long long)(ks*HEADS + z) * (B*MB);
    int mt = threadIdx.x >> 5, nt = threadIdx.x & 31;
#pragma unroll
    for (int i = 0; i < 4; i++)
#pragma unroll
        for (int j = 0; j < 4; j++) {
            int n = n0 + nt + 32*j;
            if (n < MB) C[(long long)(mt*4+i)*MB + n] = acc[i][j];
        }
}

__global__ __launch_bounds__(256) void softmax2()
{
    __shared__ float sh[256];
    int row = blockIdx.x, tid = threadIdx.x;
    const float* p0 = d_scpart + (long)row * MB;
    float* po = d_probs + (long)row * MB;
    const long PS = (long)HEADS*B*MB;
    float v[5]; float mx = -1e30f;
#pragma unroll
    for (int i = 0; i < 5; i++) {
        int idx = tid + i*256; v[i] = -1e30f;
        if (idx < MB) {
            v[i] = (p0[idx] + p0[PS + idx] + p0[2*PS + idx] + p0[3*PS + idx]) * ATT_SCALE;
            mx = fmaxf(mx, v[i]);
        }
    }
    sh[tid] = mx; __syncthreads();
    for (int st = 128; st > 0; st >>= 1) { if (tid < st) sh[tid] = fmaxf(sh[tid], sh[tid+st]); __syncthreads(); }
    float M = sh[0]; __syncthreads();
    float sum = 0.f;
#pragma unroll
    for (int i = 0; i < 5; i++) {
        int idx = tid + i*256;
        if (idx < MB) { v[i] = __expf(v[i] - M); sum += v[i]; }
    }
    sh[tid] = sum; __syncthreads();
    for (int st = 128; st > 0; st >>= 1) { if (tid < st) sh[tid] += sh[tid+st]; __syncthreads(); }
    float inv = 1.f / sh[0];
#pragma unroll
    for (int i = 0; i < 5; i++) {
        int idx = tid + i*256;
        if (idx < MB) po[idx] = v[i] * inv;
    }
}

__global__ __launch_bounds__(256) void attnVs()
{
    __shared__ float As[32][33], Bs[32][132];
    int ks = blockIdx.y, z = blockIdx.z;
    int n0 = blockIdx.x * 128;
    float acc[4][4] = {};
    nn_body(As, Bs, d_probs + (long long)z*B*MB, MB, d_Vc + z*DK, D, n0, ks*160, 5, acc);
    float* C = d_apart + (long long)ks*BD + z*DK;
    int mt = threadIdx.x >> 5, nt = threadIdx.x & 31;
#pragma unroll
    for (int i = 0; i < 4; i++)
#pragma unroll
        for (int j = 0; j < 4; j++)
            C[(long long)(mt*4+i)*D + n0 + nt + 32*j] = acc[i][j];
}

__global__ __launch_bounds__(256) void wo_gs(const float* __restrict__ Wo)
{
    __shared__ float As[32][33], Bs[32][129];
    int ks = blockIdx.y;
    int n0 = blockIdx.x * 128;
    float acc[4][4] = {};
    nt_body<7,0>(As, Bs, d_apart, D, BD, Wo, D, n0, D, ks*128, 4, acc,
                 nullptr, nullptr, nullptr);
    float* C = d_wopart + (long long)ks*BD;
    int mt = threadIdx.x >> 5, nt = threadIdx.x & 31;
#pragma unroll
    for (int i = 0; i < 4; i++)
#pragma unroll
        for (int j = 0; j < 4; j++)
            C[(long long)(mt*4+i)*D + n0 + nt + 32*j] = acc[i][j];
}

__global__ __launch_bounds__(256) void lstm_g(const float* __restrict__ Afirst,
    const float* __restrict__ e, const float* __restrict__ hc,
    const float* __restrict__ W1, const float* __restrict__ W2,
    const float* __restrict__ bo)
{
    __shared__ float As[32][33], Bs[32][129];
    int kb = blockIdx.y * 128;
    int n0 = blockIdx.x * 128;
    float acc[4][4] = {};
    if (kb < 1024) {
        nt_body<1,0>(As, Bs, Afirst, D, 0, W1, D, n0, 4096, kb, 4, acc,
                     nullptr, nullptr, nullptr);
    } else {
        nt_body<8,1>(As, Bs, d_wopart, D, BD, W2, D, n0, 4096, kb - 1024, 4, acc,
                     e, hc, bo);
    }
    float* C = d_lstmpart + (long long)blockIdx.y * (B*4096);
    int mt = threadIdx.x >> 5, nt = threadIdx.x & 31;
#pragma unroll
    for (int i = 0; i < 4; i++)
#pragma unroll
        for (int j = 0; j < 4; j++)
            C[(long long)(mt*4+i)*4096 + n0 + nt + 32*j] = acc[i][j];
}

__global__ __launch_bounds__(256) void lstm_cell2(int l, int slot,
    const float* __restrict__ bi, const float* __restrict__ bh, int writeX, int t)
{
    int idx = blockIdx.x * 256 + threadIdx.x;
    int b = idx >> 10, d = idx & 1023;
    const float* p = d_lstmpart + (long long)b * 4096 + d;
    float gi = bi[d] + bh[d];
    float gf = bi[1024+d] + bh[1024+d];
    float gg = bi[2048+d] + bh[2048+d];
    float go = bi[3072+d] + bh[3072+d];
#pragma unroll
    for (int s = 0; s < 16; s++) {
        const float* q = p + (long long)s * (B*4096);
        gi += q[0]; gf += q[1024]; gg += q[2048]; go += q[3072];
    }
    float cp = d_ccur[l*BD + idx];
    float si = 1.f / (1.f + __expf(-gi));
    float sf = 1.f / (1.f + __expf(-gf));
    float so = 1.f / (1.f + __expf(-go));
    float cn = sf * cp + si * tanhf(gg);
    float hn = so * tanhf(cn);
    d_hcur[l*BD + idx] = hn;
    d_ccur[l*BD + idx] = cn;
    d_Hh[((long long)l*MEM + slot)*BD + idx] = hn;
    d_Ch[((long long)l*MEM + slot)*BD + idx] = cn;
    if (writeX) d_X[(long long)t*BD + idx] = hn;
}

/* ---------------- bf16 split conversion ---------------- */
__global__ __launch_bounds__(256) void convW(const float* __restrict__ W)
{
    long long i = (long long)blockIdx.x * 256 + threadIdx.x;
    long long n = i >> 10, k = i & 1023;
    float w = W[i];
    __nv_bfloat16 hi = __float2bfloat16(w);
    __nv_bfloat16 lo = __float2bfloat16(w - __bfloat162float(hi));
    __nv_bfloat16* row = d_Wcat + n * DKC;
    row[k] = hi; row[1024 + k] = lo; row[2048 + k] = hi;
}

/* converts rows [stripe*128, stripe*128+128) of X -> Xcat */
__global__ __launch_bounds__(256) void convX_chunk(int stripe)
{
    long long g = (long long)stripe * (128*1024) + blockIdx.x * 256 + threadIdx.x;
    long long m = g >> 10, k = g & 1023;
    float x = d_X[g];
    __nv_bfloat16 hi = __float2bfloat16(x);
    __nv_bfloat16 lo = __float2bfloat16(x - __bfloat162float(hi));
    __nv_bfloat16* row = d_Xcat + m * DKC;
    row[k] = hi; row[1024 + k] = hi; row[2048 + k] = lo;
}

/* ---------------- decode stripe: bf16 HMMA GEMM, 4-stage cp.async pipeline ----------
   One m-stripe (128 rows) per launch: grid (250 n-blocks). */
#define DSTAGES 4
#define DTILE_B 8192
#define DEC_SMEM (DSTAGES*2*DTILE_B)

__device__ __forceinline__ void ldsm4(uint32_t& r0, uint32_t& r1, uint32_t& r2, uint32_t& r3, uint32_t addr)
{
    asm volatile("ldmatrix.sync.aligned.m8n8.x4.shared.b16 {%0,%1,%2,%3}, [%4];" : "=r"(r0), "=r"(r1), "=r"(r2), "=r"(r3) : "r"(addr));
}
__device__ __forceinline__ void mma16816(float* d, const uint32_t* a, uint32_t b0, uint32_t b1)
{
    asm volatile("mma.sync.aligned.m16n8k16.row.col.f32.bf16.bf16.f32 {%0,%1,%2,%3}, {%4,%5,%6,%7}, {%8,%9}, {%0,%1,%2,%3};" : "+f"(d[0]), "+f"(d[1]), "+f"(d[2]), "+f"(d[3]) : "r"(a[0]), "r"(a[1]), "r"(a[2]), "r"(a[3]), "r"(b0), "r"(b1));
}
__device__ __forceinline__ void cpasync16(uint32_t saddr, const void* g)
{
    asm volatile("cp.async.cg.shared.global [%0], [%1], 16;" :: "r"(saddr), "l"(g));
}
__device__ __forceinline__ uint32_t smem_u32d(const void* p)
{
    uint32_t a;
    asm("{ .reg .u64 t; cvta.to.shared.u64 t, %1; cvt.u32.u64 %0, t; }" : "=r"(a) : "l"(p));
    return a;
}

__global__ __launch_bounds__(256) void mma_decode(const float* __restrict__ bias,
                                                  float* __restrict__ C, int mstripe)
{
    extern __shared__ __align__(16) char dsm[];
    uint32_t aBase = smem_u32d(dsm);
    uint32_t bBase = aBase + DSTAGES*DTILE_B;
    int tid = threadIdx.x;
    int wid = tid >> 5, lane = tid & 31;
    int wm = wid >> 1, wn = wid & 1;
    long long m0 = (long long)mstripe * 128;
    long long n0 = (long long)blockIdx.x * 128;

    int lrow0 = tid >> 2, gc = tid & 3;
    int lrow1 = lrow0 + 64;
    uint32_t soff0 = (uint32_t)(lrow0*4 + (gc ^ ((lrow0 >> 1) & 3))) * 16;
    uint32_t soff1 = (uint32_t)(lrow1*4 + (gc ^ ((lrow1 >> 1) & 3))) * 16;
    const char* gA0 = (const char*)(d_Xcat + (m0 + lrow0)*DKC) + gc*16;
    const char* gA1 = (const char*)(d_Xcat + (m0 + lrow1)*DKC) + gc*16;
    const char* gB0 = (const char*)(d_Wcat + (n0 + lrow0)*DKC) + gc*16;
    const char* gB1 = (const char*)(d_Wcat + (n0 + lrow1)*DKC) + gc*16;

    int lane7 = lane & 7;
    int mrow[2], msw[2];
#pragma unroll
    for (int mi = 0; mi < 2; mi++) {
        mrow[mi] = wm*32 + mi*16 + lane7 + ((lane >> 3) & 1)*8;
        msw[mi] = (mrow[mi] >> 1) & 3;
    }
    int kgA = lane >> 4;
    int nrow[4], nsw[4];
#pragma unroll
    for (int nb = 0; nb < 4; nb++) {
        nrow[nb] = wn*64 + nb*16 + lane7 + ((lane >> 4) & 1)*8;
        nsw[nb] = (nrow[nb] >> 1) & 3;
    }
    int kgB = (lane >> 3) & 1;

    float acc[2][8][4];
#pragma unroll
    for (int i = 0; i < 2; i++)
#pragma unroll
        for (int j = 0; j < 8; j++)
#pragma unroll
            for (int r = 0; r < 4; r++) acc[i][j][r] = 0.f;

    const int NCHUNK = DKC/32;

#pragma unroll
    for (int s = 0; s < DSTAGES-1; s++) {
        uint32_t sa = aBase + (uint32_t)(s & (DSTAGES-1))*DTILE_B;
        uint32_t sb = bBase + (uint32_t)(s & (DSTAGES-1))*DTILE_B;
        cpasync16(sa + soff0, gA0 + s*64);
        cpasync16(sa + soff1, gA1 + s*64);
        cpasync16(sb + soff0, gB0 + s*64);
        cpasync16(sb + soff1, gB1 + s*64);
        asm volatile("cp.async.commit_group;" ::: "memory");
    }

    for (int kc = 0; kc < NCHUNK; kc++) {
        int buf = kc & (DSTAGES-1);
        asm volatile("cp.async.wait_group %0;" :: "n"(DSTAGES-2) : "memory");
        __syncthreads();
        {
            int s = kc + DSTAGES - 1;
            if (s < NCHUNK) {
                uint32_t sa = aBase + (uint32_t)(s & (DSTAGES-1))*DTILE_B;
                uint32_t sb = bBase + (uint32_t)(s & (DSTAGES-1))*DTILE_B;
                cpasync16(sa + soff0, gA0 + s*64);
                cpasync16(sa + soff1, gA1 + s*64);
                cpasync16(sb + soff0, gB0 + s*64);
                cpasync16(sb + soff1, gB1 + s*64);
            }
            asm volatile("cp.async.commit_group;" ::: "memory");
        }
        uint32_t aB = aBase + (uint32_t)buf*DTILE_B;
        uint32_t bB = bBase + (uint32_t)buf*DTILE_B;
#pragma unroll
        for (int kk = 0; kk < 2; kk++) {
            uint32_t afr[2][4];
#pragma unroll
            for (int mi = 0; mi < 2; mi++) {
                int kg = kk*2 + kgA;
                ldsm4(afr[mi][0], afr[mi][1], afr[mi][2], afr[mi][3],
                      aB + (uint32_t)(mrow[mi]*64 + ((kg ^ msw[mi])*16)));
            }
#pragma unroll
            for (int nb = 0; nb < 4; nb++) {
                uint32_t bf0, bf1, bf2, bf3;
                int kg = kk*2 + kgB;
                ldsm4(bf0, bf1, bf2, bf3,
                      bB + (uint32_t)(nrow[nb]*64 + ((kg ^ nsw[nb])*16)));
#pragma unroll
                for (int mi = 0; mi < 2; mi++) {
                    mma16816(acc[mi][nb*2+0], afr[mi], bf0, bf1);
                    mma16816(acc[mi][nb*2+1], afr[mi], bf2, bf3);
                }
            }
        }
    }

#pragma unroll
    for (int mi = 0; mi < 2; mi++) {
#pragma unroll
        for (int nt = 0; nt < 8; nt++) {
            long long row = m0 + wm*32 + mi*16 + (lane >> 2);
            long long col = n0 + wn*64 + nt*8 + (lane & 3)*2;
            float c0 = bias[col], c1 = bias[col+1];
            *(float2*)(C + row*NTOK + col) =
                make_float2(acc[mi][nt][0] + c0, acc[mi][nt][1] + c1);
            *(float2*)(C + (row+8)*NTOK + col) =
                make_float2(acc[mi][nt][2] + c0, acc[mi][nt][3] + c1);
        }
    }
}

/* ---------------- host launch ---------------- */
extern "C" void kernel_launch(void* const* d_in, const int* in_sizes, int n_in,
                              void* d_out, int out_size)
{
    (void)in_sizes; (void)n_in; (void)out_size;
    const int*   tok  = (const int*)d_in[0];
    const float* emb  = (const float*)d_in[1];
    const float* ln_g = (const float*)d_in[2];
    const float* ln_b = (const float*)d_in[3];
    const float* Wq = (const float*)d_in[4];  const float* bq = (const float*)d_in[5];
    const float* Wk = (const float*)d_in[6];  const float* bk = (const float*)d_in[7];
    const float* Wv = (const float*)d_in[8];  const float* bv = (const float*)d_in[9];
    const float* Wo = (const float*)d_in[10]; const float* bo = (const float*)d_in[11];
    const float* Wih = (const float*)d_in[12]; const float* bih = (const float*)d_in[13];
    const float* Whh = (const float*)d_in[14]; const float* bhh = (const float*)d_in[15];
    const float* dW = (const float*)d_in[16]; const float* db = (const float*)d_in[17];
    const float* h0 = (const float*)d_in[18]; const float* c0 = (const float*)d_in[19];
    const float* H0 = (const float*)d_in[20]; const float* C0 = (const float*)d_in[21];
    float* out = (float*)d_out;

    float *p_eAll, *p_lnAll, *p_hcur;
    cudaGetSymbolAddress((void**)&p_eAll,  d_eAll);
    cudaGetSymbolAddress((void**)&p_lnAll, d_lnAll);
    cudaGetSymbolAddress((void**)&p_hcur,  d_hcur);

    cudaFuncSetAttribute(mma_decode, cudaFuncAttributeMaxDynamicSharedMemorySize, DEC_SMEM);

    /* side stream (low priority) + fork/join events; handles leak (host-side only) */
    int prLeast = 0, prGreatest = 0;
    cudaDeviceGetStreamPriorityRange(&prLeast, &prGreatest);
    cudaStream_t s2;
    cudaStreamCreateWithPriority(&s2, cudaStreamNonBlocking, prLeast);
    cudaEvent_t evRoot, evDone, evReady[16];
    cudaEventCreateWithFlags(&evRoot, cudaEventDisableTiming);
    cudaEventCreateWithFlags(&evDone, cudaEventDisableTiming);
    for (int k = 0; k < 16; k++) cudaEventCreateWithFlags(&evReady[k], cudaEventDisableTiming);

    init_state<<<8960, 256>>>(h0, c0, H0, C0);
    embed_all<<<T_STEPS*B, 256>>>(tok, emb, ln_g, ln_b);
    kv_init<<<dim3(8, 35, 2), 256>>>(H0, Wk, Wv, bk, bv);

    /* fork: convW on s2 */
    cudaEventRecord(evRoot, 0);
    cudaStreamWaitEvent(s2, evRoot, 0);
    convW<<<(NTOK*1024)/256, 256, 0, s2>>>(dW);

    for (int t = 0; t < T_STEPS; t++) {
        int slot = t % MEM;
        int slotPrev = (t + MEM - 1) % MEM;
        const float* e_t = p_eAll + (long long)t*BD;
        qkv3s<<<dim3(8, 8, t == 0 ? 1 : 3), 256>>>(p_lnAll + (long long)t*BD, p_hcur,
                                                   Wq, Wk, Wv);
        qkv_red<<<384, 256>>>(bq, bk, bv, slotPrev, t > 0);
        scores_ks<<<dim3(9, 4, HEADS), 256>>>();
        softmax2<<<HEADS*B, 256>>>();
        attnVs<<<dim3(4, 7, HEADS), 256>>>();
        wo_gs<<<dim3(8, 8), 256>>>(Wo);
        lstm_g<<<dim3(32, 16), 256>>>(e_t, e_t, p_hcur, Wih, Whh, bo);
        lstm_cell2<<<128, 256>>>(0, slot, bih, bhh, 0, t);
        lstm_g<<<dim3(32, 16), 256>>>(p_hcur, e_t, p_hcur + BD,
                                      Wih + 4096*1024, Whh + 4096*1024, bo);
        lstm_cell2<<<128, 256>>>(1, slot, bih + 4096, bhh + 4096, 1, t);
        if ((t & 3) == 3) cudaEventRecord(evReady[t >> 2], 0);
    }

    /* decode stripes on s2, each gated on its 4 steps of X */
    for (int k = 0; k < 16; k++) {
        cudaStreamWaitEvent(s2, evReady[k], 0);
        convX_chunk<<<512, 256, 0, s2>>>(k);
        mma_decode<<<NTOK/128, 256, DEC_SMEM, s2>>>(db, out, k);
    }
    cudaEventRecord(evDone, s2);
    cudaStreamWaitEvent(0, evDone, 0);

    write_tail<<<8960, 256>>>(out);
}